// round 7
// baseline (speedup 1.0000x reference)
#include <cuda_runtime.h>
#include <mma.h>
#include <math.h>

using namespace nvcuda;

#define Bn   128
#define Hn   8
#define Rn   130
#define Tn   256
#define Qd   32
#define BHn  (Bn*Hn)     /* 1024 */
#define Mn   (Bn*Rn)     /* 16640 */
#define NQK  512

// ---------------- device scratch (no allocations allowed) ----------------
__device__ float g_qk[(size_t)Mn*NQK];            // q|k projections (NO bias), [M,512]
__device__ float g_feats[(size_t)BHn*Rn*Tn];      // GCN features (flagged heads only)
__device__ float g_agg[(size_t)BHn*Rn*Tn];        // sparse A @ feats scratch
__device__ float g_spval[BHn*Rn*8];               // sparse A values (pre-gate)
__device__ int   g_spcol[BHn*Rn*8];               // sparse A column indices
__device__ int   g_spcnt[BHn*Rn];                 // nnz per row
__device__ float g_gap[BHn];                      // sum of rel per (b,h)
__device__ float g_maxA[BHn];                     // max kept rel value per (b,h)
__device__ float g_gate[BHn];                     // SE gate (0 or 1)
__device__ int   g_flag[BHn];                     // gate!=0 && maxA>0
__device__ float g_S[Tn+1];                       // S[t]=sum_i relu(gcn_b[i][t]); S[256]=mean

__global__ void k_nop() {}

// ---------------- K1: qk = x @ [Wq;Wk]^T  (tf32 HMMA) ---------------------
#define XPAD 40
__global__ void __launch_bounds__(256)
k_qkproj(const float* __restrict__ x,
         const float* __restrict__ Wq, const float* __restrict__ Wk)
{
    __shared__ float Xs[128 * XPAD];
    __shared__ float Ws[128 * XPAD];

    int tid = threadIdx.x;
    int wid = tid >> 5;
    int m0 = blockIdx.x * 128, n0 = blockIdx.y * 128;
    int wm = wid >> 2;          // 0..1 : 64-row slice
    int wn = wid & 3;           // 0..3 : 32-col slice

    const float* Wbase = (n0 < 256) ? (Wq + (size_t)n0 * 256)
                                    : (Wk + (size_t)(n0 - 256) * 256);
    const float* Xbase = x + (size_t)m0 * 256;

    wmma::fragment<wmma::accumulator, 16, 16, 8, float> acc[4][2];
    #pragma unroll
    for (int i = 0; i < 4; i++)
        #pragma unroll
        for (int j = 0; j < 2; j++)
            wmma::fill_fragment(acc[i][j], 0.0f);

    for (int k0 = 0; k0 < 256; k0 += 32) {
        #pragma unroll
        for (int i = 0; i < 4; i++) {
            int idx = tid + i * 256;
            int row = idx >> 3;
            int c4  = (idx & 7) * 4;
            float4 xv = *(const float4*)(Xbase + (size_t)row * 256 + k0 + c4);
            float4 wv = *(const float4*)(Wbase + (size_t)row * 256 + k0 + c4);
            xv.x = wmma::__float_to_tf32(xv.x); xv.y = wmma::__float_to_tf32(xv.y);
            xv.z = wmma::__float_to_tf32(xv.z); xv.w = wmma::__float_to_tf32(xv.w);
            wv.x = wmma::__float_to_tf32(wv.x); wv.y = wmma::__float_to_tf32(wv.y);
            wv.z = wmma::__float_to_tf32(wv.z); wv.w = wmma::__float_to_tf32(wv.w);
            *(float4*)&Xs[row * XPAD + c4] = xv;
            *(float4*)&Ws[row * XPAD + c4] = wv;
        }
        __syncthreads();

        #pragma unroll
        for (int kk = 0; kk < 32; kk += 8) {
            wmma::fragment<wmma::matrix_a, 16, 16, 8, wmma::precision::tf32, wmma::row_major> af[4];
            wmma::fragment<wmma::matrix_b, 16, 16, 8, wmma::precision::tf32, wmma::col_major> bf[2];
            #pragma unroll
            for (int i = 0; i < 4; i++)
                wmma::load_matrix_sync(af[i], &Xs[(wm * 64 + i * 16) * XPAD + kk], XPAD);
            #pragma unroll
            for (int j = 0; j < 2; j++)
                wmma::load_matrix_sync(bf[j], &Ws[(wn * 32 + j * 16) * XPAD + kk], XPAD);
            #pragma unroll
            for (int i = 0; i < 4; i++)
                #pragma unroll
                for (int j = 0; j < 2; j++)
                    wmma::mma_sync(acc[i][j], af[i], bf[j], acc[i][j]);
        }
        __syncthreads();
    }

    #pragma unroll
    for (int i = 0; i < 4; i++)
        #pragma unroll
        for (int j = 0; j < 2; j++) {
            float* dst = g_qk + (size_t)(m0 + wm * 64 + i * 16) * NQK
                              + n0 + wn * 32 + j * 16;
            wmma::store_matrix_sync(dst, acc[i][j], NQK, wmma::mem_row_major);
        }
}

// ---------------- K2: fused rel/softmax; XOR-swizzled smem (no conflicts) --
// Row max of softmax == 1/se. rinv <= thr => relu(softmax - thr) == 0 exactly.
// smem layout: element (r,i) at r*32 + ((i&~3) ^ ((r&7)<<2)) + (i&3)
//   -> k-loads (lane = row) hit 8 distinct 16B groups per 8-lane phase: conflict-free
//   -> q-loads are row-uniform broadcasts: conflict-free
__global__ void __launch_bounds__(256, 4)
k_attn(const float* __restrict__ thr_p,
       const float* __restrict__ bq, const float* __restrict__ bk)
{
    __shared__ float sq[132 * 32];
    __shared__ float sk[132 * 32];
    __shared__ float s_gap[8], s_max[8];

    int bh = blockIdx.x, b = bh >> 3, h = bh & 7;
    int tid = threadIdx.x, lane = tid & 31, w = tid >> 5;
    const float thr = *thr_p;

    for (int e = tid; e < 132 * Qd; e += 256) {
        int r = e >> 5, i = e & 31;
        float qv = 0.f, kv = 0.f;
        if (r < Rn) {
            size_t rowb = (size_t)(b * Rn + r) * NQK + h * 32;
            qv = g_qk[rowb + i]       + bq[h * 32 + i];
            kv = g_qk[rowb + 256 + i] + bk[h * 32 + i];
        }
        int si = r * 32 + (((i & 28) ^ ((r & 7) << 2)) | (i & 3));
        sq[si] = qv;
        sk[si] = kv;
    }
    __syncthreads();

    float gapAcc = 0.f, maxAcc = 0.f;
    const float sc = 0.17677669529663687f;   // 1/sqrt(32)
    const int cols1 = 4, cols2 = 5, cols3 = 6, cols4 = 7, cols5 = 8;

    // per-lane k row bases + swizzle constants
    int kbase[5], ksw[5];
    #pragma unroll
    for (int jb = 0; jb < 5; jb++) {
        int s = jb * 32 + lane; if (s > 131) s = 131;
        kbase[jb] = s * 32;
        ksw[jb]   = (s & 7) << 2;
    }
    bool val4 = (lane < 2);   // jb=4 true columns: 128,129 only

    for (int g = w; g < 33; g += 8) {
        int r0 = g * 4;
        int qbase[4], qsw[4];
        #pragma unroll
        for (int rr = 0; rr < 4; rr++) {
            qbase[rr] = (r0 + rr) * 32;
            qsw[rr]   = ((r0 + rr) & 7) << 2;
        }

        float acc[4][5];
        #pragma unroll
        for (int rr = 0; rr < 4; rr++)
            #pragma unroll
            for (int jb = 0; jb < 5; jb++) acc[rr][jb] = 0.f;

        // QK^T for 4 rows, swizzled conflict-free loads
        #pragma unroll
        for (int i4 = 0; i4 < 32; i4 += 4) {
            float4 qv[4];
            #pragma unroll
            for (int rr = 0; rr < 4; rr++)
                qv[rr] = *(const float4*)&sq[qbase[rr] + (i4 ^ qsw[rr])];
            #pragma unroll
            for (int jb = 0; jb < 5; jb++) {
                float4 kv = *(const float4*)&sk[kbase[jb] + (i4 ^ ksw[jb])];
                #pragma unroll
                for (int rr = 0; rr < 4; rr++) {
                    float a = acc[rr][jb];
                    a = fmaf(qv[rr].x, kv.x, a);
                    a = fmaf(qv[rr].y, kv.y, a);
                    a = fmaf(qv[rr].z, kv.z, a);
                    a = fmaf(qv[rr].w, kv.w, a);
                    acc[rr][jb] = a;
                }
            }
        }

        // scale
        #pragma unroll
        for (int rr = 0; rr < 4; rr++)
            #pragma unroll
            for (int jb = 0; jb < 5; jb++) acc[rr][jb] *= sc;

        // interleaved max reduction (4 independent chains)
        float lm[4];
        #pragma unroll
        for (int rr = 0; rr < 4; rr++)
            lm[rr] = fmaxf(fmaxf(fmaxf(acc[rr][0], acc[rr][1]),
                                 fmaxf(acc[rr][2], acc[rr][3])),
                           val4 ? acc[rr][4] : -1e30f);
        #pragma unroll
        for (int o = 16; o; o >>= 1) {
            #pragma unroll
            for (int rr = 0; rr < 4; rr++)
                lm[rr] = fmaxf(lm[rr], __shfl_xor_sync(~0u, lm[rr], o));
        }

        // exp in place, interleaved sum reduction
        float es[4];
        #pragma unroll
        for (int rr = 0; rr < 4; rr++) {
            acc[rr][0] = __expf(acc[rr][0] - lm[rr]);
            acc[rr][1] = __expf(acc[rr][1] - lm[rr]);
            acc[rr][2] = __expf(acc[rr][2] - lm[rr]);
            acc[rr][3] = __expf(acc[rr][3] - lm[rr]);
            acc[rr][4] = val4 ? __expf(acc[rr][4] - lm[rr]) : 0.f;
            es[rr] = acc[rr][0] + acc[rr][1] + acc[rr][2] + acc[rr][3] + acc[rr][4];
        }
        #pragma unroll
        for (int o = 16; o; o >>= 1) {
            #pragma unroll
            for (int rr = 0; rr < 4; rr++)
                es[rr] += __shfl_xor_sync(~0u, es[rr], o);
        }

        // batched dead-row handling
        unsigned dm = 0;
        #pragma unroll
        for (int rr = 0; rr < 4; rr++)
            if (1.f <= thr * es[rr]) dm |= (1u << rr);   // rinv <= thr
        if (lane < 4) {
            int r = r0 + lane;
            if (r < Rn && ((dm >> lane) & 1u)) g_spcnt[bh * Rn + r] = 0;
        }

        if (dm == 15u) continue;   // all 4 rows dead (common case)

        // ---- rare full path ----
        #pragma unroll
        for (int rr = 0; rr < 4; rr++) {
            int r = r0 + rr;
            if (r >= Rn || ((dm >> rr) & 1u)) continue;
            float rinv = 1.f / es[rr];
            float v0 = fmaxf(fmaf(acc[rr][0], rinv, -thr), 0.f);
            float v1 = fmaxf(fmaf(acc[rr][1], rinv, -thr), 0.f);
            float v2 = fmaxf(fmaf(acc[rr][2], rinv, -thr), 0.f);
            float v3 = fmaxf(fmaf(acc[rr][3], rinv, -thr), 0.f);
            float v4 = val4 ? fmaxf(fmaf(acc[rr][4], rinv, -thr), 0.f) : 0.f;
            float gs = v0 + v1 + v2 + v3 + v4;
            #pragma unroll
            for (int o = 16; o; o >>= 1) gs += __shfl_xor_sync(~0u, gs, o);

            float c0 = __shfl_sync(~0u, v0, 0);
            float c1 = __shfl_sync(~0u, v0, cols1);
            float c2 = __shfl_sync(~0u, v0, cols2);
            float c3 = __shfl_sync(~0u, v0, cols3);
            float c4c = __shfl_sync(~0u, v0, cols4);
            float c5 = __shfl_sync(~0u, v0, cols5);

            unsigned p0 = 0, p1 = 0;
            #pragma unroll
            for (int jb = 0; jb < 5; jb++) {
                int j = jb * 32 + lane;
                float vv = (jb == 0) ? v0 : (jb == 1) ? v1 : (jb == 2) ? v2
                         : (jb == 3) ? v3 : v4;
                p0 += (vv > c0)                                   ? 1u        : 0u;
                p0 += ((vv > c1) || (vv == c1 && j < cols1))      ? (1u<<8)   : 0u;
                p0 += ((vv > c2) || (vv == c2 && j < cols2))      ? (1u<<16)  : 0u;
                p0 += ((vv > c3) || (vv == c3 && j < cols3))      ? (1u<<24)  : 0u;
                p1 += ((vv > c4c)|| (vv == c4c&& j < cols4))      ? 1u        : 0u;
                p1 += ((vv > c5) || (vv == c5 && j < cols5))      ? (1u<<8)   : 0u;
            }
            #pragma unroll
            for (int o = 16; o; o >>= 1) {
                p0 += __shfl_xor_sync(~0u, p0, o);
                p1 += __shfl_xor_sync(~0u, p1, o);
            }
            int myp = (lane < 4) ? (int)((p0 >> (8 * lane)) & 255u)
                                 : (int)((p1 >> (8 * (lane - 4))) & 255u);
            unsigned ball = __ballot_sync(~0u, (lane < 6) && (myp == r));
            int cnt = 6;
            if (!ball) { if (lane == 6) myp = r; cnt = 7; }

            int base = (bh * Rn + r) * 8;
            float rmax = 0.f;
            for (int i = 0; i < cnt; i++) {
                int p = __shfl_sync(~0u, myp, i);
                int jbp = p >> 5;
                float av = (jbp == 0) ? v0 : (jbp == 1) ? v1 : (jbp == 2) ? v2
                         : (jbp == 3) ? v3 : v4;
                float vv = __shfl_sync(~0u, av, p & 31);
                if (lane == 0) { g_spcol[base + i] = p; g_spval[base + i] = vv; }
                rmax = fmaxf(rmax, vv);
            }
            if (lane == 0) {
                g_spcnt[bh * Rn + r] = cnt;
                gapAcc += gs;
                maxAcc = fmaxf(maxAcc, rmax);
            }
        }
    }
    if (lane == 0) { s_gap[w] = gapAcc; s_max[w] = maxAcc; }
    __syncthreads();
    if (tid == 0) {
        float gsum = 0.f, mx = 0.f;
        #pragma unroll
        for (int i = 0; i < 8; i++) { gsum += s_gap[i]; mx = fmaxf(mx, s_max[i]); }
        g_gap[bh] = gsum; g_maxA[bh] = mx;
    }
}

// ---------------- K3: SE gate + flags -------------------------------------
__global__ void k_gate(const float* __restrict__ seW1, const float* __restrict__ seb1,
                       const float* __restrict__ seW2, const float* __restrict__ seb2)
{
    int b = blockIdx.x;
    if (threadIdx.x) return;
    float g[8];
    #pragma unroll
    for (int h = 0; h < 8; h++) g[h] = g_gap[b * 8 + h] * (1.f / 16900.f);
    float hd[4];
    #pragma unroll
    for (int j = 0; j < 4; j++) {
        float a = seb1[j];
        #pragma unroll
        for (int h = 0; h < 8; h++) a = fmaf(seW1[j * 8 + h], g[h], a);
        hd[j] = fmaxf(a, 0.f);
    }
    #pragma unroll
    for (int i = 0; i < 8; i++) {
        float z = seb2[i];
        #pragma unroll
        for (int j = 0; j < 4; j++) z = fmaf(seW2[i * 4 + j], hd[j], z);
        float gt = floorf(1.f / (1.f + expf(-z)));   // .long() truncation
        g_gate[b * 8 + i] = gt;
        g_flag[b * 8 + i] = (gt != 0.f) && (g_maxA[b * 8 + i] > 0.f);
    }
}

// ---------------- Kprep: S[t] = sum_i relu(gcn_b[i][t]) -------------------
__global__ void k_prep(const float* __restrict__ gcn_b)
{
    __shared__ float red[256];
    int t = threadIdx.x;
    float s = 0.f;
    #pragma unroll
    for (int i = 0; i < 8; i++) s += fmaxf(gcn_b[i * 256 + t], 0.f);
    g_S[t] = s;
    red[t] = s; __syncthreads();
    for (int o = 128; o; o >>= 1) { if (t < o) red[t] += red[t + o]; __syncthreads(); }
    if (t == 0) g_S[256] = red[0] * (1.f / 256.f);
}

// ---------------- GCN: all 8 layers, one block per (b,h), flag-guarded ----
__global__ void k_gcnall(const float* __restrict__ x,
                         const float* __restrict__ gcnW, const float* __restrict__ gcnb)
{
    int bh = blockIdx.x;
    if (!g_flag[bh]) return;
    int b = bh >> 3;
    float gt = g_gate[bh];
    size_t base = (size_t)bh * Rn * Tn;
    const float* xb = x + (size_t)b * Rn * Tn;

    for (int e = threadIdx.x; e < Rn * Tn; e += 256) g_feats[base + e] = xb[e];
    __syncthreads();

    for (int L = 0; L < 8; L++) {
        const float* W    = gcnW + (size_t)L * Tn * Tn;
        const float* bias = gcnb + L * Tn;
        for (int e = threadIdx.x; e < Rn * Tn; e += 256) {
            int r = e >> 8, t = e & 255;
            int cnt = g_spcnt[bh * Rn + r];
            int sb  = (bh * Rn + r) * 8;
            float a = 0.f;
            for (int i = 0; i < cnt; i++)
                a = fmaf(g_spval[sb + i],
                         g_feats[base + (size_t)g_spcol[sb + i] * Tn + t], a);
            g_agg[base + e] = a * gt;
        }
        __syncthreads();
        for (int e = threadIdx.x; e < Rn * Tn; e += 256) {
            int r = e >> 8, t = e & 255;
            float acc = bias[t];
            const float* ag = g_agg + base + (size_t)r * Tn;
            const float* wr = W + (size_t)t * Tn;
            for (int u = 0; u < Tn; u++) acc = fmaf(ag[u], wr[u], acc);
            g_feats[base + e] = fmaxf(acc, 0.f) + g_feats[base + e];
        }
        __syncthreads();
    }
}

// ---------------- K5: fusion + pool + MLP head ----------------------------
__global__ void k_head(const float* __restrict__ x,
                       const float* __restrict__ fw, const float* __restrict__ fb,
                       const float* __restrict__ W1, const float* __restrict__ b1,
                       const float* __restrict__ W2, const float* __restrict__ b2,
                       const float* __restrict__ W3, const float* __restrict__ b3,
                       float* __restrict__ out)
{
    int b = blockIdx.x;
    int tid = threadIdx.x, lane = tid & 31, w = tid >> 5;
    __shared__ float pooled[132], sh1[64], sh2[16];
    __shared__ float swf[8];
    __shared__ int   sfl[8];
    if (tid < 8) { swf[tid] = fw[tid]; sfl[tid] = g_flag[b * 8 + tid]; }
    __syncthreads();
    float meanS = g_S[256], fbv = *fb;

    for (int r = w; r < Rn; r += 8) {
        const float* xr = x + ((size_t)b * Rn + r) * Tn;
        float sx = 0.f;
        for (int t = lane; t < Tn; t += 32) sx += xr[t];
        #pragma unroll
        for (int o = 16; o; o >>= 1) sx += __shfl_xor_sync(~0u, sx, o);
        float mx = sx * (1.f / 256.f);
        float acc = fbv;
        #pragma unroll
        for (int h = 0; h < 8; h++) {
            if (sfl[h]) {
                const float* fr = g_feats + ((size_t)(b * 8 + h) * Rn + r) * Tn;
                float sf = 0.f;
                for (int t = lane; t < Tn; t += 32) sf += fr[t];
                #pragma unroll
                for (int o = 16; o; o >>= 1) sf += __shfl_xor_sync(~0u, sf, o);
                acc = fmaf(swf[h], sf * (1.f / 256.f), acc);
            } else {
                acc = fmaf(swf[h], mx + meanS, acc);   // closed form: feats = x + S
            }
        }
        if (lane == 0) pooled[r] = acc;
    }
    __syncthreads();
    if (tid < 64) {
        float a = b1[tid];
        for (int r = 0; r < Rn; r++) a = fmaf(W1[tid * Rn + r], pooled[r], a);
        sh1[tid] = fmaxf(a, 0.f);
    }
    __syncthreads();
    if (tid < 16) {
        float a = b2[tid];
        #pragma unroll
        for (int j = 0; j < 64; j++) a = fmaf(W2[tid * 64 + j], sh1[j], a);
        sh2[tid] = fmaxf(a, 0.f);
    }
    __syncthreads();
    if (tid < 5) {
        float a = b3[tid];
        #pragma unroll
        for (int j = 0; j < 16; j++) a = fmaf(W3[tid * 16 + j], sh2[j], a);
        out[b * 5 + tid] = fmaxf(a, 0.f);
    }
}

// ---------------- launch ---------------------------------------------------
extern "C" void kernel_launch(void* const* d_in, const int* in_sizes, int n_in,
                              void* d_out, int out_size)
{
    const float* x    = (const float*)d_in[0];
    const float* Wq   = (const float*)d_in[1];
    const float* bq   = (const float*)d_in[2];
    const float* Wk   = (const float*)d_in[3];
    const float* bk   = (const float*)d_in[4];
    const float* thr  = (const float*)d_in[5];
    const float* seW1 = (const float*)d_in[6];
    const float* seb1 = (const float*)d_in[7];
    const float* seW2 = (const float*)d_in[8];
    const float* seb2 = (const float*)d_in[9];
    const float* gcnW = (const float*)d_in[10];
    const float* gcnb = (const float*)d_in[11];
    const float* fw   = (const float*)d_in[12];
    const float* fb   = (const float*)d_in[13];
    const float* W1   = (const float*)d_in[14];
    const float* b1   = (const float*)d_in[15];
    const float* W2   = (const float*)d_in[16];
    const float* b2   = (const float*)d_in[17];
    const float* W3   = (const float*)d_in[18];
    const float* b3   = (const float*)d_in[19];
    float* out = (float*)d_out;

    dim3 g1(Mn / 128, NQK / 128);
    k_qkproj<<<g1, 256>>>(x, Wq, Wk);                    // launch 1
    k_prep<<<1, 256>>>(gcnb);                            // launch 2
    k_nop<<<1, 32>>>();                                  // launch 3
    k_attn<<<BHn, 256>>>(thr, bq, bk);                   // launch 4 <- ncu capture
    k_gate<<<Bn, 32>>>(seW1, seb1, seW2, seb2);          // launch 5
    k_gcnall<<<BHn, 256>>>(x, gcnW, gcnb);               // launch 6
    k_head<<<Bn, 256>>>(x, fw, fb, W1, b1, W2, b2, W3, b3, out);  // launch 7
}

// round 8
// speedup vs baseline: 1.4505x; 1.4505x over previous
#include <cuda_runtime.h>
#include <mma.h>
#include <math.h>

using namespace nvcuda;

#define Bn   128
#define Hn   8
#define Rn   130
#define Tn   256
#define Qd   32
#define BHn  (Bn*Hn)     /* 1024 */
#define Mn   (Bn*Rn)     /* 16640 */
#define NQK  512

// ---------------- device scratch (no allocations allowed) ----------------
__device__ float g_qk[(size_t)Mn*NQK];            // q|k projections (NO bias), [M,512]
__device__ float g_feats[(size_t)BHn*Rn*Tn];      // GCN features (flagged heads only)
__device__ float g_agg[(size_t)BHn*Rn*Tn];        // sparse A @ feats scratch
__device__ float g_spval[BHn*Rn*8];               // sparse A values (pre-gate)
__device__ int   g_spcol[BHn*Rn*8];               // sparse A column indices
__device__ int   g_spcnt[BHn*Rn];                 // nnz per row
__device__ float g_gap2[BHn*2];                   // per-half sums of rel
__device__ float g_max2[BHn*2];                   // per-half max kept rel
__device__ float g_gate[BHn];                     // SE gate (0 or 1)
__device__ int   g_flag[BHn];                     // gate!=0 && maxA>0
__device__ float g_S[Tn+1];                       // S[t]=sum_i relu(gcn_b[i][t]); S[256]=mean

__global__ void k_nop() {}

// ---------------- K1: qk = x @ [Wq;Wk]^T  (tf32 HMMA) ---------------------
#define XPAD 40
__global__ void __launch_bounds__(256)
k_qkproj(const float* __restrict__ x,
         const float* __restrict__ Wq, const float* __restrict__ Wk)
{
    __shared__ float Xs[128 * XPAD];
    __shared__ float Ws[128 * XPAD];

    int tid = threadIdx.x;
    int wid = tid >> 5;
    int m0 = blockIdx.x * 128, n0 = blockIdx.y * 128;
    int wm = wid >> 2;          // 0..1 : 64-row slice
    int wn = wid & 3;           // 0..3 : 32-col slice

    const float* Wbase = (n0 < 256) ? (Wq + (size_t)n0 * 256)
                                    : (Wk + (size_t)(n0 - 256) * 256);
    const float* Xbase = x + (size_t)m0 * 256;

    wmma::fragment<wmma::accumulator, 16, 16, 8, float> acc[4][2];
    #pragma unroll
    for (int i = 0; i < 4; i++)
        #pragma unroll
        for (int j = 0; j < 2; j++)
            wmma::fill_fragment(acc[i][j], 0.0f);

    for (int k0 = 0; k0 < 256; k0 += 32) {
        #pragma unroll
        for (int i = 0; i < 4; i++) {
            int idx = tid + i * 256;
            int row = idx >> 3;
            int c4  = (idx & 7) * 4;
            float4 xv = *(const float4*)(Xbase + (size_t)row * 256 + k0 + c4);
            float4 wv = *(const float4*)(Wbase + (size_t)row * 256 + k0 + c4);
            xv.x = wmma::__float_to_tf32(xv.x); xv.y = wmma::__float_to_tf32(xv.y);
            xv.z = wmma::__float_to_tf32(xv.z); xv.w = wmma::__float_to_tf32(xv.w);
            wv.x = wmma::__float_to_tf32(wv.x); wv.y = wmma::__float_to_tf32(wv.y);
            wv.z = wmma::__float_to_tf32(wv.z); wv.w = wmma::__float_to_tf32(wv.w);
            *(float4*)&Xs[row * XPAD + c4] = xv;
            *(float4*)&Ws[row * XPAD + c4] = wv;
        }
        __syncthreads();

        #pragma unroll
        for (int kk = 0; kk < 32; kk += 8) {
            wmma::fragment<wmma::matrix_a, 16, 16, 8, wmma::precision::tf32, wmma::row_major> af[4];
            wmma::fragment<wmma::matrix_b, 16, 16, 8, wmma::precision::tf32, wmma::col_major> bf[2];
            #pragma unroll
            for (int i = 0; i < 4; i++)
                wmma::load_matrix_sync(af[i], &Xs[(wm * 64 + i * 16) * XPAD + kk], XPAD);
            #pragma unroll
            for (int j = 0; j < 2; j++)
                wmma::load_matrix_sync(bf[j], &Ws[(wn * 32 + j * 16) * XPAD + kk], XPAD);
            #pragma unroll
            for (int i = 0; i < 4; i++)
                #pragma unroll
                for (int j = 0; j < 2; j++)
                    wmma::mma_sync(acc[i][j], af[i], bf[j], acc[i][j]);
        }
        __syncthreads();
    }

    #pragma unroll
    for (int i = 0; i < 4; i++)
        #pragma unroll
        for (int j = 0; j < 2; j++) {
            float* dst = g_qk + (size_t)(m0 + wm * 64 + i * 16) * NQK
                              + n0 + wn * 32 + j * 16;
            wmma::store_matrix_sync(dst, acc[i][j], NQK, wmma::mem_row_major);
        }
}

// ---------------- K2: fused rel/softmax (R6 body), 2 blocks per (b,h) -----
// Row max of softmax == 1/se. rinv <= thr => relu(softmax - thr) == 0 exactly.
#define SQS 36
__global__ void __launch_bounds__(256, 4)
k_attn(const float* __restrict__ thr_p,
       const float* __restrict__ bq, const float* __restrict__ bk)
{
    __shared__ float sq[132 * SQS];
    __shared__ float sk[132 * SQS];
    __shared__ float s_gap[8], s_max[8];

    int bhh = blockIdx.x;
    int bh = bhh >> 1, half = bhh & 1;
    int b = bh >> 3, h = bh & 7;
    int tid = threadIdx.x, lane = tid & 31, w = tid >> 5;
    const float thr = *thr_p;

    // group range: half 0 -> groups [0,17) (rows 0..67); half 1 -> [17,33) (rows 68..131)
    int gstart = half ? 17 : 0;
    int gend   = half ? 33 : 17;
    int rlo    = gstart * 4;           // first row this block needs from sq
    int rhi    = gend * 4;             // one past last (132 for half 1)

    // load k (all rows) + q (only this block's rows); rows >=130 zero
    for (int e = tid; e < 132 * Qd; e += 256) {
        int r = e >> 5, i = e & 31;
        float kv = 0.f;
        if (r < Rn) {
            size_t rowb = (size_t)(b * Rn + r) * NQK + h * 32;
            kv = g_qk[rowb + 256 + i] + bk[h * 32 + i];
        }
        sk[r * SQS + i] = kv;
        if (r >= rlo && r < rhi) {
            float qv = 0.f;
            if (r < Rn) {
                size_t rowb = (size_t)(b * Rn + r) * NQK + h * 32;
                qv = g_qk[rowb + i] + bq[h * 32 + i];
            }
            sq[r * SQS + i] = qv;
        }
    }
    __syncthreads();

    float gapAcc = 0.f, maxAcc = 0.f;
    const float sc = 0.17677669529663687f;   // 1/sqrt(32)
    const int cols1 = 4, cols2 = 5, cols3 = 6, cols4 = 7, cols5 = 8;

    int sjb[5];
    #pragma unroll
    for (int jb = 0; jb < 5; jb++) {
        int s = jb * 32 + lane; sjb[jb] = (s > 131) ? 131 : s;
    }
    bool val4 = (lane < 2);   // jb=4 true columns: 128,129 only

    for (int g = gstart + w; g < gend; g += 8) {
        int r0 = g * 4;
        float acc[4][5];
        #pragma unroll
        for (int rr = 0; rr < 4; rr++)
            #pragma unroll
            for (int jb = 0; jb < 5; jb++) acc[rr][jb] = 0.f;

        // QK^T for 4 rows
        #pragma unroll
        for (int i4 = 0; i4 < 32; i4 += 4) {
            float4 qv[4];
            #pragma unroll
            for (int rr = 0; rr < 4; rr++)
                qv[rr] = *(const float4*)&sq[(r0 + rr) * SQS + i4];
            #pragma unroll
            for (int jb = 0; jb < 5; jb++) {
                float4 kv = *(const float4*)&sk[sjb[jb] * SQS + i4];
                #pragma unroll
                for (int rr = 0; rr < 4; rr++) {
                    float a = acc[rr][jb];
                    a = fmaf(qv[rr].x, kv.x, a);
                    a = fmaf(qv[rr].y, kv.y, a);
                    a = fmaf(qv[rr].z, kv.z, a);
                    a = fmaf(qv[rr].w, kv.w, a);
                    acc[rr][jb] = a;
                }
            }
        }

        // scale
        #pragma unroll
        for (int rr = 0; rr < 4; rr++)
            #pragma unroll
            for (int jb = 0; jb < 5; jb++) acc[rr][jb] *= sc;

        // interleaved max reduction (4 independent chains)
        float lm[4];
        #pragma unroll
        for (int rr = 0; rr < 4; rr++)
            lm[rr] = fmaxf(fmaxf(fmaxf(acc[rr][0], acc[rr][1]),
                                 fmaxf(acc[rr][2], acc[rr][3])),
                           val4 ? acc[rr][4] : -1e30f);
        #pragma unroll
        for (int o = 16; o; o >>= 1) {
            #pragma unroll
            for (int rr = 0; rr < 4; rr++)
                lm[rr] = fmaxf(lm[rr], __shfl_xor_sync(~0u, lm[rr], o));
        }

        // exp in place, interleaved sum reduction
        float es[4];
        #pragma unroll
        for (int rr = 0; rr < 4; rr++) {
            acc[rr][0] = __expf(acc[rr][0] - lm[rr]);
            acc[rr][1] = __expf(acc[rr][1] - lm[rr]);
            acc[rr][2] = __expf(acc[rr][2] - lm[rr]);
            acc[rr][3] = __expf(acc[rr][3] - lm[rr]);
            acc[rr][4] = val4 ? __expf(acc[rr][4] - lm[rr]) : 0.f;
            es[rr] = acc[rr][0] + acc[rr][1] + acc[rr][2] + acc[rr][3] + acc[rr][4];
        }
        #pragma unroll
        for (int o = 16; o; o >>= 1) {
            #pragma unroll
            for (int rr = 0; rr < 4; rr++)
                es[rr] += __shfl_xor_sync(~0u, es[rr], o);
        }

        // batched dead-row handling
        unsigned dm = 0;
        #pragma unroll
        for (int rr = 0; rr < 4; rr++)
            if (1.f <= thr * es[rr]) dm |= (1u << rr);   // rinv <= thr
        if (lane < 4) {
            int r = r0 + lane;
            if (r < Rn && ((dm >> lane) & 1u)) g_spcnt[bh * Rn + r] = 0;
        }

        if (dm == 15u) continue;   // all 4 rows dead (common case)

        // ---- rare full path ----
        #pragma unroll
        for (int rr = 0; rr < 4; rr++) {
            int r = r0 + rr;
            if (r >= Rn || ((dm >> rr) & 1u)) continue;
            float rinv = 1.f / es[rr];
            float v0 = fmaxf(fmaf(acc[rr][0], rinv, -thr), 0.f);
            float v1 = fmaxf(fmaf(acc[rr][1], rinv, -thr), 0.f);
            float v2 = fmaxf(fmaf(acc[rr][2], rinv, -thr), 0.f);
            float v3 = fmaxf(fmaf(acc[rr][3], rinv, -thr), 0.f);
            float v4 = val4 ? fmaxf(fmaf(acc[rr][4], rinv, -thr), 0.f) : 0.f;
            float gs = v0 + v1 + v2 + v3 + v4;
            #pragma unroll
            for (int o = 16; o; o >>= 1) gs += __shfl_xor_sync(~0u, gs, o);

            float c0 = __shfl_sync(~0u, v0, 0);
            float c1 = __shfl_sync(~0u, v0, cols1);
            float c2 = __shfl_sync(~0u, v0, cols2);
            float c3 = __shfl_sync(~0u, v0, cols3);
            float c4c = __shfl_sync(~0u, v0, cols4);
            float c5 = __shfl_sync(~0u, v0, cols5);

            unsigned p0 = 0, p1 = 0;
            #pragma unroll
            for (int jb = 0; jb < 5; jb++) {
                int j = jb * 32 + lane;
                float vv = (jb == 0) ? v0 : (jb == 1) ? v1 : (jb == 2) ? v2
                         : (jb == 3) ? v3 : v4;
                p0 += (vv > c0)                                   ? 1u        : 0u;
                p0 += ((vv > c1) || (vv == c1 && j < cols1))      ? (1u<<8)   : 0u;
                p0 += ((vv > c2) || (vv == c2 && j < cols2))      ? (1u<<16)  : 0u;
                p0 += ((vv > c3) || (vv == c3 && j < cols3))      ? (1u<<24)  : 0u;
                p1 += ((vv > c4c)|| (vv == c4c&& j < cols4))      ? 1u        : 0u;
                p1 += ((vv > c5) || (vv == c5 && j < cols5))      ? (1u<<8)   : 0u;
            }
            #pragma unroll
            for (int o = 16; o; o >>= 1) {
                p0 += __shfl_xor_sync(~0u, p0, o);
                p1 += __shfl_xor_sync(~0u, p1, o);
            }
            int myp = (lane < 4) ? (int)((p0 >> (8 * lane)) & 255u)
                                 : (int)((p1 >> (8 * (lane - 4))) & 255u);
            unsigned ball = __ballot_sync(~0u, (lane < 6) && (myp == r));
            int cnt = 6;
            if (!ball) { if (lane == 6) myp = r; cnt = 7; }

            int base = (bh * Rn + r) * 8;
            float rmax = 0.f;
            for (int i = 0; i < cnt; i++) {
                int p = __shfl_sync(~0u, myp, i);
                int jbp = p >> 5;
                float av = (jbp == 0) ? v0 : (jbp == 1) ? v1 : (jbp == 2) ? v2
                         : (jbp == 3) ? v3 : v4;
                float vv = __shfl_sync(~0u, av, p & 31);
                if (lane == 0) { g_spcol[base + i] = p; g_spval[base + i] = vv; }
                rmax = fmaxf(rmax, vv);
            }
            if (lane == 0) {
                g_spcnt[bh * Rn + r] = cnt;
                gapAcc += gs;
                maxAcc = fmaxf(maxAcc, rmax);
            }
        }
    }
    if (lane == 0) { s_gap[w] = gapAcc; s_max[w] = maxAcc; }
    __syncthreads();
    if (tid == 0) {
        float gsum = 0.f, mx = 0.f;
        #pragma unroll
        for (int i = 0; i < 8; i++) { gsum += s_gap[i]; mx = fmaxf(mx, s_max[i]); }
        g_gap2[bhh] = gsum; g_max2[bhh] = mx;
    }
}

// ---------------- K3: SE gate + flags (sums the two halves) ---------------
__global__ void k_gate(const float* __restrict__ seW1, const float* __restrict__ seb1,
                       const float* __restrict__ seW2, const float* __restrict__ seb2)
{
    int b = blockIdx.x;
    if (threadIdx.x) return;
    float g[8], mxa[8];
    #pragma unroll
    for (int h = 0; h < 8; h++) {
        int bh = b * 8 + h;
        g[h] = (g_gap2[bh * 2] + g_gap2[bh * 2 + 1]) * (1.f / 16900.f);
        mxa[h] = fmaxf(g_max2[bh * 2], g_max2[bh * 2 + 1]);
    }
    float hd[4];
    #pragma unroll
    for (int j = 0; j < 4; j++) {
        float a = seb1[j];
        #pragma unroll
        for (int h = 0; h < 8; h++) a = fmaf(seW1[j * 8 + h], g[h], a);
        hd[j] = fmaxf(a, 0.f);
    }
    #pragma unroll
    for (int i = 0; i < 8; i++) {
        float z = seb2[i];
        #pragma unroll
        for (int j = 0; j < 4; j++) z = fmaf(seW2[i * 4 + j], hd[j], z);
        float gt = floorf(1.f / (1.f + expf(-z)));   // .long() truncation
        g_gate[b * 8 + i] = gt;
        g_flag[b * 8 + i] = (gt != 0.f) && (mxa[i] > 0.f);
    }
}

// ---------------- Kprep: S[t] = sum_i relu(gcn_b[i][t]) -------------------
__global__ void k_prep(const float* __restrict__ gcn_b)
{
    __shared__ float red[256];
    int t = threadIdx.x;
    float s = 0.f;
    #pragma unroll
    for (int i = 0; i < 8; i++) s += fmaxf(gcn_b[i * 256 + t], 0.f);
    g_S[t] = s;
    red[t] = s; __syncthreads();
    for (int o = 128; o; o >>= 1) { if (t < o) red[t] += red[t + o]; __syncthreads(); }
    if (t == 0) g_S[256] = red[0] * (1.f / 256.f);
}

// ---------------- GCN: all 8 layers, one block per (b,h), flag-guarded ----
__global__ void k_gcnall(const float* __restrict__ x,
                         const float* __restrict__ gcnW, const float* __restrict__ gcnb)
{
    int bh = blockIdx.x;
    if (!g_flag[bh]) return;
    int b = bh >> 3;
    float gt = g_gate[bh];
    size_t base = (size_t)bh * Rn * Tn;
    const float* xb = x + (size_t)b * Rn * Tn;

    for (int e = threadIdx.x; e < Rn * Tn; e += 256) g_feats[base + e] = xb[e];
    __syncthreads();

    for (int L = 0; L < 8; L++) {
        const float* W    = gcnW + (size_t)L * Tn * Tn;
        const float* bias = gcnb + L * Tn;
        for (int e = threadIdx.x; e < Rn * Tn; e += 256) {
            int r = e >> 8, t = e & 255;
            int cnt = g_spcnt[bh * Rn + r];
            int sb  = (bh * Rn + r) * 8;
            float a = 0.f;
            for (int i = 0; i < cnt; i++)
                a = fmaf(g_spval[sb + i],
                         g_feats[base + (size_t)g_spcol[sb + i] * Tn + t], a);
            g_agg[base + e] = a * gt;
        }
        __syncthreads();
        for (int e = threadIdx.x; e < Rn * Tn; e += 256) {
            int r = e >> 8, t = e & 255;
            float acc = bias[t];
            const float* ag = g_agg + base + (size_t)r * Tn;
            const float* wr = W + (size_t)t * Tn;
            for (int u = 0; u < Tn; u++) acc = fmaf(ag[u], wr[u], acc);
            g_feats[base + e] = fmaxf(acc, 0.f) + g_feats[base + e];
        }
        __syncthreads();
    }
}

// ---------------- K5: fusion + pool + MLP head ----------------------------
__global__ void k_head(const float* __restrict__ x,
                       const float* __restrict__ fw, const float* __restrict__ fb,
                       const float* __restrict__ W1, const float* __restrict__ b1,
                       const float* __restrict__ W2, const float* __restrict__ b2,
                       const float* __restrict__ W3, const float* __restrict__ b3,
                       float* __restrict__ out)
{
    int b = blockIdx.x;
    int tid = threadIdx.x, lane = tid & 31, w = tid >> 5;
    __shared__ float pooled[132], sh1[64], sh2[16];
    __shared__ float swf[8];
    __shared__ int   sfl[8];
    if (tid < 8) { swf[tid] = fw[tid]; sfl[tid] = g_flag[b * 8 + tid]; }
    __syncthreads();
    float meanS = g_S[256], fbv = *fb;

    for (int r = w; r < Rn; r += 8) {
        const float* xr = x + ((size_t)b * Rn + r) * Tn;
        float sx = 0.f;
        for (int t = lane; t < Tn; t += 32) sx += xr[t];
        #pragma unroll
        for (int o = 16; o; o >>= 1) sx += __shfl_xor_sync(~0u, sx, o);
        float mx = sx * (1.f / 256.f);
        float acc = fbv;
        #pragma unroll
        for (int h = 0; h < 8; h++) {
            if (sfl[h]) {
                const float* fr = g_feats + ((size_t)(b * 8 + h) * Rn + r) * Tn;
                float sf = 0.f;
                for (int t = lane; t < Tn; t += 32) sf += fr[t];
                #pragma unroll
                for (int o = 16; o; o >>= 1) sf += __shfl_xor_sync(~0u, sf, o);
                acc = fmaf(swf[h], sf * (1.f / 256.f), acc);
            } else {
                acc = fmaf(swf[h], mx + meanS, acc);   // closed form: feats = x + S
            }
        }
        if (lane == 0) pooled[r] = acc;
    }
    __syncthreads();
    if (tid < 64) {
        float a = b1[tid];
        for (int r = 0; r < Rn; r++) a = fmaf(W1[tid * Rn + r], pooled[r], a);
        sh1[tid] = fmaxf(a, 0.f);
    }
    __syncthreads();
    if (tid < 16) {
        float a = b2[tid];
        #pragma unroll
        for (int j = 0; j < 64; j++) a = fmaf(W2[tid * 64 + j], sh1[j], a);
        sh2[tid] = fmaxf(a, 0.f);
    }
    __syncthreads();
    if (tid < 5) {
        float a = b3[tid];
        #pragma unroll
        for (int j = 0; j < 16; j++) a = fmaf(W3[tid * 16 + j], sh2[j], a);
        out[b * 5 + tid] = fmaxf(a, 0.f);
    }
}

// ---------------- launch ---------------------------------------------------
extern "C" void kernel_launch(void* const* d_in, const int* in_sizes, int n_in,
                              void* d_out, int out_size)
{
    const float* x    = (const float*)d_in[0];
    const float* Wq   = (const float*)d_in[1];
    const float* bq   = (const float*)d_in[2];
    const float* Wk   = (const float*)d_in[3];
    const float* bk   = (const float*)d_in[4];
    const float* thr  = (const float*)d_in[5];
    const float* seW1 = (const float*)d_in[6];
    const float* seb1 = (const float*)d_in[7];
    const float* seW2 = (const float*)d_in[8];
    const float* seb2 = (const float*)d_in[9];
    const float* gcnW = (const float*)d_in[10];
    const float* gcnb = (const float*)d_in[11];
    const float* fw   = (const float*)d_in[12];
    const float* fb   = (const float*)d_in[13];
    const float* W1   = (const float*)d_in[14];
    const float* b1   = (const float*)d_in[15];
    const float* W2   = (const float*)d_in[16];
    const float* b2   = (const float*)d_in[17];
    const float* W3   = (const float*)d_in[18];
    const float* b3   = (const float*)d_in[19];
    float* out = (float*)d_out;

    dim3 g1(Mn / 128, NQK / 128);
    k_prep<<<1, 256>>>(gcnb);                            // launch 1
    k_nop<<<1, 32>>>();                                  // launch 2
    k_nop<<<1, 32>>>();                                  // launch 3
    k_qkproj<<<g1, 256>>>(x, Wq, Wk);                    // launch 4 <- ncu capture
    k_attn<<<BHn * 2, 256>>>(thr, bq, bk);               // launch 5
    k_gate<<<Bn, 32>>>(seW1, seb1, seW2, seb2);          // launch 6
    k_gcnall<<<BHn, 256>>>(x, gcnW, gcnb);               // launch 7
    k_head<<<Bn, 256>>>(x, fw, fb, W1, b1, W2, b2, W3, b3, out);  // launch 8
}

// round 10
// speedup vs baseline: 1.7127x; 1.1808x over previous
#include <cuda_runtime.h>
#include <cstdint>
#include <mma.h>
#include <math.h>

using namespace nvcuda;

#define Bn   128
#define Hn   8
#define Rn   130
#define Tn   256
#define Qd   32
#define BHn  (Bn*Hn)     /* 1024 */
#define Mn   (Bn*Rn)     /* 16640 */
#define NQK  512

// ---------------- device scratch (no allocations allowed) ----------------
__device__ float g_qk[(size_t)Mn*NQK];            // q|k projections (NO bias), [M,512]
__device__ float g_feats[(size_t)BHn*Rn*Tn];      // GCN features (flagged heads only)
__device__ float g_agg[(size_t)BHn*Rn*Tn];        // sparse A @ feats scratch
__device__ float g_spval[BHn*Rn*8];               // sparse A values (pre-gate)
__device__ int   g_spcol[BHn*Rn*8];               // sparse A column indices
__device__ int   g_spcnt[BHn*Rn];                 // nnz per row
__device__ float g_gap[BHn];                      // sum of rel per (b,h)
__device__ float g_maxA[BHn];                     // max kept rel value per (b,h)
__device__ float g_gate[BHn];                     // SE gate (0 or 1)
__device__ int   g_flag[BHn];                     // gate!=0 && maxA>0
__device__ float g_S[Tn+1];                       // S[t]=sum_i relu(gcn_b[i][t]); S[256]=mean

__global__ void k_nop() {}

// ---------------- cp.async helpers ----------------------------------------
__device__ __forceinline__ void cp16(void* smem, const void* gmem) {
    unsigned int s = (unsigned int)__cvta_generic_to_shared(smem);
    asm volatile("cp.async.ca.shared.global [%0], [%1], 16;\n" :: "r"(s), "l"(gmem));
}

// ---------------- K1: qk = x @ [Wq;Wk]^T  (tf32 HMMA, cp.async pipeline) ---
#define BK 16
#define XP 20   /* 16 + 4 pad floats; 16B-aligned rows (80B stride) */
__global__ void __launch_bounds__(256, 2)
k_qkproj(const float* __restrict__ x,
         const float* __restrict__ Wq, const float* __restrict__ Wk)
{
    __shared__ __align__(16) float Xs[2][128 * XP];
    __shared__ __align__(16) float Ws[2][128 * XP];

    int tid = threadIdx.x;
    int wid = tid >> 5;
    int m0 = blockIdx.x * 128, n0 = blockIdx.y * 128;
    int wm = wid >> 2;          // 0..1 : 64-row slice
    int wn = wid & 3;           // 0..3 : 32-col slice

    const float* Wbase = (n0 < 256) ? (Wq + (size_t)n0 * 256)
                                    : (Wk + (size_t)(n0 - 256) * 256);
    const float* Xbase = x + (size_t)m0 * 256;

    // per-thread load slots: row = tid>>1 (0..127), cols lc0..lc0+7
    int lrow = tid >> 1;
    int lc0  = (tid & 1) * 8;
    const float* gx = Xbase + (size_t)lrow * 256 + lc0;
    const float* gw = Wbase + (size_t)lrow * 256 + lc0;
    float* sx = &Xs[0][lrow * XP + lc0];
    float* sw = &Ws[0][lrow * XP + lc0];
    const int bufstride = 128 * XP;

    wmma::fragment<wmma::accumulator, 16, 16, 8, float> acc[4][2];
    #pragma unroll
    for (int i = 0; i < 4; i++)
        #pragma unroll
        for (int j = 0; j < 2; j++)
            wmma::fill_fragment(acc[i][j], 0.0f);

    // stage 0 prefetch
    {
        cp16(sx,     gx);     cp16(sx + 4, gx + 4);
        cp16(sw,     gw);     cp16(sw + 4, gw + 4);
        asm volatile("cp.async.commit_group;\n");
    }

    #pragma unroll 1
    for (int s = 0; s < 16; s++) {
        if (s + 1 < 16) {
            int buf = (s + 1) & 1;
            int k0  = (s + 1) * BK;
            cp16(sx + buf * bufstride,     gx + k0);
            cp16(sx + buf * bufstride + 4, gx + k0 + 4);
            cp16(sw + buf * bufstride,     gw + k0);
            cp16(sw + buf * bufstride + 4, gw + k0 + 4);
            asm volatile("cp.async.commit_group;\n");
            asm volatile("cp.async.wait_group 1;\n");
        } else {
            asm volatile("cp.async.wait_group 0;\n");
        }
        __syncthreads();

        const float* Xb = &Xs[s & 1][0];
        const float* Wb = &Ws[s & 1][0];
        #pragma unroll
        for (int kk = 0; kk < 16; kk += 8) {
            wmma::fragment<wmma::matrix_a, 16, 16, 8, wmma::precision::tf32, wmma::row_major> af[4];
            wmma::fragment<wmma::matrix_b, 16, 16, 8, wmma::precision::tf32, wmma::col_major> bf[2];
            #pragma unroll
            for (int i = 0; i < 4; i++)
                wmma::load_matrix_sync(af[i], Xb + (wm * 64 + i * 16) * XP + kk, XP);
            #pragma unroll
            for (int j = 0; j < 2; j++)
                wmma::load_matrix_sync(bf[j], Wb + (wn * 32 + j * 16) * XP + kk, XP);
            #pragma unroll
            for (int i = 0; i < 4; i++)
                #pragma unroll
                for (int j = 0; j < 2; j++)
                    wmma::mma_sync(acc[i][j], af[i], bf[j], acc[i][j]);
        }
        __syncthreads();
    }

    #pragma unroll
    for (int i = 0; i < 4; i++)
        #pragma unroll
        for (int j = 0; j < 2; j++) {
            float* dst = g_qk + (size_t)(m0 + wm * 64 + i * 16) * NQK
                              + n0 + wn * 32 + j * 16;
            wmma::store_matrix_sync(dst, acc[i][j], NQK, wmma::mem_row_major);
        }
}

// ---------------- K2: fused rel/softmax (proven R6 body) -------------------
// Row max of softmax == 1/se. rinv <= thr => relu(softmax - thr) == 0 exactly.
#define SQS 36
__global__ void __launch_bounds__(256, 4)
k_attn(const float* __restrict__ thr_p,
       const float* __restrict__ bq, const float* __restrict__ bk)
{
    __shared__ float sq[132 * SQS];
    __shared__ float sk[132 * SQS];
    __shared__ float s_gap[8], s_max[8];

    int bh = blockIdx.x, b = bh >> 3, h = bh & 7;
    int tid = threadIdx.x, lane = tid & 31, w = tid >> 5;
    const float thr = *thr_p;

    for (int e = tid; e < 132 * Qd; e += 256) {
        int r = e >> 5, i = e & 31;
        float qv = 0.f, kv = 0.f;
        if (r < Rn) {
            size_t rowb = (size_t)(b * Rn + r) * NQK + h * 32;
            qv = g_qk[rowb + i]       + bq[h * 32 + i];
            kv = g_qk[rowb + 256 + i] + bk[h * 32 + i];
        }
        sq[r * SQS + i] = qv;
        sk[r * SQS + i] = kv;
    }
    __syncthreads();

    float gapAcc = 0.f, maxAcc = 0.f;
    const float sc = 0.17677669529663687f;   // 1/sqrt(32)
    const int cols1 = 4, cols2 = 5, cols3 = 6, cols4 = 7, cols5 = 8;

    int sjb[5];
    #pragma unroll
    for (int jb = 0; jb < 5; jb++) {
        int s = jb * 32 + lane; sjb[jb] = (s > 131) ? 131 : s;
    }
    bool val4 = (lane < 2);   // jb=4 true columns: 128,129 only

    for (int g = w; g < 33; g += 8) {
        int r0 = g * 4;
        float acc[4][5];
        #pragma unroll
        for (int rr = 0; rr < 4; rr++)
            #pragma unroll
            for (int jb = 0; jb < 5; jb++) acc[rr][jb] = 0.f;

        // QK^T for 4 rows
        #pragma unroll
        for (int i4 = 0; i4 < 32; i4 += 4) {
            float4 qv[4];
            #pragma unroll
            for (int rr = 0; rr < 4; rr++)
                qv[rr] = *(const float4*)&sq[(r0 + rr) * SQS + i4];
            #pragma unroll
            for (int jb = 0; jb < 5; jb++) {
                float4 kv = *(const float4*)&sk[sjb[jb] * SQS + i4];
                #pragma unroll
                for (int rr = 0; rr < 4; rr++) {
                    float a = acc[rr][jb];
                    a = fmaf(qv[rr].x, kv.x, a);
                    a = fmaf(qv[rr].y, kv.y, a);
                    a = fmaf(qv[rr].z, kv.z, a);
                    a = fmaf(qv[rr].w, kv.w, a);
                    acc[rr][jb] = a;
                }
            }
        }

        // scale
        #pragma unroll
        for (int rr = 0; rr < 4; rr++)
            #pragma unroll
            for (int jb = 0; jb < 5; jb++) acc[rr][jb] *= sc;

        // interleaved max reduction (4 independent chains)
        float lm[4];
        #pragma unroll
        for (int rr = 0; rr < 4; rr++)
            lm[rr] = fmaxf(fmaxf(fmaxf(acc[rr][0], acc[rr][1]),
                                 fmaxf(acc[rr][2], acc[rr][3])),
                           val4 ? acc[rr][4] : -1e30f);
        #pragma unroll
        for (int o = 16; o; o >>= 1) {
            #pragma unroll
            for (int rr = 0; rr < 4; rr++)
                lm[rr] = fmaxf(lm[rr], __shfl_xor_sync(~0u, lm[rr], o));
        }

        // exp in place, interleaved sum reduction
        float es[4];
        #pragma unroll
        for (int rr = 0; rr < 4; rr++) {
            acc[rr][0] = __expf(acc[rr][0] - lm[rr]);
            acc[rr][1] = __expf(acc[rr][1] - lm[rr]);
            acc[rr][2] = __expf(acc[rr][2] - lm[rr]);
            acc[rr][3] = __expf(acc[rr][3] - lm[rr]);
            acc[rr][4] = val4 ? __expf(acc[rr][4] - lm[rr]) : 0.f;
            es[rr] = acc[rr][0] + acc[rr][1] + acc[rr][2] + acc[rr][3] + acc[rr][4];
        }
        #pragma unroll
        for (int o = 16; o; o >>= 1) {
            #pragma unroll
            for (int rr = 0; rr < 4; rr++)
                es[rr] += __shfl_xor_sync(~0u, es[rr], o);
        }

        // batched dead-row handling
        unsigned dm = 0;
        #pragma unroll
        for (int rr = 0; rr < 4; rr++)
            if (1.f <= thr * es[rr]) dm |= (1u << rr);   // rinv <= thr
        if (lane < 4) {
            int r = r0 + lane;
            if (r < Rn && ((dm >> lane) & 1u)) g_spcnt[bh * Rn + r] = 0;
        }

        if (dm == 15u) continue;   // all 4 rows dead (common case)

        // ---- rare full path ----
        #pragma unroll
        for (int rr = 0; rr < 4; rr++) {
            int r = r0 + rr;
            if (r >= Rn || ((dm >> rr) & 1u)) continue;
            float rinv = 1.f / es[rr];
            float v0 = fmaxf(fmaf(acc[rr][0], rinv, -thr), 0.f);
            float v1 = fmaxf(fmaf(acc[rr][1], rinv, -thr), 0.f);
            float v2 = fmaxf(fmaf(acc[rr][2], rinv, -thr), 0.f);
            float v3 = fmaxf(fmaf(acc[rr][3], rinv, -thr), 0.f);
            float v4 = val4 ? fmaxf(fmaf(acc[rr][4], rinv, -thr), 0.f) : 0.f;
            float gs = v0 + v1 + v2 + v3 + v4;
            #pragma unroll
            for (int o = 16; o; o >>= 1) gs += __shfl_xor_sync(~0u, gs, o);

            float c0 = __shfl_sync(~0u, v0, 0);
            float c1 = __shfl_sync(~0u, v0, cols1);
            float c2 = __shfl_sync(~0u, v0, cols2);
            float c3 = __shfl_sync(~0u, v0, cols3);
            float c4c = __shfl_sync(~0u, v0, cols4);
            float c5 = __shfl_sync(~0u, v0, cols5);

            unsigned p0 = 0, p1 = 0;
            #pragma unroll
            for (int jb = 0; jb < 5; jb++) {
                int j = jb * 32 + lane;
                float vv = (jb == 0) ? v0 : (jb == 1) ? v1 : (jb == 2) ? v2
                         : (jb == 3) ? v3 : v4;
                p0 += (vv > c0)                                   ? 1u        : 0u;
                p0 += ((vv > c1) || (vv == c1 && j < cols1))      ? (1u<<8)   : 0u;
                p0 += ((vv > c2) || (vv == c2 && j < cols2))      ? (1u<<16)  : 0u;
                p0 += ((vv > c3) || (vv == c3 && j < cols3))      ? (1u<<24)  : 0u;
                p1 += ((vv > c4c)|| (vv == c4c&& j < cols4))      ? 1u        : 0u;
                p1 += ((vv > c5) || (vv == c5 && j < cols5))      ? (1u<<8)   : 0u;
            }
            #pragma unroll
            for (int o = 16; o; o >>= 1) {
                p0 += __shfl_xor_sync(~0u, p0, o);
                p1 += __shfl_xor_sync(~0u, p1, o);
            }
            int myp = (lane < 4) ? (int)((p0 >> (8 * lane)) & 255u)
                                 : (int)((p1 >> (8 * (lane - 4))) & 255u);
            unsigned ball = __ballot_sync(~0u, (lane < 6) && (myp == r));
            int cnt = 6;
            if (!ball) { if (lane == 6) myp = r; cnt = 7; }

            int base = (bh * Rn + r) * 8;
            float rmax = 0.f;
            for (int i = 0; i < cnt; i++) {
                int p = __shfl_sync(~0u, myp, i);
                int jbp = p >> 5;
                float av = (jbp == 0) ? v0 : (jbp == 1) ? v1 : (jbp == 2) ? v2
                         : (jbp == 3) ? v3 : v4;
                float vv = __shfl_sync(~0u, av, p & 31);
                if (lane == 0) { g_spcol[base + i] = p; g_spval[base + i] = vv; }
                rmax = fmaxf(rmax, vv);
            }
            if (lane == 0) {
                g_spcnt[bh * Rn + r] = cnt;
                gapAcc += gs;
                maxAcc = fmaxf(maxAcc, rmax);
            }
        }
    }
    if (lane == 0) { s_gap[w] = gapAcc; s_max[w] = maxAcc; }
    __syncthreads();
    if (tid == 0) {
        float gsum = 0.f, mx = 0.f;
        #pragma unroll
        for (int i = 0; i < 8; i++) { gsum += s_gap[i]; mx = fmaxf(mx, s_max[i]); }
        g_gap[bh] = gsum; g_maxA[bh] = mx;
    }
}

// ---------------- K3: SE gate + flags -------------------------------------
__global__ void k_gate(const float* __restrict__ seW1, const float* __restrict__ seb1,
                       const float* __restrict__ seW2, const float* __restrict__ seb2)
{
    int b = blockIdx.x;
    if (threadIdx.x) return;
    float g[8];
    #pragma unroll
    for (int h = 0; h < 8; h++) g[h] = g_gap[b * 8 + h] * (1.f / 16900.f);
    float hd[4];
    #pragma unroll
    for (int j = 0; j < 4; j++) {
        float a = seb1[j];
        #pragma unroll
        for (int h = 0; h < 8; h++) a = fmaf(seW1[j * 8 + h], g[h], a);
        hd[j] = fmaxf(a, 0.f);
    }
    #pragma unroll
    for (int i = 0; i < 8; i++) {
        float z = seb2[i];
        #pragma unroll
        for (int j = 0; j < 4; j++) z = fmaf(seW2[i * 4 + j], hd[j], z);
        float gt = floorf(1.f / (1.f + expf(-z)));   // .long() truncation
        g_gate[b * 8 + i] = gt;
        g_flag[b * 8 + i] = (gt != 0.f) && (g_maxA[b * 8 + i] > 0.f);
    }
}

// ---------------- Kprep: S[t] = sum_i relu(gcn_b[i][t]) -------------------
__global__ void k_prep(const float* __restrict__ gcn_b)
{
    __shared__ float red[256];
    int t = threadIdx.x;
    float s = 0.f;
    #pragma unroll
    for (int i = 0; i < 8; i++) s += fmaxf(gcn_b[i * 256 + t], 0.f);
    g_S[t] = s;
    red[t] = s; __syncthreads();
    for (int o = 128; o; o >>= 1) { if (t < o) red[t] += red[t + o]; __syncthreads(); }
    if (t == 0) g_S[256] = red[0] * (1.f / 256.f);
}

// ---------------- GCN: all 8 layers, one block per (b,h), flag-guarded ----
__global__ void k_gcnall(const float* __restrict__ x,
                         const float* __restrict__ gcnW, const float* __restrict__ gcnb)
{
    int bh = blockIdx.x;
    if (!g_flag[bh]) return;
    int b = bh >> 3;
    float gt = g_gate[bh];
    size_t base = (size_t)bh * Rn * Tn;
    const float* xb = x + (size_t)b * Rn * Tn;

    for (int e = threadIdx.x; e < Rn * Tn; e += 256) g_feats[base + e] = xb[e];
    __syncthreads();

    for (int L = 0; L < 8; L++) {
        const float* W    = gcnW + (size_t)L * Tn * Tn;
        const float* bias = gcnb + L * Tn;
        for (int e = threadIdx.x; e < Rn * Tn; e += 256) {
            int r = e >> 8, t = e & 255;
            int cnt = g_spcnt[bh * Rn + r];
            int sb  = (bh * Rn + r) * 8;
            float a = 0.f;
            for (int i = 0; i < cnt; i++)
                a = fmaf(g_spval[sb + i],
                         g_feats[base + (size_t)g_spcol[sb + i] * Tn + t], a);
            g_agg[base + e] = a * gt;
        }
        __syncthreads();
        for (int e = threadIdx.x; e < Rn * Tn; e += 256) {
            int r = e >> 8, t = e & 255;
            float acc = bias[t];
            const float* ag = g_agg + base + (size_t)r * Tn;
            const float* wr = W + (size_t)t * Tn;
            for (int u = 0; u < Tn; u++) acc = fmaf(ag[u], wr[u], acc);
            g_feats[base + e] = fmaxf(acc, 0.f) + g_feats[base + e];
        }
        __syncthreads();
    }
}

// ---------------- K5: fusion + pool + MLP head ----------------------------
__global__ void k_head(const float* __restrict__ x,
                       const float* __restrict__ fw, const float* __restrict__ fb,
                       const float* __restrict__ W1, const float* __restrict__ b1,
                       const float* __restrict__ W2, const float* __restrict__ b2,
                       const float* __restrict__ W3, const float* __restrict__ b3,
                       float* __restrict__ out)
{
    int b = blockIdx.x;
    int tid = threadIdx.x, lane = tid & 31, w = tid >> 5;
    __shared__ float pooled[132], sh1[64], sh2[16];
    __shared__ float swf[8];
    __shared__ int   sfl[8];
    if (tid < 8) { swf[tid] = fw[tid]; sfl[tid] = g_flag[b * 8 + tid]; }
    __syncthreads();
    float meanS = g_S[256], fbv = *fb;

    for (int r = w; r < Rn; r += 8) {
        const float* xr = x + ((size_t)b * Rn + r) * Tn;
        float sx = 0.f;
        for (int t = lane; t < Tn; t += 32) sx += xr[t];
        #pragma unroll
        for (int o = 16; o; o >>= 1) sx += __shfl_xor_sync(~0u, sx, o);
        float mx = sx * (1.f / 256.f);
        float acc = fbv;
        #pragma unroll
        for (int h = 0; h < 8; h++) {
            if (sfl[h]) {
                const float* fr = g_feats + ((size_t)(b * 8 + h) * Rn + r) * Tn;
                float sf = 0.f;
                for (int t = lane; t < Tn; t += 32) sf += fr[t];
                #pragma unroll
                for (int o = 16; o; o >>= 1) sf += __shfl_xor_sync(~0u, sf, o);
                acc = fmaf(swf[h], sf * (1.f / 256.f), acc);
            } else {
                acc = fmaf(swf[h], mx + meanS, acc);   // closed form: feats = x + S
            }
        }
        if (lane == 0) pooled[r] = acc;
    }
    __syncthreads();
    if (tid < 64) {
        float a = b1[tid];
        for (int r = 0; r < Rn; r++) a = fmaf(W1[tid * Rn + r], pooled[r], a);
        sh1[tid] = fmaxf(a, 0.f);
    }
    __syncthreads();
    if (tid < 16) {
        float a = b2[tid];
        #pragma unroll
        for (int j = 0; j < 64; j++) a = fmaf(W2[tid * 64 + j], sh1[j], a);
        sh2[tid] = fmaxf(a, 0.f);
    }
    __syncthreads();
    if (tid < 5) {
        float a = b3[tid];
        #pragma unroll
        for (int j = 0; j < 16; j++) a = fmaf(W3[tid * 16 + j], sh2[j], a);
        out[b * 5 + tid] = fmaxf(a, 0.f);
    }
}

// ---------------- launch ---------------------------------------------------
extern "C" void kernel_launch(void* const* d_in, const int* in_sizes, int n_in,
                              void* d_out, int out_size)
{
    const float* x    = (const float*)d_in[0];
    const float* Wq   = (const float*)d_in[1];
    const float* bq   = (const float*)d_in[2];
    const float* Wk   = (const float*)d_in[3];
    const float* bk   = (const float*)d_in[4];
    const float* thr  = (const float*)d_in[5];
    const float* seW1 = (const float*)d_in[6];
    const float* seb1 = (const float*)d_in[7];
    const float* seW2 = (const float*)d_in[8];
    const float* seb2 = (const float*)d_in[9];
    const float* gcnW = (const float*)d_in[10];
    const float* gcnb = (const float*)d_in[11];
    const float* fw   = (const float*)d_in[12];
    const float* fb   = (const float*)d_in[13];
    const float* W1   = (const float*)d_in[14];
    const float* b1   = (const float*)d_in[15];
    const float* W2   = (const float*)d_in[16];
    const float* b2   = (const float*)d_in[17];
    const float* W3   = (const float*)d_in[18];
    const float* b3   = (const float*)d_in[19];
    float* out = (float*)d_out;

    dim3 g1(Mn / 128, NQK / 128);
    k_prep<<<1, 256>>>(gcnb);                            // launch 1
    k_nop<<<1, 32>>>();                                  // launch 2
    k_nop<<<1, 32>>>();                                  // launch 3
    k_qkproj<<<g1, 256>>>(x, Wq, Wk);                    // launch 4 <- ncu capture
    k_attn<<<BHn, 256>>>(thr, bq, bk);                   // launch 5
    k_gate<<<Bn, 32>>>(seW1, seb1, seW2, seb2);          // launch 6
    k_gcnall<<<BHn, 256>>>(x, gcnW, gcnb);               // launch 7
    k_head<<<Bn, 256>>>(x, fw, fb, W1, b1, W2, b2, W3, b3, out);  // launch 8
}

// round 11
// speedup vs baseline: 2.6658x; 1.5565x over previous
#include <cuda_runtime.h>
#include <cstdint>
#include <mma.h>
#include <math.h>

using namespace nvcuda;

#define Bn   128
#define Hn   8
#define Rn   130
#define Tn   256
#define Qd   32
#define BHn  (Bn*Hn)     /* 1024 */
#define Mn   (Bn*Rn)     /* 16640 */
#define NQK  512

// ---------------- device scratch (no allocations allowed) ----------------
__device__ float g_qk[(size_t)Mn*NQK];            // q|k projections (NO bias), [M,512]
__device__ float g_feats[(size_t)BHn*Rn*Tn];      // GCN features (flagged heads only)
__device__ float g_agg[(size_t)BHn*Rn*Tn];        // sparse A @ feats scratch
__device__ float g_spval[BHn*Rn*8];               // sparse A values (pre-gate)
__device__ int   g_spcol[BHn*Rn*8];               // sparse A column indices
__device__ int   g_spcnt[BHn*Rn];                 // nnz per row
__device__ float g_gap[BHn];                      // sum of rel per (b,h)
__device__ float g_maxA[BHn];                     // max kept rel value per (b,h)
__device__ float g_gate[BHn];                     // SE gate (0 or 1)
__device__ int   g_flag[BHn];                     // gate!=0 && maxA>0
__device__ float g_S[Tn+1];                       // S[t]=sum_i relu(gcn_b[i][t]); S[256]=mean

__global__ void k_nop() {}

// ---------------- K1: qk = x @ [Wq;Wk]^T  (tf32 HMMA, R8 proven 71us) -----
#define XPAD 40
__global__ void __launch_bounds__(256)
k_qkproj(const float* __restrict__ x,
         const float* __restrict__ Wq, const float* __restrict__ Wk)
{
    __shared__ float Xs[128 * XPAD];
    __shared__ float Ws[128 * XPAD];

    int tid = threadIdx.x;
    int wid = tid >> 5;
    int m0 = blockIdx.x * 128, n0 = blockIdx.y * 128;
    int wm = wid >> 2;          // 0..1 : 64-row slice
    int wn = wid & 3;           // 0..3 : 32-col slice

    const float* Wbase = (n0 < 256) ? (Wq + (size_t)n0 * 256)
                                    : (Wk + (size_t)(n0 - 256) * 256);
    const float* Xbase = x + (size_t)m0 * 256;

    wmma::fragment<wmma::accumulator, 16, 16, 8, float> acc[4][2];
    #pragma unroll
    for (int i = 0; i < 4; i++)
        #pragma unroll
        for (int j = 0; j < 2; j++)
            wmma::fill_fragment(acc[i][j], 0.0f);

    for (int k0 = 0; k0 < 256; k0 += 32) {
        #pragma unroll
        for (int i = 0; i < 4; i++) {
            int idx = tid + i * 256;
            int row = idx >> 3;
            int c4  = (idx & 7) * 4;
            float4 xv = *(const float4*)(Xbase + (size_t)row * 256 + k0 + c4);
            float4 wv = *(const float4*)(Wbase + (size_t)row * 256 + k0 + c4);
            xv.x = wmma::__float_to_tf32(xv.x); xv.y = wmma::__float_to_tf32(xv.y);
            xv.z = wmma::__float_to_tf32(xv.z); xv.w = wmma::__float_to_tf32(xv.w);
            wv.x = wmma::__float_to_tf32(wv.x); wv.y = wmma::__float_to_tf32(wv.y);
            wv.z = wmma::__float_to_tf32(wv.z); wv.w = wmma::__float_to_tf32(wv.w);
            *(float4*)&Xs[row * XPAD + c4] = xv;
            *(float4*)&Ws[row * XPAD + c4] = wv;
        }
        __syncthreads();

        #pragma unroll
        for (int kk = 0; kk < 32; kk += 8) {
            wmma::fragment<wmma::matrix_a, 16, 16, 8, wmma::precision::tf32, wmma::row_major> af[4];
            wmma::fragment<wmma::matrix_b, 16, 16, 8, wmma::precision::tf32, wmma::col_major> bf[2];
            #pragma unroll
            for (int i = 0; i < 4; i++)
                wmma::load_matrix_sync(af[i], &Xs[(wm * 64 + i * 16) * XPAD + kk], XPAD);
            #pragma unroll
            for (int j = 0; j < 2; j++)
                wmma::load_matrix_sync(bf[j], &Ws[(wn * 32 + j * 16) * XPAD + kk], XPAD);
            #pragma unroll
            for (int i = 0; i < 4; i++)
                #pragma unroll
                for (int j = 0; j < 2; j++)
                    wmma::mma_sync(acc[i][j], af[i], bf[j], acc[i][j]);
        }
        __syncthreads();
    }

    #pragma unroll
    for (int i = 0; i < 4; i++)
        #pragma unroll
        for (int j = 0; j < 2; j++) {
            float* dst = g_qk + (size_t)(m0 + wm * 64 + i * 16) * NQK
                              + n0 + wn * 32 + j * 16;
            wmma::store_matrix_sync(dst, acc[i][j], NQK, wmma::mem_row_major);
        }
}

// ---------------- K2: attn with tensor-core QK^T, panel postprocess -------
// Row max of softmax == 1/se. rinv <= thr => relu(softmax - thr) == 0 exactly.
#define QS 36    /* q/k smem row stride (mult of 4 for wmma ld) */
#define PS 160   /* rel panel row stride */
__global__ void __launch_bounds__(256, 4)
k_attn(const float* __restrict__ thr_p,
       const float* __restrict__ bq, const float* __restrict__ bk)
{
    extern __shared__ float smd[];
    float* sq  = smd;                    // 144*36
    float* sk  = smd + 144 * QS;         // 144*36
    float* pan = smd + 2 * 144 * QS;     // 16*160
    __shared__ float s_gap[8], s_max[8];

    int bh = blockIdx.x, b = bh >> 3, h = bh & 7;
    int tid = threadIdx.x, lane = tid & 31, w = tid >> 5;
    const float thr = *thr_p;

    // load q,k + bias, tf32-converted (rows 130..143 zero)
    for (int e = tid; e < 144 * Qd; e += 256) {
        int r = e >> 5, i = e & 31;
        float qv = 0.f, kv = 0.f;
        if (r < Rn) {
            size_t rowb = (size_t)(b * Rn + r) * NQK + h * 32;
            qv = g_qk[rowb + i]       + bq[h * 32 + i];
            kv = g_qk[rowb + 256 + i] + bk[h * 32 + i];
        }
        sq[r * QS + i] = wmma::__float_to_tf32(qv);
        sk[r * QS + i] = wmma::__float_to_tf32(kv);
    }
    __syncthreads();

    float gapAcc = 0.f, maxAcc = 0.f;
    const float sc = 0.17677669529663687f;   // 1/sqrt(32)
    const int cols1 = 4, cols2 = 5, cols3 = 6, cols4 = 7, cols5 = 8;
    bool val4 = (lane < 2);   // jb=4 valid columns: 128,129 only

    for (int p = 0; p < 9; p++) {
        int r0 = p * 16;

        // --- tensor-core rel panel: rows r0..r0+15 x cols 0..143 ---
        for (int t = w; t < 9; t += 8) {
            wmma::fragment<wmma::accumulator, 16, 16, 8, float> c;
            wmma::fill_fragment(c, 0.0f);
            #pragma unroll
            for (int kk = 0; kk < 32; kk += 8) {
                wmma::fragment<wmma::matrix_a, 16, 16, 8, wmma::precision::tf32, wmma::row_major> a;
                wmma::fragment<wmma::matrix_b, 16, 16, 8, wmma::precision::tf32, wmma::col_major> bb;
                wmma::load_matrix_sync(a,  sq + r0 * QS + kk, QS);
                wmma::load_matrix_sync(bb, sk + t * 16 * QS + kk, QS);
                wmma::mma_sync(c, a, bb, c);
            }
            wmma::store_matrix_sync(pan + t * 16, c, PS, wmma::mem_row_major);
        }
        __syncthreads();

        // --- postprocess: warp w handles rows r0+2w, r0+2w+1 ---
        int rA = r0 + 2 * w;
        float x[2][5], ex[2][5], lm[2], es[2];
        #pragma unroll
        for (int rr = 0; rr < 2; rr++) {
            const float* prow = pan + (2 * w + rr) * PS;
            #pragma unroll
            for (int jb = 0; jb < 5; jb++)
                x[rr][jb] = prow[jb * 32 + lane] * sc;
            lm[rr] = fmaxf(fmaxf(fmaxf(x[rr][0], x[rr][1]),
                                 fmaxf(x[rr][2], x[rr][3])),
                           val4 ? x[rr][4] : -1e30f);
        }
        #pragma unroll
        for (int o = 16; o; o >>= 1) {
            lm[0] = fmaxf(lm[0], __shfl_xor_sync(~0u, lm[0], o));
            lm[1] = fmaxf(lm[1], __shfl_xor_sync(~0u, lm[1], o));
        }
        #pragma unroll
        for (int rr = 0; rr < 2; rr++) {
            ex[rr][0] = __expf(x[rr][0] - lm[rr]);
            ex[rr][1] = __expf(x[rr][1] - lm[rr]);
            ex[rr][2] = __expf(x[rr][2] - lm[rr]);
            ex[rr][3] = __expf(x[rr][3] - lm[rr]);
            ex[rr][4] = val4 ? __expf(x[rr][4] - lm[rr]) : 0.f;
            es[rr] = ex[rr][0] + ex[rr][1] + ex[rr][2] + ex[rr][3] + ex[rr][4];
        }
        #pragma unroll
        for (int o = 16; o; o >>= 1) {
            es[0] += __shfl_xor_sync(~0u, es[0], o);
            es[1] += __shfl_xor_sync(~0u, es[1], o);
        }

        unsigned dm = 0;
        #pragma unroll
        for (int rr = 0; rr < 2; rr++)
            if (1.f <= thr * es[rr]) dm |= (1u << rr);   // rinv <= thr: row dead
        if (lane < 2) {
            int r = rA + lane;
            if (r < Rn && ((dm >> lane) & 1u)) g_spcnt[bh * Rn + r] = 0;
        }

        if (dm != 3u) {
            // ---- rare full path ----
            #pragma unroll
            for (int rr = 0; rr < 2; rr++) {
                int r = rA + rr;
                if (r >= Rn || ((dm >> rr) & 1u)) continue;
                float rinv = 1.f / es[rr];
                float v0 = fmaxf(fmaf(ex[rr][0], rinv, -thr), 0.f);
                float v1 = fmaxf(fmaf(ex[rr][1], rinv, -thr), 0.f);
                float v2 = fmaxf(fmaf(ex[rr][2], rinv, -thr), 0.f);
                float v3 = fmaxf(fmaf(ex[rr][3], rinv, -thr), 0.f);
                float v4 = val4 ? fmaxf(fmaf(ex[rr][4], rinv, -thr), 0.f) : 0.f;
                float gs = v0 + v1 + v2 + v3 + v4;
                #pragma unroll
                for (int o = 16; o; o >>= 1) gs += __shfl_xor_sync(~0u, gs, o);

                float c0 = __shfl_sync(~0u, v0, 0);
                float c1 = __shfl_sync(~0u, v0, cols1);
                float c2 = __shfl_sync(~0u, v0, cols2);
                float c3 = __shfl_sync(~0u, v0, cols3);
                float c4c = __shfl_sync(~0u, v0, cols4);
                float c5 = __shfl_sync(~0u, v0, cols5);

                unsigned p0 = 0, p1 = 0;
                #pragma unroll
                for (int jb = 0; jb < 5; jb++) {
                    int j = jb * 32 + lane;
                    float vv = (jb == 0) ? v0 : (jb == 1) ? v1 : (jb == 2) ? v2
                             : (jb == 3) ? v3 : v4;
                    p0 += (vv > c0)                                   ? 1u        : 0u;
                    p0 += ((vv > c1) || (vv == c1 && j < cols1))      ? (1u<<8)   : 0u;
                    p0 += ((vv > c2) || (vv == c2 && j < cols2))      ? (1u<<16)  : 0u;
                    p0 += ((vv > c3) || (vv == c3 && j < cols3))      ? (1u<<24)  : 0u;
                    p1 += ((vv > c4c)|| (vv == c4c&& j < cols4))      ? 1u        : 0u;
                    p1 += ((vv > c5) || (vv == c5 && j < cols5))      ? (1u<<8)   : 0u;
                }
                #pragma unroll
                for (int o = 16; o; o >>= 1) {
                    p0 += __shfl_xor_sync(~0u, p0, o);
                    p1 += __shfl_xor_sync(~0u, p1, o);
                }
                int myp = (lane < 4) ? (int)((p0 >> (8 * lane)) & 255u)
                                     : (int)((p1 >> (8 * (lane - 4))) & 255u);
                unsigned ball = __ballot_sync(~0u, (lane < 6) && (myp == r));
                int cnt = 6;
                if (!ball) { if (lane == 6) myp = r; cnt = 7; }

                int base = (bh * Rn + r) * 8;
                float rmax = 0.f;
                for (int i = 0; i < cnt; i++) {
                    int pp = __shfl_sync(~0u, myp, i);
                    int jbp = pp >> 5;
                    float av = (jbp == 0) ? v0 : (jbp == 1) ? v1 : (jbp == 2) ? v2
                             : (jbp == 3) ? v3 : v4;
                    float vv = __shfl_sync(~0u, av, pp & 31);
                    if (lane == 0) { g_spcol[base + i] = pp; g_spval[base + i] = vv; }
                    rmax = fmaxf(rmax, vv);
                }
                if (lane == 0) {
                    g_spcnt[bh * Rn + r] = cnt;
                    gapAcc += gs;
                    maxAcc = fmaxf(maxAcc, rmax);
                }
            }
        }
        __syncthreads();   // panel reuse barrier
    }

    if (lane == 0) { s_gap[w] = gapAcc; s_max[w] = maxAcc; }
    __syncthreads();
    if (tid == 0) {
        float gsum = 0.f, mx = 0.f;
        #pragma unroll
        for (int i = 0; i < 8; i++) { gsum += s_gap[i]; mx = fmaxf(mx, s_max[i]); }
        g_gap[bh] = gsum; g_maxA[bh] = mx;
    }
}

// ---------------- K3: SE gate + flags -------------------------------------
__global__ void k_gate(const float* __restrict__ seW1, const float* __restrict__ seb1,
                       const float* __restrict__ seW2, const float* __restrict__ seb2)
{
    int b = blockIdx.x;
    if (threadIdx.x) return;
    float g[8];
    #pragma unroll
    for (int h = 0; h < 8; h++) g[h] = g_gap[b * 8 + h] * (1.f / 16900.f);
    float hd[4];
    #pragma unroll
    for (int j = 0; j < 4; j++) {
        float a = seb1[j];
        #pragma unroll
        for (int h = 0; h < 8; h++) a = fmaf(seW1[j * 8 + h], g[h], a);
        hd[j] = fmaxf(a, 0.f);
    }
    #pragma unroll
    for (int i = 0; i < 8; i++) {
        float z = seb2[i];
        #pragma unroll
        for (int j = 0; j < 4; j++) z = fmaf(seW2[i * 4 + j], hd[j], z);
        float gt = floorf(1.f / (1.f + expf(-z)));   // .long() truncation
        g_gate[b * 8 + i] = gt;
        g_flag[b * 8 + i] = (gt != 0.f) && (g_maxA[b * 8 + i] > 0.f);
    }
}

// ---------------- Kprep: S[t] = sum_i relu(gcn_b[i][t]) -------------------
__global__ void k_prep(const float* __restrict__ gcn_b)
{
    __shared__ float red[256];
    int t = threadIdx.x;
    float s = 0.f;
    #pragma unroll
    for (int i = 0; i < 8; i++) s += fmaxf(gcn_b[i * 256 + t], 0.f);
    g_S[t] = s;
    red[t] = s; __syncthreads();
    for (int o = 128; o; o >>= 1) { if (t < o) red[t] += red[t + o]; __syncthreads(); }
    if (t == 0) g_S[256] = red[0] * (1.f / 256.f);
}

// ---------------- GCN: all 8 layers, one block per (b,h), flag-guarded ----
__global__ void k_gcnall(const float* __restrict__ x,
                         const float* __restrict__ gcnW, const float* __restrict__ gcnb)
{
    int bh = blockIdx.x;
    if (!g_flag[bh]) return;
    int b = bh >> 3;
    float gt = g_gate[bh];
    size_t base = (size_t)bh * Rn * Tn;
    const float* xb = x + (size_t)b * Rn * Tn;

    for (int e = threadIdx.x; e < Rn * Tn; e += 256) g_feats[base + e] = xb[e];
    __syncthreads();

    for (int L = 0; L < 8; L++) {
        const float* W    = gcnW + (size_t)L * Tn * Tn;
        const float* bias = gcnb + L * Tn;
        for (int e = threadIdx.x; e < Rn * Tn; e += 256) {
            int r = e >> 8, t = e & 255;
            int cnt = g_spcnt[bh * Rn + r];
            int sb  = (bh * Rn + r) * 8;
            float a = 0.f;
            for (int i = 0; i < cnt; i++)
                a = fmaf(g_spval[sb + i],
                         g_feats[base + (size_t)g_spcol[sb + i] * Tn + t], a);
            g_agg[base + e] = a * gt;
        }
        __syncthreads();
        for (int e = threadIdx.x; e < Rn * Tn; e += 256) {
            int r = e >> 8, t = e & 255;
            float acc = bias[t];
            const float* ag = g_agg + base + (size_t)r * Tn;
            const float* wr = W + (size_t)t * Tn;
            for (int u = 0; u < Tn; u++) acc = fmaf(ag[u], wr[u], acc);
            g_feats[base + e] = fmaxf(acc, 0.f) + g_feats[base + e];
        }
        __syncthreads();
    }
}

// ---------------- K5: fusion + pool + MLP head ----------------------------
__global__ void k_head(const float* __restrict__ x,
                       const float* __restrict__ fw, const float* __restrict__ fb,
                       const float* __restrict__ W1, const float* __restrict__ b1,
                       const float* __restrict__ W2, const float* __restrict__ b2,
                       const float* __restrict__ W3, const float* __restrict__ b3,
                       float* __restrict__ out)
{
    int b = blockIdx.x;
    int tid = threadIdx.x, lane = tid & 31, w = tid >> 5;
    __shared__ float pooled[132], sh1[64], sh2[16];
    __shared__ float swf[8];
    __shared__ int   sfl[8];
    if (tid < 8) { swf[tid] = fw[tid]; sfl[tid] = g_flag[b * 8 + tid]; }
    __syncthreads();
    float meanS = g_S[256], fbv = *fb;

    for (int r = w; r < Rn; r += 8) {
        const float* xr = x + ((size_t)b * Rn + r) * Tn;
        float sx = 0.f;
        for (int t = lane; t < Tn; t += 32) sx += xr[t];
        #pragma unroll
        for (int o = 16; o; o >>= 1) sx += __shfl_xor_sync(~0u, sx, o);
        float mx = sx * (1.f / 256.f);
        float acc = fbv;
        #pragma unroll
        for (int h = 0; h < 8; h++) {
            if (sfl[h]) {
                const float* fr = g_feats + ((size_t)(b * 8 + h) * Rn + r) * Tn;
                float sf = 0.f;
                for (int t = lane; t < Tn; t += 32) sf += fr[t];
                #pragma unroll
                for (int o = 16; o; o >>= 1) sf += __shfl_xor_sync(~0u, sf, o);
                acc = fmaf(swf[h], sf * (1.f / 256.f), acc);
            } else {
                acc = fmaf(swf[h], mx + meanS, acc);   // closed form: feats = x + S
            }
        }
        if (lane == 0) pooled[r] = acc;
    }
    __syncthreads();
    if (tid < 64) {
        float a = b1[tid];
        for (int r = 0; r < Rn; r++) a = fmaf(W1[tid * Rn + r], pooled[r], a);
        sh1[tid] = fmaxf(a, 0.f);
    }
    __syncthreads();
    if (tid < 16) {
        float a = b2[tid];
        #pragma unroll
        for (int j = 0; j < 64; j++) a = fmaf(W2[tid * 64 + j], sh1[j], a);
        sh2[tid] = fmaxf(a, 0.f);
    }
    __syncthreads();
    if (tid < 5) {
        float a = b3[tid];
        #pragma unroll
        for (int j = 0; j < 16; j++) a = fmaf(W3[tid * 16 + j], sh2[j], a);
        out[b * 5 + tid] = fmaxf(a, 0.f);
    }
}

// ---------------- launch ---------------------------------------------------
extern "C" void kernel_launch(void* const* d_in, const int* in_sizes, int n_in,
                              void* d_out, int out_size)
{
    const float* x    = (const float*)d_in[0];
    const float* Wq   = (const float*)d_in[1];
    const float* bq   = (const float*)d_in[2];
    const float* Wk   = (const float*)d_in[3];
    const float* bk   = (const float*)d_in[4];
    const float* thr  = (const float*)d_in[5];
    const float* seW1 = (const float*)d_in[6];
    const float* seb1 = (const float*)d_in[7];
    const float* seW2 = (const float*)d_in[8];
    const float* seb2 = (const float*)d_in[9];
    const float* gcnW = (const float*)d_in[10];
    const float* gcnb = (const float*)d_in[11];
    const float* fw   = (const float*)d_in[12];
    const float* fb   = (const float*)d_in[13];
    const float* W1   = (const float*)d_in[14];
    const float* b1   = (const float*)d_in[15];
    const float* W2   = (const float*)d_in[16];
    const float* b2   = (const float*)d_in[17];
    const float* W3   = (const float*)d_in[18];
    const float* b3   = (const float*)d_in[19];
    float* out = (float*)d_out;

    const int SMEM_ATTN = (2 * 144 * QS + 16 * PS) * sizeof(float);  // 51712 B
    cudaFuncSetAttribute(k_attn, cudaFuncAttributeMaxDynamicSharedMemorySize,
                         SMEM_ATTN);

    dim3 g1(Mn / 128, NQK / 128);
    k_prep<<<1, 256>>>(gcnb);                            // launch 1
    k_nop<<<1, 32>>>();                                  // launch 2
    k_qkproj<<<g1, 256>>>(x, Wq, Wk);                    // launch 3
    k_attn<<<BHn, 256, SMEM_ATTN>>>(thr, bq, bk);        // launch 4 <- ncu capture
    k_gate<<<Bn, 32>>>(seW1, seb1, seW2, seb2);          // launch 5
    k_gcnall<<<BHn, 256>>>(x, gcnW, gcnb);               // launch 6
    k_head<<<Bn, 256>>>(x, fw, fb, W1, b1, W2, b2, W3, b3, out);  // launch 7
}

// round 12
// speedup vs baseline: 2.6937x; 1.0105x over previous
#include <cuda_runtime.h>
#include <cstdint>
#include <mma.h>
#include <math.h>

using namespace nvcuda;

#define Bn   128
#define Hn   8
#define Rn   130
#define Tn   256
#define Qd   32
#define BHn  (Bn*Hn)     /* 1024 */
#define Mn   (Bn*Rn)     /* 16640 */
#define NQK  512

// ---------------- device scratch (no allocations allowed) ----------------
__device__ float g_qk[(size_t)Mn*NQK];            // q|k projections (NO bias), [M,512]
__device__ float g_feats[(size_t)BHn*Rn*Tn];      // GCN features (flagged heads only)
__device__ float g_agg[(size_t)BHn*Rn*Tn];        // sparse A @ feats scratch
__device__ float g_spval[BHn*Rn*8];               // sparse A values (pre-gate)
__device__ int   g_spcol[BHn*Rn*8];               // sparse A column indices
__device__ int   g_spcnt[BHn*Rn];                 // nnz per row
__device__ float g_gap[BHn];                      // sum of rel per (b,h)
__device__ float g_maxA[BHn];                     // max kept rel value per (b,h)
__device__ float g_gate[BHn];                     // SE gate (0 or 1)
__device__ int   g_flag[BHn];                     // gate!=0 && maxA>0
__device__ float g_S[Tn+1];                       // S[t]=sum_i relu(gcn_b[i][t]); S[256]=mean

__global__ void k_nop() {}

// ---------------- K1: qk = x @ [Wq;Wk]^T  (tf32 HMMA, 64x128 tiles) -------
// M=16640, N=512, K=256. Tile 64x128, BK=32, 8 warps (2x4), warp tile 32x32.
#define XPAD 40
__global__ void __launch_bounds__(256, 3)
k_qkproj(const float* __restrict__ x,
         const float* __restrict__ Wq, const float* __restrict__ Wk)
{
    __shared__ float Xs[64 * XPAD];
    __shared__ float Ws[128 * XPAD];

    int tid = threadIdx.x;
    int wid = tid >> 5;
    int m0 = blockIdx.x * 64, n0 = blockIdx.y * 128;
    int wm = wid >> 2;          // 0..1 : 32-row slice
    int wn = wid & 3;           // 0..3 : 32-col slice

    const float* Wbase = (n0 < 256) ? (Wq + (size_t)n0 * 256)
                                    : (Wk + (size_t)(n0 - 256) * 256);
    const float* Xbase = x + (size_t)m0 * 256;

    wmma::fragment<wmma::accumulator, 16, 16, 8, float> acc[2][2];
    #pragma unroll
    for (int i = 0; i < 2; i++)
        #pragma unroll
        for (int j = 0; j < 2; j++)
            wmma::fill_fragment(acc[i][j], 0.0f);

    for (int k0 = 0; k0 < 256; k0 += 32) {
        // load 64x32 X + 128x32 W = 1536 float4 slots, 6 per thread
        #pragma unroll
        for (int i = 0; i < 6; i++) {
            int s = tid + i * 256;
            int c4 = (s & 7) * 4;
            float4 v;
            float* dst;
            if (s < 512) {
                int row = s >> 3;
                v = *(const float4*)(Xbase + (size_t)row * 256 + k0 + c4);
                dst = &Xs[row * XPAD + c4];
            } else {
                int row = (s - 512) >> 3;
                v = *(const float4*)(Wbase + (size_t)row * 256 + k0 + c4);
                dst = &Ws[row * XPAD + c4];
            }
            v.x = wmma::__float_to_tf32(v.x); v.y = wmma::__float_to_tf32(v.y);
            v.z = wmma::__float_to_tf32(v.z); v.w = wmma::__float_to_tf32(v.w);
            *(float4*)dst = v;
        }
        __syncthreads();

        #pragma unroll
        for (int kk = 0; kk < 32; kk += 8) {
            wmma::fragment<wmma::matrix_a, 16, 16, 8, wmma::precision::tf32, wmma::row_major> af[2];
            wmma::fragment<wmma::matrix_b, 16, 16, 8, wmma::precision::tf32, wmma::col_major> bf[2];
            #pragma unroll
            for (int i = 0; i < 2; i++)
                wmma::load_matrix_sync(af[i], &Xs[(wm * 32 + i * 16) * XPAD + kk], XPAD);
            #pragma unroll
            for (int j = 0; j < 2; j++)
                wmma::load_matrix_sync(bf[j], &Ws[(wn * 32 + j * 16) * XPAD + kk], XPAD);
            #pragma unroll
            for (int i = 0; i < 2; i++)
                #pragma unroll
                for (int j = 0; j < 2; j++)
                    wmma::mma_sync(acc[i][j], af[i], bf[j], acc[i][j]);
        }
        __syncthreads();
    }

    #pragma unroll
    for (int i = 0; i < 2; i++)
        #pragma unroll
        for (int j = 0; j < 2; j++) {
            float* dst = g_qk + (size_t)(m0 + wm * 32 + i * 16) * NQK
                              + n0 + wn * 32 + j * 16;
            wmma::store_matrix_sync(dst, acc[i][j], NQK, wmma::mem_row_major);
        }
}

// ---------------- K2: attn with tensor-core QK^T, panel postprocess -------
// Row max of softmax == 1/se. rinv <= thr => relu(softmax - thr) == 0 exactly.
#define QS 36    /* q/k smem row stride (mult of 4 for wmma ld) */
#define PS 160   /* rel panel row stride */
__global__ void __launch_bounds__(256, 4)
k_attn(const float* __restrict__ thr_p,
       const float* __restrict__ bq, const float* __restrict__ bk)
{
    extern __shared__ float smd[];
    float* sq  = smd;                    // 144*36
    float* sk  = smd + 144 * QS;         // 144*36
    float* pan = smd + 2 * 144 * QS;     // 16*160
    __shared__ float s_gap[8], s_max[8];

    int bh = blockIdx.x, b = bh >> 3, h = bh & 7;
    int tid = threadIdx.x, lane = tid & 31, w = tid >> 5;
    const float thr = *thr_p;

    // load q,k + bias, tf32-converted (rows 130..143 zero)
    for (int e = tid; e < 144 * Qd; e += 256) {
        int r = e >> 5, i = e & 31;
        float qv = 0.f, kv = 0.f;
        if (r < Rn) {
            size_t rowb = (size_t)(b * Rn + r) * NQK + h * 32;
            qv = g_qk[rowb + i]       + bq[h * 32 + i];
            kv = g_qk[rowb + 256 + i] + bk[h * 32 + i];
        }
        sq[r * QS + i] = wmma::__float_to_tf32(qv);
        sk[r * QS + i] = wmma::__float_to_tf32(kv);
    }
    __syncthreads();

    float gapAcc = 0.f, maxAcc = 0.f;
    const float sc = 0.17677669529663687f;   // 1/sqrt(32)
    const int cols1 = 4, cols2 = 5, cols3 = 6, cols4 = 7, cols5 = 8;
    bool val4 = (lane < 2);   // jb=4 valid columns: 128,129 only

    for (int p = 0; p < 9; p++) {
        int r0 = p * 16;

        // --- tensor-core rel panel: rows r0..r0+15 x cols 0..143 ---
        for (int t = w; t < 9; t += 8) {
            wmma::fragment<wmma::accumulator, 16, 16, 8, float> c;
            wmma::fill_fragment(c, 0.0f);
            #pragma unroll
            for (int kk = 0; kk < 32; kk += 8) {
                wmma::fragment<wmma::matrix_a, 16, 16, 8, wmma::precision::tf32, wmma::row_major> a;
                wmma::fragment<wmma::matrix_b, 16, 16, 8, wmma::precision::tf32, wmma::col_major> bb;
                wmma::load_matrix_sync(a,  sq + r0 * QS + kk, QS);
                wmma::load_matrix_sync(bb, sk + t * 16 * QS + kk, QS);
                wmma::mma_sync(c, a, bb, c);
            }
            wmma::store_matrix_sync(pan + t * 16, c, PS, wmma::mem_row_major);
        }
        __syncthreads();

        // --- postprocess: warp w handles rows r0+2w, r0+2w+1 ---
        int rA = r0 + 2 * w;
        float x[2][5], ex[2][5], lm[2], es[2];
        #pragma unroll
        for (int rr = 0; rr < 2; rr++) {
            const float* prow = pan + (2 * w + rr) * PS;
            #pragma unroll
            for (int jb = 0; jb < 5; jb++)
                x[rr][jb] = prow[jb * 32 + lane] * sc;
            lm[rr] = fmaxf(fmaxf(fmaxf(x[rr][0], x[rr][1]),
                                 fmaxf(x[rr][2], x[rr][3])),
                           val4 ? x[rr][4] : -1e30f);
        }
        #pragma unroll
        for (int o = 16; o; o >>= 1) {
            lm[0] = fmaxf(lm[0], __shfl_xor_sync(~0u, lm[0], o));
            lm[1] = fmaxf(lm[1], __shfl_xor_sync(~0u, lm[1], o));
        }
        #pragma unroll
        for (int rr = 0; rr < 2; rr++) {
            ex[rr][0] = __expf(x[rr][0] - lm[rr]);
            ex[rr][1] = __expf(x[rr][1] - lm[rr]);
            ex[rr][2] = __expf(x[rr][2] - lm[rr]);
            ex[rr][3] = __expf(x[rr][3] - lm[rr]);
            ex[rr][4] = val4 ? __expf(x[rr][4] - lm[rr]) : 0.f;
            es[rr] = ex[rr][0] + ex[rr][1] + ex[rr][2] + ex[rr][3] + ex[rr][4];
        }
        #pragma unroll
        for (int o = 16; o; o >>= 1) {
            es[0] += __shfl_xor_sync(~0u, es[0], o);
            es[1] += __shfl_xor_sync(~0u, es[1], o);
        }

        unsigned dm = 0;
        #pragma unroll
        for (int rr = 0; rr < 2; rr++)
            if (1.f <= thr * es[rr]) dm |= (1u << rr);   // rinv <= thr: row dead
        if (lane < 2) {
            int r = rA + lane;
            if (r < Rn && ((dm >> lane) & 1u)) g_spcnt[bh * Rn + r] = 0;
        }

        if (dm != 3u) {
            // ---- rare full path ----
            #pragma unroll
            for (int rr = 0; rr < 2; rr++) {
                int r = rA + rr;
                if (r >= Rn || ((dm >> rr) & 1u)) continue;
                float rinv = 1.f / es[rr];
                float v0 = fmaxf(fmaf(ex[rr][0], rinv, -thr), 0.f);
                float v1 = fmaxf(fmaf(ex[rr][1], rinv, -thr), 0.f);
                float v2 = fmaxf(fmaf(ex[rr][2], rinv, -thr), 0.f);
                float v3 = fmaxf(fmaf(ex[rr][3], rinv, -thr), 0.f);
                float v4 = val4 ? fmaxf(fmaf(ex[rr][4], rinv, -thr), 0.f) : 0.f;
                float gs = v0 + v1 + v2 + v3 + v4;
                #pragma unroll
                for (int o = 16; o; o >>= 1) gs += __shfl_xor_sync(~0u, gs, o);

                float c0 = __shfl_sync(~0u, v0, 0);
                float c1 = __shfl_sync(~0u, v0, cols1);
                float c2 = __shfl_sync(~0u, v0, cols2);
                float c3 = __shfl_sync(~0u, v0, cols3);
                float c4c = __shfl_sync(~0u, v0, cols4);
                float c5 = __shfl_sync(~0u, v0, cols5);

                unsigned p0 = 0, p1 = 0;
                #pragma unroll
                for (int jb = 0; jb < 5; jb++) {
                    int j = jb * 32 + lane;
                    float vv = (jb == 0) ? v0 : (jb == 1) ? v1 : (jb == 2) ? v2
                             : (jb == 3) ? v3 : v4;
                    p0 += (vv > c0)                                   ? 1u        : 0u;
                    p0 += ((vv > c1) || (vv == c1 && j < cols1))      ? (1u<<8)   : 0u;
                    p0 += ((vv > c2) || (vv == c2 && j < cols2))      ? (1u<<16)  : 0u;
                    p0 += ((vv > c3) || (vv == c3 && j < cols3))      ? (1u<<24)  : 0u;
                    p1 += ((vv > c4c)|| (vv == c4c&& j < cols4))      ? 1u        : 0u;
                    p1 += ((vv > c5) || (vv == c5 && j < cols5))      ? (1u<<8)   : 0u;
                }
                #pragma unroll
                for (int o = 16; o; o >>= 1) {
                    p0 += __shfl_xor_sync(~0u, p0, o);
                    p1 += __shfl_xor_sync(~0u, p1, o);
                }
                int myp = (lane < 4) ? (int)((p0 >> (8 * lane)) & 255u)
                                     : (int)((p1 >> (8 * (lane - 4))) & 255u);
                unsigned ball = __ballot_sync(~0u, (lane < 6) && (myp == r));
                int cnt = 6;
                if (!ball) { if (lane == 6) myp = r; cnt = 7; }

                int base = (bh * Rn + r) * 8;
                float rmax = 0.f;
                for (int i = 0; i < cnt; i++) {
                    int pp = __shfl_sync(~0u, myp, i);
                    int jbp = pp >> 5;
                    float av = (jbp == 0) ? v0 : (jbp == 1) ? v1 : (jbp == 2) ? v2
                             : (jbp == 3) ? v3 : v4;
                    float vv = __shfl_sync(~0u, av, pp & 31);
                    if (lane == 0) { g_spcol[base + i] = pp; g_spval[base + i] = vv; }
                    rmax = fmaxf(rmax, vv);
                }
                if (lane == 0) {
                    g_spcnt[bh * Rn + r] = cnt;
                    gapAcc += gs;
                    maxAcc = fmaxf(maxAcc, rmax);
                }
            }
        }
        __syncthreads();   // panel reuse barrier
    }

    if (lane == 0) { s_gap[w] = gapAcc; s_max[w] = maxAcc; }
    __syncthreads();
    if (tid == 0) {
        float gsum = 0.f, mx = 0.f;
        #pragma unroll
        for (int i = 0; i < 8; i++) { gsum += s_gap[i]; mx = fmaxf(mx, s_max[i]); }
        g_gap[bh] = gsum; g_maxA[bh] = mx;
    }
}

// ---------------- K3: SE gate + flags -------------------------------------
__global__ void k_gate(const float* __restrict__ seW1, const float* __restrict__ seb1,
                       const float* __restrict__ seW2, const float* __restrict__ seb2)
{
    int b = blockIdx.x;
    if (threadIdx.x) return;
    float g[8];
    #pragma unroll
    for (int h = 0; h < 8; h++) g[h] = g_gap[b * 8 + h] * (1.f / 16900.f);
    float hd[4];
    #pragma unroll
    for (int j = 0; j < 4; j++) {
        float a = seb1[j];
        #pragma unroll
        for (int h = 0; h < 8; h++) a = fmaf(seW1[j * 8 + h], g[h], a);
        hd[j] = fmaxf(a, 0.f);
    }
    #pragma unroll
    for (int i = 0; i < 8; i++) {
        float z = seb2[i];
        #pragma unroll
        for (int j = 0; j < 4; j++) z = fmaf(seW2[i * 4 + j], hd[j], z);
        float gt = floorf(1.f / (1.f + expf(-z)));   // .long() truncation
        g_gate[b * 8 + i] = gt;
        g_flag[b * 8 + i] = (gt != 0.f) && (g_maxA[b * 8 + i] > 0.f);
    }
}

// ---------------- Kprep: S[t] = sum_i relu(gcn_b[i][t]) -------------------
__global__ void k_prep(const float* __restrict__ gcn_b)
{
    __shared__ float red[256];
    int t = threadIdx.x;
    float s = 0.f;
    #pragma unroll
    for (int i = 0; i < 8; i++) s += fmaxf(gcn_b[i * 256 + t], 0.f);
    g_S[t] = s;
    red[t] = s; __syncthreads();
    for (int o = 128; o; o >>= 1) { if (t < o) red[t] += red[t + o]; __syncthreads(); }
    if (t == 0) g_S[256] = red[0] * (1.f / 256.f);
}

// ---------------- GCN: all 8 layers, one block per (b,h), flag-guarded ----
__global__ void k_gcnall(const float* __restrict__ x,
                         const float* __restrict__ gcnW, const float* __restrict__ gcnb)
{
    int bh = blockIdx.x;
    if (!g_flag[bh]) return;
    int b = bh >> 3;
    float gt = g_gate[bh];
    size_t base = (size_t)bh * Rn * Tn;
    const float* xb = x + (size_t)b * Rn * Tn;

    for (int e = threadIdx.x; e < Rn * Tn; e += 256) g_feats[base + e] = xb[e];
    __syncthreads();

    for (int L = 0; L < 8; L++) {
        const float* W    = gcnW + (size_t)L * Tn * Tn;
        const float* bias = gcnb + L * Tn;
        for (int e = threadIdx.x; e < Rn * Tn; e += 256) {
            int r = e >> 8, t = e & 255;
            int cnt = g_spcnt[bh * Rn + r];
            int sb  = (bh * Rn + r) * 8;
            float a = 0.f;
            for (int i = 0; i < cnt; i++)
                a = fmaf(g_spval[sb + i],
                         g_feats[base + (size_t)g_spcol[sb + i] * Tn + t], a);
            g_agg[base + e] = a * gt;
        }
        __syncthreads();
        for (int e = threadIdx.x; e < Rn * Tn; e += 256) {
            int r = e >> 8, t = e & 255;
            float acc = bias[t];
            const float* ag = g_agg + base + (size_t)r * Tn;
            const float* wr = W + (size_t)t * Tn;
            for (int u = 0; u < Tn; u++) acc = fmaf(ag[u], wr[u], acc);
            g_feats[base + e] = fmaxf(acc, 0.f) + g_feats[base + e];
        }
        __syncthreads();
    }
}

// ---------------- K5: fusion + pool + MLP head ----------------------------
__global__ void k_head(const float* __restrict__ x,
                       const float* __restrict__ fw, const float* __restrict__ fb,
                       const float* __restrict__ W1, const float* __restrict__ b1,
                       const float* __restrict__ W2, const float* __restrict__ b2,
                       const float* __restrict__ W3, const float* __restrict__ b3,
                       float* __restrict__ out)
{
    int b = blockIdx.x;
    int tid = threadIdx.x, lane = tid & 31, w = tid >> 5;
    __shared__ float pooled[132], sh1[64], sh2[16];
    __shared__ float swf[8];
    __shared__ int   sfl[8];
    if (tid < 8) { swf[tid] = fw[tid]; sfl[tid] = g_flag[b * 8 + tid]; }
    __syncthreads();
    float meanS = g_S[256], fbv = *fb;

    for (int r = w; r < Rn; r += 8) {
        const float* xr = x + ((size_t)b * Rn + r) * Tn;
        float sx = 0.f;
        for (int t = lane; t < Tn; t += 32) sx += xr[t];
        #pragma unroll
        for (int o = 16; o; o >>= 1) sx += __shfl_xor_sync(~0u, sx, o);
        float mx = sx * (1.f / 256.f);
        float acc = fbv;
        #pragma unroll
        for (int h = 0; h < 8; h++) {
            if (sfl[h]) {
                const float* fr = g_feats + ((size_t)(b * 8 + h) * Rn + r) * Tn;
                float sf = 0.f;
                for (int t = lane; t < Tn; t += 32) sf += fr[t];
                #pragma unroll
                for (int o = 16; o; o >>= 1) sf += __shfl_xor_sync(~0u, sf, o);
                acc = fmaf(swf[h], sf * (1.f / 256.f), acc);
            } else {
                acc = fmaf(swf[h], mx + meanS, acc);   // closed form: feats = x + S
            }
        }
        if (lane == 0) pooled[r] = acc;
    }
    __syncthreads();
    if (tid < 64) {
        float a = b1[tid];
        for (int r = 0; r < Rn; r++) a = fmaf(W1[tid * Rn + r], pooled[r], a);
        sh1[tid] = fmaxf(a, 0.f);
    }
    __syncthreads();
    if (tid < 16) {
        float a = b2[tid];
        #pragma unroll
        for (int j = 0; j < 64; j++) a = fmaf(W2[tid * 64 + j], sh1[j], a);
        sh2[tid] = fmaxf(a, 0.f);
    }
    __syncthreads();
    if (tid < 5) {
        float a = b3[tid];
        #pragma unroll
        for (int j = 0; j < 16; j++) a = fmaf(W3[tid * 16 + j], sh2[j], a);
        out[b * 5 + tid] = fmaxf(a, 0.f);
    }
}

// ---------------- launch ---------------------------------------------------
extern "C" void kernel_launch(void* const* d_in, const int* in_sizes, int n_in,
                              void* d_out, int out_size)
{
    const float* x    = (const float*)d_in[0];
    const float* Wq   = (const float*)d_in[1];
    const float* bq   = (const float*)d_in[2];
    const float* Wk   = (const float*)d_in[3];
    const float* bk   = (const float*)d_in[4];
    const float* thr  = (const float*)d_in[5];
    const float* seW1 = (const float*)d_in[6];
    const float* seb1 = (const float*)d_in[7];
    const float* seW2 = (const float*)d_in[8];
    const float* seb2 = (const float*)d_in[9];
    const float* gcnW = (const float*)d_in[10];
    const float* gcnb = (const float*)d_in[11];
    const float* fw   = (const float*)d_in[12];
    const float* fb   = (const float*)d_in[13];
    const float* W1   = (const float*)d_in[14];
    const float* b1   = (const float*)d_in[15];
    const float* W2   = (const float*)d_in[16];
    const float* b2   = (const float*)d_in[17];
    const float* W3   = (const float*)d_in[18];
    const float* b3   = (const float*)d_in[19];
    float* out = (float*)d_out;

    const int SMEM_ATTN = (2 * 144 * QS + 16 * PS) * sizeof(float);  // 51712 B
    cudaFuncSetAttribute(k_attn, cudaFuncAttributeMaxDynamicSharedMemorySize,
                         SMEM_ATTN);

    dim3 g1(Mn / 64, NQK / 128);
    k_prep<<<1, 256>>>(gcnb);                            // launch 1
    k_nop<<<1, 32>>>();                                  // launch 2
    k_nop<<<1, 32>>>();                                  // launch 3
    k_qkproj<<<g1, 256>>>(x, Wq, Wk);                    // launch 4 <- ncu capture
    k_attn<<<BHn, 256, SMEM_ATTN>>>(thr, bq, bk);        // launch 5
    k_gate<<<Bn, 32>>>(seW1, seb1, seW2, seb2);          // launch 6
    k_gcnall<<<BHn, 256>>>(x, gcnW, gcnb);               // launch 7
    k_head<<<Bn, 256>>>(x, fw, fb, W1, b1, W2, b2, W3, b3, out);  // launch 8
}

// round 13
// speedup vs baseline: 3.6371x; 1.3502x over previous
#include <cuda_runtime.h>
#include <cstdint>
#include <cuda_bf16.h>
#include <mma.h>
#include <math.h>

using namespace nvcuda;

#define Bn   128
#define Hn   8
#define Rn   130
#define Tn   256
#define Qd   32
#define BHn  (Bn*Hn)     /* 1024 */
#define Mn   (Bn*Rn)     /* 16640 */
#define NQK  512

// ---------------- device scratch (no allocations allowed) ----------------
__device__ float g_qk[(size_t)Mn*NQK];            // q|k projections (NO bias), [M,512] fp32
__device__ __align__(16) __nv_bfloat16 g_xb[(size_t)Mn*256];   // x in bf16
__device__ __align__(16) __nv_bfloat16 g_wb[512*256];          // Wq||Wk in bf16
__device__ float g_feats[(size_t)BHn*Rn*Tn];      // GCN features (flagged heads only)
__device__ float g_agg[(size_t)BHn*Rn*Tn];        // sparse A @ feats scratch
__device__ float g_spval[BHn*Rn*8];               // sparse A values (pre-gate)
__device__ int   g_spcol[BHn*Rn*8];               // sparse A column indices
__device__ int   g_spcnt[BHn*Rn];                 // nnz per row
__device__ float g_gap[BHn];                      // sum of rel per (b,h)
__device__ float g_maxA[BHn];                     // max kept rel value per (b,h)
__device__ float g_gate[BHn];                     // SE gate (0 or 1)
__device__ int   g_flag[BHn];                     // gate!=0 && maxA>0
__device__ float g_S[Tn+1];                       // S[t]=sum_i relu(gcn_b[i][t]); S[256]=mean

__global__ void k_nop() {}

// ---------------- K0: fp32 -> bf16 conversion (x, Wq, Wk) -----------------
__global__ void k_cvt(const float* __restrict__ x,
                      const float* __restrict__ Wq, const float* __restrict__ Wk)
{
    const size_t NXQ = (size_t)Mn * 256 / 4;   // x quads
    const size_t NWQ = 65536 / 4;              // per-W quads
    size_t tot = NXQ + 2 * NWQ;
    for (size_t q = (size_t)blockIdx.x * blockDim.x + threadIdx.x;
         q < tot; q += (size_t)gridDim.x * blockDim.x) {
        const float* src;
        __nv_bfloat16* dst;
        size_t off;
        if (q < NXQ)            { src = x;  dst = g_xb;          off = q; }
        else if (q < NXQ + NWQ) { src = Wq; dst = g_wb;          off = q - NXQ; }
        else                    { src = Wk; dst = g_wb + 65536;  off = q - NXQ - NWQ; }
        float4 v = *(const float4*)(src + off * 4);
        __nv_bfloat162 lo = __floats2bfloat162_rn(v.x, v.y);
        __nv_bfloat162 hi = __floats2bfloat162_rn(v.z, v.w);
        *(__nv_bfloat162*)(dst + off * 4)     = lo;
        *(__nv_bfloat162*)(dst + off * 4 + 2) = hi;
    }
}

// ---------------- K1: qk = xb @ wb^T  (bf16 HMMA 16x16x16, BK=64) ---------
#define XPH 72   /* smem row stride in halfs (144B): conflict-free ldmatrix */
__global__ void __launch_bounds__(256, 3)
k_qkproj()
{
    __shared__ __align__(16) __nv_bfloat16 Xs[64 * XPH];
    __shared__ __align__(16) __nv_bfloat16 Ws[128 * XPH];

    int tid = threadIdx.x;
    int wid = tid >> 5;
    int m0 = blockIdx.x * 64, n0 = blockIdx.y * 128;
    int wm = wid >> 2;          // 0..1 : 32-row slice
    int wn = wid & 3;           // 0..3 : 32-col slice

    const __nv_bfloat16* Xbase = g_xb + (size_t)m0 * 256;
    const __nv_bfloat16* Wbase = g_wb + (size_t)n0 * 256;

    wmma::fragment<wmma::accumulator, 16, 16, 16, float> acc[2][2];
    #pragma unroll
    for (int i = 0; i < 2; i++)
        #pragma unroll
        for (int j = 0; j < 2; j++)
            wmma::fill_fragment(acc[i][j], 0.0f);

    for (int k0 = 0; k0 < 256; k0 += 64) {
        // load 64x64 X (512 slots of 8 halfs) + 128x64 W (1024 slots): 6/thread
        #pragma unroll
        for (int i = 0; i < 6; i++) {
            int s = tid + i * 256;
            int c8 = (s & 7) * 8;
            if (s < 512) {
                int row = s >> 3;
                *(float4*)&Xs[row * XPH + c8] =
                    *(const float4*)(Xbase + (size_t)row * 256 + k0 + c8);
            } else {
                int row = (s - 512) >> 3;
                *(float4*)&Ws[row * XPH + c8] =
                    *(const float4*)(Wbase + (size_t)row * 256 + k0 + c8);
            }
        }
        __syncthreads();

        #pragma unroll
        for (int kk = 0; kk < 64; kk += 16) {
            wmma::fragment<wmma::matrix_a, 16, 16, 16, __nv_bfloat16, wmma::row_major> af[2];
            wmma::fragment<wmma::matrix_b, 16, 16, 16, __nv_bfloat16, wmma::col_major> bf[2];
            #pragma unroll
            for (int i = 0; i < 2; i++)
                wmma::load_matrix_sync(af[i], &Xs[(wm * 32 + i * 16) * XPH + kk], XPH);
            #pragma unroll
            for (int j = 0; j < 2; j++)
                wmma::load_matrix_sync(bf[j], &Ws[(wn * 32 + j * 16) * XPH + kk], XPH);
            #pragma unroll
            for (int i = 0; i < 2; i++)
                #pragma unroll
                for (int j = 0; j < 2; j++)
                    wmma::mma_sync(acc[i][j], af[i], bf[j], acc[i][j]);
        }
        __syncthreads();
    }

    #pragma unroll
    for (int i = 0; i < 2; i++)
        #pragma unroll
        for (int j = 0; j < 2; j++) {
            float* dst = g_qk + (size_t)(m0 + wm * 32 + i * 16) * NQK
                              + n0 + wn * 32 + j * 16;
            wmma::store_matrix_sync(dst, acc[i][j], NQK, wmma::mem_row_major);
        }
}

// ---------------- K2: attn with tensor-core QK^T, panel postprocess -------
// Row max of softmax == 1/se. rinv <= thr => relu(softmax - thr) == 0 exactly.
#define QS 36    /* q/k smem row stride (mult of 4 for wmma ld) */
#define PS 160   /* rel panel row stride */
__global__ void __launch_bounds__(256, 4)
k_attn(const float* __restrict__ thr_p,
       const float* __restrict__ bq, const float* __restrict__ bk)
{
    extern __shared__ float smd[];
    float* sq  = smd;                    // 144*36
    float* sk  = smd + 144 * QS;         // 144*36
    float* pan = smd + 2 * 144 * QS;     // 16*160
    __shared__ float s_gap[8], s_max[8];

    int bh = blockIdx.x, b = bh >> 3, h = bh & 7;
    int tid = threadIdx.x, lane = tid & 31, w = tid >> 5;
    const float thr = *thr_p;

    // load q,k + bias, tf32-converted (rows 130..143 zero)
    for (int e = tid; e < 144 * Qd; e += 256) {
        int r = e >> 5, i = e & 31;
        float qv = 0.f, kv = 0.f;
        if (r < Rn) {
            size_t rowb = (size_t)(b * Rn + r) * NQK + h * 32;
            qv = g_qk[rowb + i]       + bq[h * 32 + i];
            kv = g_qk[rowb + 256 + i] + bk[h * 32 + i];
        }
        sq[r * QS + i] = wmma::__float_to_tf32(qv);
        sk[r * QS + i] = wmma::__float_to_tf32(kv);
    }
    __syncthreads();

    float gapAcc = 0.f, maxAcc = 0.f;
    const float sc = 0.17677669529663687f;   // 1/sqrt(32)
    const int cols1 = 4, cols2 = 5, cols3 = 6, cols4 = 7, cols5 = 8;
    bool val4 = (lane < 2);   // jb=4 valid columns: 128,129 only

    for (int p = 0; p < 9; p++) {
        int r0 = p * 16;

        // --- tensor-core rel panel: rows r0..r0+15 x cols 0..143 ---
        for (int t = w; t < 9; t += 8) {
            wmma::fragment<wmma::accumulator, 16, 16, 8, float> c;
            wmma::fill_fragment(c, 0.0f);
            #pragma unroll
            for (int kk = 0; kk < 32; kk += 8) {
                wmma::fragment<wmma::matrix_a, 16, 16, 8, wmma::precision::tf32, wmma::row_major> a;
                wmma::fragment<wmma::matrix_b, 16, 16, 8, wmma::precision::tf32, wmma::col_major> bb;
                wmma::load_matrix_sync(a,  sq + r0 * QS + kk, QS);
                wmma::load_matrix_sync(bb, sk + t * 16 * QS + kk, QS);
                wmma::mma_sync(c, a, bb, c);
            }
            wmma::store_matrix_sync(pan + t * 16, c, PS, wmma::mem_row_major);
        }
        __syncthreads();

        // --- postprocess: warp w handles rows r0+2w, r0+2w+1 ---
        int rA = r0 + 2 * w;
        float x[2][5], ex[2][5], lm[2], es[2];
        #pragma unroll
        for (int rr = 0; rr < 2; rr++) {
            const float* prow = pan + (2 * w + rr) * PS;
            #pragma unroll
            for (int jb = 0; jb < 5; jb++)
                x[rr][jb] = prow[jb * 32 + lane] * sc;
            lm[rr] = fmaxf(fmaxf(fmaxf(x[rr][0], x[rr][1]),
                                 fmaxf(x[rr][2], x[rr][3])),
                           val4 ? x[rr][4] : -1e30f);
        }
        #pragma unroll
        for (int o = 16; o; o >>= 1) {
            lm[0] = fmaxf(lm[0], __shfl_xor_sync(~0u, lm[0], o));
            lm[1] = fmaxf(lm[1], __shfl_xor_sync(~0u, lm[1], o));
        }
        #pragma unroll
        for (int rr = 0; rr < 2; rr++) {
            ex[rr][0] = __expf(x[rr][0] - lm[rr]);
            ex[rr][1] = __expf(x[rr][1] - lm[rr]);
            ex[rr][2] = __expf(x[rr][2] - lm[rr]);
            ex[rr][3] = __expf(x[rr][3] - lm[rr]);
            ex[rr][4] = val4 ? __expf(x[rr][4] - lm[rr]) : 0.f;
            es[rr] = ex[rr][0] + ex[rr][1] + ex[rr][2] + ex[rr][3] + ex[rr][4];
        }
        #pragma unroll
        for (int o = 16; o; o >>= 1) {
            es[0] += __shfl_xor_sync(~0u, es[0], o);
            es[1] += __shfl_xor_sync(~0u, es[1], o);
        }

        unsigned dm = 0;
        #pragma unroll
        for (int rr = 0; rr < 2; rr++)
            if (1.f <= thr * es[rr]) dm |= (1u << rr);   // rinv <= thr: row dead
        if (lane < 2) {
            int r = rA + lane;
            if (r < Rn && ((dm >> lane) & 1u)) g_spcnt[bh * Rn + r] = 0;
        }

        if (dm != 3u) {
            // ---- rare full path ----
            #pragma unroll
            for (int rr = 0; rr < 2; rr++) {
                int r = rA + rr;
                if (r >= Rn || ((dm >> rr) & 1u)) continue;
                float rinv = 1.f / es[rr];
                float v0 = fmaxf(fmaf(ex[rr][0], rinv, -thr), 0.f);
                float v1 = fmaxf(fmaf(ex[rr][1], rinv, -thr), 0.f);
                float v2 = fmaxf(fmaf(ex[rr][2], rinv, -thr), 0.f);
                float v3 = fmaxf(fmaf(ex[rr][3], rinv, -thr), 0.f);
                float v4 = val4 ? fmaxf(fmaf(ex[rr][4], rinv, -thr), 0.f) : 0.f;
                float gs = v0 + v1 + v2 + v3 + v4;
                #pragma unroll
                for (int o = 16; o; o >>= 1) gs += __shfl_xor_sync(~0u, gs, o);

                float c0 = __shfl_sync(~0u, v0, 0);
                float c1 = __shfl_sync(~0u, v0, cols1);
                float c2 = __shfl_sync(~0u, v0, cols2);
                float c3 = __shfl_sync(~0u, v0, cols3);
                float c4c = __shfl_sync(~0u, v0, cols4);
                float c5 = __shfl_sync(~0u, v0, cols5);

                unsigned p0 = 0, p1 = 0;
                #pragma unroll
                for (int jb = 0; jb < 5; jb++) {
                    int j = jb * 32 + lane;
                    float vv = (jb == 0) ? v0 : (jb == 1) ? v1 : (jb == 2) ? v2
                             : (jb == 3) ? v3 : v4;
                    p0 += (vv > c0)                                   ? 1u        : 0u;
                    p0 += ((vv > c1) || (vv == c1 && j < cols1))      ? (1u<<8)   : 0u;
                    p0 += ((vv > c2) || (vv == c2 && j < cols2))      ? (1u<<16)  : 0u;
                    p0 += ((vv > c3) || (vv == c3 && j < cols3))      ? (1u<<24)  : 0u;
                    p1 += ((vv > c4c)|| (vv == c4c&& j < cols4))      ? 1u        : 0u;
                    p1 += ((vv > c5) || (vv == c5 && j < cols5))      ? (1u<<8)   : 0u;
                }
                #pragma unroll
                for (int o = 16; o; o >>= 1) {
                    p0 += __shfl_xor_sync(~0u, p0, o);
                    p1 += __shfl_xor_sync(~0u, p1, o);
                }
                int myp = (lane < 4) ? (int)((p0 >> (8 * lane)) & 255u)
                                     : (int)((p1 >> (8 * (lane - 4))) & 255u);
                unsigned ball = __ballot_sync(~0u, (lane < 6) && (myp == r));
                int cnt = 6;
                if (!ball) { if (lane == 6) myp = r; cnt = 7; }

                int base = (bh * Rn + r) * 8;
                float rmax = 0.f;
                for (int i = 0; i < cnt; i++) {
                    int pp = __shfl_sync(~0u, myp, i);
                    int jbp = pp >> 5;
                    float av = (jbp == 0) ? v0 : (jbp == 1) ? v1 : (jbp == 2) ? v2
                             : (jbp == 3) ? v3 : v4;
                    float vv = __shfl_sync(~0u, av, pp & 31);
                    if (lane == 0) { g_spcol[base + i] = pp; g_spval[base + i] = vv; }
                    rmax = fmaxf(rmax, vv);
                }
                if (lane == 0) {
                    g_spcnt[bh * Rn + r] = cnt;
                    gapAcc += gs;
                    maxAcc = fmaxf(maxAcc, rmax);
                }
            }
        }
        __syncthreads();   // panel reuse barrier
    }

    if (lane == 0) { s_gap[w] = gapAcc; s_max[w] = maxAcc; }
    __syncthreads();
    if (tid == 0) {
        float gsum = 0.f, mx = 0.f;
        #pragma unroll
        for (int i = 0; i < 8; i++) { gsum += s_gap[i]; mx = fmaxf(mx, s_max[i]); }
        g_gap[bh] = gsum; g_maxA[bh] = mx;
    }
}

// ---------------- K3: SE gate + flags -------------------------------------
__global__ void k_gate(const float* __restrict__ seW1, const float* __restrict__ seb1,
                       const float* __restrict__ seW2, const float* __restrict__ seb2)
{
    int b = blockIdx.x;
    if (threadIdx.x) return;
    float g[8];
    #pragma unroll
    for (int h = 0; h < 8; h++) g[h] = g_gap[b * 8 + h] * (1.f / 16900.f);
    float hd[4];
    #pragma unroll
    for (int j = 0; j < 4; j++) {
        float a = seb1[j];
        #pragma unroll
        for (int h = 0; h < 8; h++) a = fmaf(seW1[j * 8 + h], g[h], a);
        hd[j] = fmaxf(a, 0.f);
    }
    #pragma unroll
    for (int i = 0; i < 8; i++) {
        float z = seb2[i];
        #pragma unroll
        for (int j = 0; j < 4; j++) z = fmaf(seW2[i * 4 + j], hd[j], z);
        float gt = floorf(1.f / (1.f + expf(-z)));   // .long() truncation
        g_gate[b * 8 + i] = gt;
        g_flag[b * 8 + i] = (gt != 0.f) && (g_maxA[b * 8 + i] > 0.f);
    }
}

// ---------------- Kprep: S[t] = sum_i relu(gcn_b[i][t]) -------------------
__global__ void k_prep(const float* __restrict__ gcn_b)
{
    __shared__ float red[256];
    int t = threadIdx.x;
    float s = 0.f;
    #pragma unroll
    for (int i = 0; i < 8; i++) s += fmaxf(gcn_b[i * 256 + t], 0.f);
    g_S[t] = s;
    red[t] = s; __syncthreads();
    for (int o = 128; o; o >>= 1) { if (t < o) red[t] += red[t + o]; __syncthreads(); }
    if (t == 0) g_S[256] = red[0] * (1.f / 256.f);
}

// ---------------- GCN: all 8 layers, one block per (b,h), flag-guarded ----
__global__ void k_gcnall(const float* __restrict__ x,
                         const float* __restrict__ gcnW, const float* __restrict__ gcnb)
{
    int bh = blockIdx.x;
    if (!g_flag[bh]) return;
    int b = bh >> 3;
    float gt = g_gate[bh];
    size_t base = (size_t)bh * Rn * Tn;
    const float* xb = x + (size_t)b * Rn * Tn;

    for (int e = threadIdx.x; e < Rn * Tn; e += 256) g_feats[base + e] = xb[e];
    __syncthreads();

    for (int L = 0; L < 8; L++) {
        const float* W    = gcnW + (size_t)L * Tn * Tn;
        const float* bias = gcnb + L * Tn;
        for (int e = threadIdx.x; e < Rn * Tn; e += 256) {
            int r = e >> 8, t = e & 255;
            int cnt = g_spcnt[bh * Rn + r];
            int sb  = (bh * Rn + r) * 8;
            float a = 0.f;
            for (int i = 0; i < cnt; i++)
                a = fmaf(g_spval[sb + i],
                         g_feats[base + (size_t)g_spcol[sb + i] * Tn + t], a);
            g_agg[base + e] = a * gt;
        }
        __syncthreads();
        for (int e = threadIdx.x; e < Rn * Tn; e += 256) {
            int r = e >> 8, t = e & 255;
            float acc = bias[t];
            const float* ag = g_agg + base + (size_t)r * Tn;
            const float* wr = W + (size_t)t * Tn;
            for (int u = 0; u < Tn; u++) acc = fmaf(ag[u], wr[u], acc);
            g_feats[base + e] = fmaxf(acc, 0.f) + g_feats[base + e];
        }
        __syncthreads();
    }
}

// ---------------- K5: fusion + pool + MLP head ----------------------------
__global__ void k_head(const float* __restrict__ x,
                       const float* __restrict__ fw, const float* __restrict__ fb,
                       const float* __restrict__ W1, const float* __restrict__ b1,
                       const float* __restrict__ W2, const float* __restrict__ b2,
                       const float* __restrict__ W3, const float* __restrict__ b3,
                       float* __restrict__ out)
{
    int b = blockIdx.x;
    int tid = threadIdx.x, lane = tid & 31, w = tid >> 5;
    __shared__ float pooled[132], sh1[64], sh2[16];
    __shared__ float swf[8];
    __shared__ int   sfl[8];
    if (tid < 8) { swf[tid] = fw[tid]; sfl[tid] = g_flag[b * 8 + tid]; }
    __syncthreads();
    float meanS = g_S[256], fbv = *fb;

    for (int r = w; r < Rn; r += 8) {
        const float* xr = x + ((size_t)b * Rn + r) * Tn;
        float sx = 0.f;
        for (int t = lane; t < Tn; t += 32) sx += xr[t];
        #pragma unroll
        for (int o = 16; o; o >>= 1) sx += __shfl_xor_sync(~0u, sx, o);
        float mx = sx * (1.f / 256.f);
        float acc = fbv;
        #pragma unroll
        for (int h = 0; h < 8; h++) {
            if (sfl[h]) {
                const float* fr = g_feats + ((size_t)(b * 8 + h) * Rn + r) * Tn;
                float sf = 0.f;
                for (int t = lane; t < Tn; t += 32) sf += fr[t];
                #pragma unroll
                for (int o = 16; o; o >>= 1) sf += __shfl_xor_sync(~0u, sf, o);
                acc = fmaf(swf[h], sf * (1.f / 256.f), acc);
            } else {
                acc = fmaf(swf[h], mx + meanS, acc);   // closed form: feats = x + S
            }
        }
        if (lane == 0) pooled[r] = acc;
    }
    __syncthreads();
    if (tid < 64) {
        float a = b1[tid];
        for (int r = 0; r < Rn; r++) a = fmaf(W1[tid * Rn + r], pooled[r], a);
        sh1[tid] = fmaxf(a, 0.f);
    }
    __syncthreads();
    if (tid < 16) {
        float a = b2[tid];
        #pragma unroll
        for (int j = 0; j < 64; j++) a = fmaf(W2[tid * 64 + j], sh1[j], a);
        sh2[tid] = fmaxf(a, 0.f);
    }
    __syncthreads();
    if (tid < 5) {
        float a = b3[tid];
        #pragma unroll
        for (int j = 0; j < 16; j++) a = fmaf(W3[tid * 16 + j], sh2[j], a);
        out[b * 5 + tid] = fmaxf(a, 0.f);
    }
}

// ---------------- launch ---------------------------------------------------
extern "C" void kernel_launch(void* const* d_in, const int* in_sizes, int n_in,
                              void* d_out, int out_size)
{
    const float* x    = (const float*)d_in[0];
    const float* Wq   = (const float*)d_in[1];
    const float* bq   = (const float*)d_in[2];
    const float* Wk   = (const float*)d_in[3];
    const float* bk   = (const float*)d_in[4];
    const float* thr  = (const float*)d_in[5];
    const float* seW1 = (const float*)d_in[6];
    const float* seb1 = (const float*)d_in[7];
    const float* seW2 = (const float*)d_in[8];
    const float* seb2 = (const float*)d_in[9];
    const float* gcnW = (const float*)d_in[10];
    const float* gcnb = (const float*)d_in[11];
    const float* fw   = (const float*)d_in[12];
    const float* fb   = (const float*)d_in[13];
    const float* W1   = (const float*)d_in[14];
    const float* b1   = (const float*)d_in[15];
    const float* W2   = (const float*)d_in[16];
    const float* b2   = (const float*)d_in[17];
    const float* W3   = (const float*)d_in[18];
    const float* b3   = (const float*)d_in[19];
    float* out = (float*)d_out;

    const int SMEM_ATTN = (2 * 144 * QS + 16 * PS) * sizeof(float);  // 51712 B
    cudaFuncSetAttribute(k_attn, cudaFuncAttributeMaxDynamicSharedMemorySize,
                         SMEM_ATTN);

    dim3 g1(Mn / 64, NQK / 128);
    k_prep<<<1, 256>>>(gcnb);                            // launch 1
    k_cvt<<<2144, 256>>>(x, Wq, Wk);                     // launch 2
    k_nop<<<1, 32>>>();                                  // launch 3
    k_qkproj<<<g1, 256>>>();                             // launch 4 <- ncu capture
    k_attn<<<BHn, 256, SMEM_ATTN>>>(thr, bq, bk);        // launch 5
    k_gate<<<Bn, 32>>>(seW1, seb1, seW2, seb2);          // launch 6
    k_gcnall<<<BHn, 256>>>(x, gcnW, gcnb);               // launch 7
    k_head<<<Bn, 256>>>(x, fw, fb, W1, b1, W2, b2, W3, b3, out);  // launch 8
}

// round 14
// speedup vs baseline: 4.4812x; 1.2321x over previous
#include <cuda_runtime.h>
#include <cstdint>
#include <cuda_bf16.h>
#include <mma.h>
#include <math.h>

using namespace nvcuda;

#define Bn   128
#define Hn   8
#define Rn   130
#define Tn   256
#define Qd   32
#define BHn  (Bn*Hn)     /* 1024 */
#define Mn   (Bn*Rn)     /* 16640 */
#define NQK  512

// ---------------- device scratch (no allocations allowed) ----------------
__device__ float g_qk[(size_t)Mn*NQK];            // q|k projections (NO bias), [M,512] fp32
__device__ __align__(16) __nv_bfloat16 g_xb[(size_t)Mn*256];   // x in bf16
__device__ __align__(16) __nv_bfloat16 g_wb[512*256];          // Wq||Wk in bf16
__device__ float g_feats[(size_t)BHn*Rn*Tn];      // GCN features (flagged heads only)
__device__ float g_agg[(size_t)BHn*Rn*Tn];        // sparse A @ feats scratch
__device__ float g_spval[BHn*Rn*8];               // sparse A values (pre-gate)
__device__ int   g_spcol[BHn*Rn*8];               // sparse A column indices
__device__ int   g_spcnt[BHn*Rn];                 // nnz per row
__device__ float g_gap[BHn];                      // sum of rel per (b,h)
__device__ float g_maxA[BHn];                     // max kept rel value per (b,h)
__device__ float g_gate[BHn];                     // SE gate (0 or 1)
__device__ int   g_flag[BHn];                     // gate!=0 && maxA>0
__device__ float g_S[Tn+1];                       // S[t]=sum_i relu(gcn_b[i][t]); S[256]=mean

__global__ void k_nop() {}

// ---------------- K0: fp32 -> bf16 conversion (x, Wq, Wk) -----------------
__global__ void k_cvt(const float* __restrict__ x,
                      const float* __restrict__ Wq, const float* __restrict__ Wk)
{
    const size_t NXQ = (size_t)Mn * 256 / 4;   // x quads
    const size_t NWQ = 65536 / 4;              // per-W quads
    size_t tot = NXQ + 2 * NWQ;
    for (size_t q = (size_t)blockIdx.x * blockDim.x + threadIdx.x;
         q < tot; q += (size_t)gridDim.x * blockDim.x) {
        const float* src;
        __nv_bfloat16* dst;
        size_t off;
        if (q < NXQ)            { src = x;  dst = g_xb;          off = q; }
        else if (q < NXQ + NWQ) { src = Wq; dst = g_wb;          off = q - NXQ; }
        else                    { src = Wk; dst = g_wb + 65536;  off = q - NXQ - NWQ; }
        float4 v = *(const float4*)(src + off * 4);
        __nv_bfloat162 lo = __floats2bfloat162_rn(v.x, v.y);
        __nv_bfloat162 hi = __floats2bfloat162_rn(v.z, v.w);
        *(__nv_bfloat162*)(dst + off * 4)     = lo;
        *(__nv_bfloat162*)(dst + off * 4 + 2) = hi;
    }
}

// ---------------- K1: qk = xb @ wb^T  (bf16 HMMA 16x16x16, BK=64) ---------
#define XPH 72   /* smem row stride in halfs (144B): conflict-free ldmatrix */
__global__ void __launch_bounds__(256, 3)
k_qkproj()
{
    __shared__ __align__(16) __nv_bfloat16 Xs[64 * XPH];
    __shared__ __align__(16) __nv_bfloat16 Ws[128 * XPH];

    int tid = threadIdx.x;
    int wid = tid >> 5;
    int m0 = blockIdx.x * 64, n0 = blockIdx.y * 128;
    int wm = wid >> 2;          // 0..1 : 32-row slice
    int wn = wid & 3;           // 0..3 : 32-col slice

    const __nv_bfloat16* Xbase = g_xb + (size_t)m0 * 256;
    const __nv_bfloat16* Wbase = g_wb + (size_t)n0 * 256;

    wmma::fragment<wmma::accumulator, 16, 16, 16, float> acc[2][2];
    #pragma unroll
    for (int i = 0; i < 2; i++)
        #pragma unroll
        for (int j = 0; j < 2; j++)
            wmma::fill_fragment(acc[i][j], 0.0f);

    for (int k0 = 0; k0 < 256; k0 += 64) {
        #pragma unroll
        for (int i = 0; i < 6; i++) {
            int s = tid + i * 256;
            int c8 = (s & 7) * 8;
            if (s < 512) {
                int row = s >> 3;
                *(float4*)&Xs[row * XPH + c8] =
                    *(const float4*)(Xbase + (size_t)row * 256 + k0 + c8);
            } else {
                int row = (s - 512) >> 3;
                *(float4*)&Ws[row * XPH + c8] =
                    *(const float4*)(Wbase + (size_t)row * 256 + k0 + c8);
            }
        }
        __syncthreads();

        #pragma unroll
        for (int kk = 0; kk < 64; kk += 16) {
            wmma::fragment<wmma::matrix_a, 16, 16, 16, __nv_bfloat16, wmma::row_major> af[2];
            wmma::fragment<wmma::matrix_b, 16, 16, 16, __nv_bfloat16, wmma::col_major> bf[2];
            #pragma unroll
            for (int i = 0; i < 2; i++)
                wmma::load_matrix_sync(af[i], &Xs[(wm * 32 + i * 16) * XPH + kk], XPH);
            #pragma unroll
            for (int j = 0; j < 2; j++)
                wmma::load_matrix_sync(bf[j], &Ws[(wn * 32 + j * 16) * XPH + kk], XPH);
            #pragma unroll
            for (int i = 0; i < 2; i++)
                #pragma unroll
                for (int j = 0; j < 2; j++)
                    wmma::mma_sync(acc[i][j], af[i], bf[j], acc[i][j]);
        }
        __syncthreads();
    }

    #pragma unroll
    for (int i = 0; i < 2; i++)
        #pragma unroll
        for (int j = 0; j < 2; j++) {
            float* dst = g_qk + (size_t)(m0 + wm * 32 + i * 16) * NQK
                              + n0 + wn * 32 + j * 16;
            wmma::store_matrix_sync(dst, acc[i][j], NQK, wmma::mem_row_major);
        }
}

// ---------------- K2: attn, bf16 tensor-core QK^T, panel postprocess ------
// Row max of softmax == 1/se. rinv <= thr => relu(softmax - thr) == 0 exactly.
#define QSH 40   /* q/k smem row stride in halfs (80B): conflict-free ldmatrix */
#define PS 160   /* rel panel row stride (fp32) */
__global__ void __launch_bounds__(256, 4)
k_attn(const float* __restrict__ thr_p,
       const float* __restrict__ bq, const float* __restrict__ bk)
{
    extern __shared__ char smd[];
    __nv_bfloat16* sq = (__nv_bfloat16*)smd;                     // 144*40 halfs
    __nv_bfloat16* sk = (__nv_bfloat16*)(smd + 144 * QSH * 2);   // 144*40 halfs
    float*        pan = (float*)(smd + 2 * 144 * QSH * 2);       // 16*160 fp32
    __shared__ float s_gap[8], s_max[8];

    int bh = blockIdx.x, b = bh >> 3, h = bh & 7;
    int tid = threadIdx.x, lane = tid & 31, w = tid >> 5;
    const float thr = *thr_p;

    // load q,k + bias, bf16-converted (rows 130..143 zero)
    for (int e = tid; e < 144 * Qd; e += 256) {
        int r = e >> 5, i = e & 31;
        float qv = 0.f, kv = 0.f;
        if (r < Rn) {
            size_t rowb = (size_t)(b * Rn + r) * NQK + h * 32;
            qv = g_qk[rowb + i]       + bq[h * 32 + i];
            kv = g_qk[rowb + 256 + i] + bk[h * 32 + i];
        }
        sq[r * QSH + i] = __float2bfloat16(qv);
        sk[r * QSH + i] = __float2bfloat16(kv);
    }
    __syncthreads();

    float gapAcc = 0.f, maxAcc = 0.f;
    const float sc = 0.17677669529663687f;   // 1/sqrt(32)
    const int cols1 = 4, cols2 = 5, cols3 = 6, cols4 = 7, cols5 = 8;
    bool val4 = (lane < 2);   // jb=4 valid columns: 128,129 only

    for (int p = 0; p < 9; p++) {
        int r0 = p * 16;

        // --- bf16 tensor-core rel panel: rows r0..r0+15 x cols 0..143 ---
        for (int t = w; t < 9; t += 8) {
            wmma::fragment<wmma::accumulator, 16, 16, 16, float> c;
            wmma::fill_fragment(c, 0.0f);
            #pragma unroll
            for (int kk = 0; kk < 32; kk += 16) {
                wmma::fragment<wmma::matrix_a, 16, 16, 16, __nv_bfloat16, wmma::row_major> a;
                wmma::fragment<wmma::matrix_b, 16, 16, 16, __nv_bfloat16, wmma::col_major> bb;
                wmma::load_matrix_sync(a,  sq + r0 * QSH + kk, QSH);
                wmma::load_matrix_sync(bb, sk + t * 16 * QSH + kk, QSH);
                wmma::mma_sync(c, a, bb, c);
            }
            wmma::store_matrix_sync(pan + t * 16, c, PS, wmma::mem_row_major);
        }
        __syncthreads();

        // --- postprocess: warp w handles rows r0+2w, r0+2w+1 ---
        int rA = r0 + 2 * w;
        float x[2][5], ex[2][5], lm[2], es[2];
        #pragma unroll
        for (int rr = 0; rr < 2; rr++) {
            const float* prow = pan + (2 * w + rr) * PS;
            #pragma unroll
            for (int jb = 0; jb < 5; jb++)
                x[rr][jb] = prow[jb * 32 + lane] * sc;
            lm[rr] = fmaxf(fmaxf(fmaxf(x[rr][0], x[rr][1]),
                                 fmaxf(x[rr][2], x[rr][3])),
                           val4 ? x[rr][4] : -1e30f);
        }
        #pragma unroll
        for (int o = 16; o; o >>= 1) {
            lm[0] = fmaxf(lm[0], __shfl_xor_sync(~0u, lm[0], o));
            lm[1] = fmaxf(lm[1], __shfl_xor_sync(~0u, lm[1], o));
        }
        #pragma unroll
        for (int rr = 0; rr < 2; rr++) {
            ex[rr][0] = __expf(x[rr][0] - lm[rr]);
            ex[rr][1] = __expf(x[rr][1] - lm[rr]);
            ex[rr][2] = __expf(x[rr][2] - lm[rr]);
            ex[rr][3] = __expf(x[rr][3] - lm[rr]);
            ex[rr][4] = val4 ? __expf(x[rr][4] - lm[rr]) : 0.f;
            es[rr] = ex[rr][0] + ex[rr][1] + ex[rr][2] + ex[rr][3] + ex[rr][4];
        }
        #pragma unroll
        for (int o = 16; o; o >>= 1) {
            es[0] += __shfl_xor_sync(~0u, es[0], o);
            es[1] += __shfl_xor_sync(~0u, es[1], o);
        }

        unsigned dm = 0;
        #pragma unroll
        for (int rr = 0; rr < 2; rr++)
            if (1.f <= thr * es[rr]) dm |= (1u << rr);   // rinv <= thr: row dead
        if (lane < 2) {
            int r = rA + lane;
            if (r < Rn && ((dm >> lane) & 1u)) g_spcnt[bh * Rn + r] = 0;
        }

        if (dm != 3u) {
            // ---- rare full path ----
            #pragma unroll
            for (int rr = 0; rr < 2; rr++) {
                int r = rA + rr;
                if (r >= Rn || ((dm >> rr) & 1u)) continue;
                float rinv = 1.f / es[rr];
                float v0 = fmaxf(fmaf(ex[rr][0], rinv, -thr), 0.f);
                float v1 = fmaxf(fmaf(ex[rr][1], rinv, -thr), 0.f);
                float v2 = fmaxf(fmaf(ex[rr][2], rinv, -thr), 0.f);
                float v3 = fmaxf(fmaf(ex[rr][3], rinv, -thr), 0.f);
                float v4 = val4 ? fmaxf(fmaf(ex[rr][4], rinv, -thr), 0.f) : 0.f;
                float gs = v0 + v1 + v2 + v3 + v4;
                #pragma unroll
                for (int o = 16; o; o >>= 1) gs += __shfl_xor_sync(~0u, gs, o);

                float c0 = __shfl_sync(~0u, v0, 0);
                float c1 = __shfl_sync(~0u, v0, cols1);
                float c2 = __shfl_sync(~0u, v0, cols2);
                float c3 = __shfl_sync(~0u, v0, cols3);
                float c4c = __shfl_sync(~0u, v0, cols4);
                float c5 = __shfl_sync(~0u, v0, cols5);

                unsigned p0 = 0, p1 = 0;
                #pragma unroll
                for (int jb = 0; jb < 5; jb++) {
                    int j = jb * 32 + lane;
                    float vv = (jb == 0) ? v0 : (jb == 1) ? v1 : (jb == 2) ? v2
                             : (jb == 3) ? v3 : v4;
                    p0 += (vv > c0)                                   ? 1u        : 0u;
                    p0 += ((vv > c1) || (vv == c1 && j < cols1))      ? (1u<<8)   : 0u;
                    p0 += ((vv > c2) || (vv == c2 && j < cols2))      ? (1u<<16)  : 0u;
                    p0 += ((vv > c3) || (vv == c3 && j < cols3))      ? (1u<<24)  : 0u;
                    p1 += ((vv > c4c)|| (vv == c4c&& j < cols4))      ? 1u        : 0u;
                    p1 += ((vv > c5) || (vv == c5 && j < cols5))      ? (1u<<8)   : 0u;
                }
                #pragma unroll
                for (int o = 16; o; o >>= 1) {
                    p0 += __shfl_xor_sync(~0u, p0, o);
                    p1 += __shfl_xor_sync(~0u, p1, o);
                }
                int myp = (lane < 4) ? (int)((p0 >> (8 * lane)) & 255u)
                                     : (int)((p1 >> (8 * (lane - 4))) & 255u);
                unsigned ball = __ballot_sync(~0u, (lane < 6) && (myp == r));
                int cnt = 6;
                if (!ball) { if (lane == 6) myp = r; cnt = 7; }

                int base = (bh * Rn + r) * 8;
                float rmax = 0.f;
                for (int i = 0; i < cnt; i++) {
                    int pp = __shfl_sync(~0u, myp, i);
                    int jbp = pp >> 5;
                    float av = (jbp == 0) ? v0 : (jbp == 1) ? v1 : (jbp == 2) ? v2
                             : (jbp == 3) ? v3 : v4;
                    float vv = __shfl_sync(~0u, av, pp & 31);
                    if (lane == 0) { g_spcol[base + i] = pp; g_spval[base + i] = vv; }
                    rmax = fmaxf(rmax, vv);
                }
                if (lane == 0) {
                    g_spcnt[bh * Rn + r] = cnt;
                    gapAcc += gs;
                    maxAcc = fmaxf(maxAcc, rmax);
                }
            }
        }
        __syncthreads();   // panel reuse barrier
    }

    if (lane == 0) { s_gap[w] = gapAcc; s_max[w] = maxAcc; }
    __syncthreads();
    if (tid == 0) {
        float gsum = 0.f, mx = 0.f;
        #pragma unroll
        for (int i = 0; i < 8; i++) { gsum += s_gap[i]; mx = fmaxf(mx, s_max[i]); }
        g_gap[bh] = gsum; g_maxA[bh] = mx;
    }
}

// ---------------- K3: SE gate + flags -------------------------------------
__global__ void k_gate(const float* __restrict__ seW1, const float* __restrict__ seb1,
                       const float* __restrict__ seW2, const float* __restrict__ seb2)
{
    int b = blockIdx.x;
    if (threadIdx.x) return;
    float g[8];
    #pragma unroll
    for (int h = 0; h < 8; h++) g[h] = g_gap[b * 8 + h] * (1.f / 16900.f);
    float hd[4];
    #pragma unroll
    for (int j = 0; j < 4; j++) {
        float a = seb1[j];
        #pragma unroll
        for (int h = 0; h < 8; h++) a = fmaf(seW1[j * 8 + h], g[h], a);
        hd[j] = fmaxf(a, 0.f);
    }
    #pragma unroll
    for (int i = 0; i < 8; i++) {
        float z = seb2[i];
        #pragma unroll
        for (int j = 0; j < 4; j++) z = fmaf(seW2[i * 4 + j], hd[j], z);
        float gt = floorf(1.f / (1.f + expf(-z)));   // .long() truncation
        g_gate[b * 8 + i] = gt;
        g_flag[b * 8 + i] = (gt != 0.f) && (g_maxA[b * 8 + i] > 0.f);
    }
}

// ---------------- Kprep: S[t] = sum_i relu(gcn_b[i][t]) -------------------
__global__ void k_prep(const float* __restrict__ gcn_b)
{
    __shared__ float red[256];
    int t = threadIdx.x;
    float s = 0.f;
    #pragma unroll
    for (int i = 0; i < 8; i++) s += fmaxf(gcn_b[i * 256 + t], 0.f);
    g_S[t] = s;
    red[t] = s; __syncthreads();
    for (int o = 128; o; o >>= 1) { if (t < o) red[t] += red[t + o]; __syncthreads(); }
    if (t == 0) g_S[256] = red[0] * (1.f / 256.f);
}

// ---------------- GCN: all 8 layers, one block per (b,h), flag-guarded ----
__global__ void k_gcnall(const float* __restrict__ x,
                         const float* __restrict__ gcnW, const float* __restrict__ gcnb)
{
    int bh = blockIdx.x;
    if (!g_flag[bh]) return;
    int b = bh >> 3;
    float gt = g_gate[bh];
    size_t base = (size_t)bh * Rn * Tn;
    const float* xb = x + (size_t)b * Rn * Tn;

    for (int e = threadIdx.x; e < Rn * Tn; e += 256) g_feats[base + e] = xb[e];
    __syncthreads();

    for (int L = 0; L < 8; L++) {
        const float* W    = gcnW + (size_t)L * Tn * Tn;
        const float* bias = gcnb + L * Tn;
        for (int e = threadIdx.x; e < Rn * Tn; e += 256) {
            int r = e >> 8, t = e & 255;
            int cnt = g_spcnt[bh * Rn + r];
            int sb  = (bh * Rn + r) * 8;
            float a = 0.f;
            for (int i = 0; i < cnt; i++)
                a = fmaf(g_spval[sb + i],
                         g_feats[base + (size_t)g_spcol[sb + i] * Tn + t], a);
            g_agg[base + e] = a * gt;
        }
        __syncthreads();
        for (int e = threadIdx.x; e < Rn * Tn; e += 256) {
            int r = e >> 8, t = e & 255;
            float acc = bias[t];
            const float* ag = g_agg + base + (size_t)r * Tn;
            const float* wr = W + (size_t)t * Tn;
            for (int u = 0; u < Tn; u++) acc = fmaf(ag[u], wr[u], acc);
            g_feats[base + e] = fmaxf(acc, 0.f) + g_feats[base + e];
        }
        __syncthreads();
    }
}

// ---------------- K5: fusion + pool + MLP head ----------------------------
__global__ void k_head(const float* __restrict__ x,
                       const float* __restrict__ fw, const float* __restrict__ fb,
                       const float* __restrict__ W1, const float* __restrict__ b1,
                       const float* __restrict__ W2, const float* __restrict__ b2,
                       const float* __restrict__ W3, const float* __restrict__ b3,
                       float* __restrict__ out)
{
    int b = blockIdx.x;
    int tid = threadIdx.x, lane = tid & 31, w = tid >> 5;
    __shared__ float pooled[132], sh1[64], sh2[16];
    __shared__ float swf[8];
    __shared__ int   sfl[8];
    if (tid < 8) { swf[tid] = fw[tid]; sfl[tid] = g_flag[b * 8 + tid]; }
    __syncthreads();
    float meanS = g_S[256], fbv = *fb;

    for (int r = w; r < Rn; r += 8) {
        const float* xr = x + ((size_t)b * Rn + r) * Tn;
        float sx = 0.f;
        for (int t = lane; t < Tn; t += 32) sx += xr[t];
        #pragma unroll
        for (int o = 16; o; o >>= 1) sx += __shfl_xor_sync(~0u, sx, o);
        float mx = sx * (1.f / 256.f);
        float acc = fbv;
        #pragma unroll
        for (int h = 0; h < 8; h++) {
            if (sfl[h]) {
                const float* fr = g_feats + ((size_t)(b * 8 + h) * Rn + r) * Tn;
                float sf = 0.f;
                for (int t = lane; t < Tn; t += 32) sf += fr[t];
                #pragma unroll
                for (int o = 16; o; o >>= 1) sf += __shfl_xor_sync(~0u, sf, o);
                acc = fmaf(swf[h], sf * (1.f / 256.f), acc);
            } else {
                acc = fmaf(swf[h], mx + meanS, acc);   // closed form: feats = x + S
            }
        }
        if (lane == 0) pooled[r] = acc;
    }
    __syncthreads();
    if (tid < 64) {
        float a = b1[tid];
        for (int r = 0; r < Rn; r++) a = fmaf(W1[tid * Rn + r], pooled[r], a);
        sh1[tid] = fmaxf(a, 0.f);
    }
    __syncthreads();
    if (tid < 16) {
        float a = b2[tid];
        #pragma unroll
        for (int j = 0; j < 64; j++) a = fmaf(W2[tid * 64 + j], sh1[j], a);
        sh2[tid] = fmaxf(a, 0.f);
    }
    __syncthreads();
    if (tid < 5) {
        float a = b3[tid];
        #pragma unroll
        for (int j = 0; j < 16; j++) a = fmaf(W3[tid * 16 + j], sh2[j], a);
        out[b * 5 + tid] = fmaxf(a, 0.f);
    }
}

// ---------------- launch ---------------------------------------------------
extern "C" void kernel_launch(void* const* d_in, const int* in_sizes, int n_in,
                              void* d_out, int out_size)
{
    const float* x    = (const float*)d_in[0];
    const float* Wq   = (const float*)d_in[1];
    const float* bq   = (const float*)d_in[2];
    const float* Wk   = (const float*)d_in[3];
    const float* bk   = (const float*)d_in[4];
    const float* thr  = (const float*)d_in[5];
    const float* seW1 = (const float*)d_in[6];
    const float* seb1 = (const float*)d_in[7];
    const float* seW2 = (const float*)d_in[8];
    const float* seb2 = (const float*)d_in[9];
    const float* gcnW = (const float*)d_in[10];
    const float* gcnb = (const float*)d_in[11];
    const float* fw   = (const float*)d_in[12];
    const float* fb   = (const float*)d_in[13];
    const float* W1   = (const float*)d_in[14];
    const float* b1   = (const float*)d_in[15];
    const float* W2   = (const float*)d_in[16];
    const float* b2   = (const float*)d_in[17];
    const float* W3   = (const float*)d_in[18];
    const float* b3   = (const float*)d_in[19];
    float* out = (float*)d_out;

    const int SMEM_ATTN = 2 * 144 * QSH * 2 + 16 * PS * 4;   // 33280 B
    cudaFuncSetAttribute(k_attn, cudaFuncAttributeMaxDynamicSharedMemorySize,
                         SMEM_ATTN);

    dim3 g1(Mn / 64, NQK / 128);
    k_prep<<<1, 256>>>(gcnb);                            // launch 1
    k_cvt<<<2144, 256>>>(x, Wq, Wk);                     // launch 2
    k_qkproj<<<g1, 256>>>();                             // launch 3
    k_attn<<<BHn, 256, SMEM_ATTN>>>(thr, bq, bk);        // launch 4 <- ncu capture
    k_gate<<<Bn, 32>>>(seW1, seb1, seW2, seb2);          // launch 5
    k_gcnall<<<BHn, 256>>>(x, gcnW, gcnb);               // launch 6
    k_head<<<Bn, 256>>>(x, fw, fb, W1, b1, W2, b2, W3, b3, out);  // launch 7
}

// round 15
// speedup vs baseline: 4.7833x; 1.0674x over previous
#include <cuda_runtime.h>
#include <cstdint>
#include <cuda_bf16.h>
#include <mma.h>
#include <math.h>

using namespace nvcuda;

#define Bn   128
#define Hn   8
#define Rn   130
#define Tn   256
#define Qd   32
#define BHn  (Bn*Hn)     /* 1024 */
#define Mn   (Bn*Rn)     /* 16640 */
#define NQK  512

// ---------------- device scratch (no allocations allowed) ----------------
__device__ __align__(16) __nv_bfloat16 g_qkb[(size_t)Mn*NQK];  // q|k + bias, bf16
__device__ __align__(16) __nv_bfloat16 g_xb[(size_t)Mn*256];   // x in bf16
__device__ __align__(16) __nv_bfloat16 g_wb[512*256];          // Wq||Wk in bf16
__device__ float g_feats[(size_t)BHn*Rn*Tn];      // GCN features (flagged heads only)
__device__ float g_agg[(size_t)BHn*Rn*Tn];        // sparse A @ feats scratch
__device__ float g_spval[BHn*Rn*8];               // sparse A values (pre-gate)
__device__ int   g_spcol[BHn*Rn*8];               // sparse A column indices
__device__ int   g_spcnt[BHn*Rn];                 // nnz per row
__device__ float g_gap[BHn];                      // sum of rel per (b,h)
__device__ float g_maxA[BHn];                     // max kept rel value per (b,h)
__device__ float g_gate[BHn];                     // SE gate (0 or 1)
__device__ int   g_flag[BHn];                     // gate!=0 && maxA>0
__device__ float g_S[Tn+1];                       // S[t]=sum_i relu(gcn_b[i][t]); S[256]=mean

__global__ void k_nop() {}

// ---------------- K0: fp32 -> bf16 conversion (x, Wq, Wk) -----------------
__global__ void k_cvt(const float* __restrict__ x,
                      const float* __restrict__ Wq, const float* __restrict__ Wk)
{
    const size_t NXQ = (size_t)Mn * 256 / 4;   // x quads
    const size_t NWQ = 65536 / 4;              // per-W quads
    size_t tot = NXQ + 2 * NWQ;
    for (size_t q = (size_t)blockIdx.x * blockDim.x + threadIdx.x;
         q < tot; q += (size_t)gridDim.x * blockDim.x) {
        const float* src;
        __nv_bfloat16* dst;
        size_t off;
        if (q < NXQ)            { src = x;  dst = g_xb;          off = q; }
        else if (q < NXQ + NWQ) { src = Wq; dst = g_wb;          off = q - NXQ; }
        else                    { src = Wk; dst = g_wb + 65536;  off = q - NXQ - NWQ; }
        float4 v = *(const float4*)(src + off * 4);
        __nv_bfloat162 lo = __floats2bfloat162_rn(v.x, v.y);
        __nv_bfloat162 hi = __floats2bfloat162_rn(v.z, v.w);
        *(__nv_bfloat162*)(dst + off * 4)     = lo;
        *(__nv_bfloat162*)(dst + off * 4 + 2) = hi;
    }
}

// ---------------- K1: qkb = bf16(xb @ wb^T + bias)  (bf16 HMMA, BK=64) ----
#define XPH 72   /* smem row stride in halfs (144B): conflict-free ldmatrix */
__global__ void __launch_bounds__(256, 3)
k_qkproj(const float* __restrict__ bq, const float* __restrict__ bk)
{
    __shared__ __align__(16) __nv_bfloat16 Xs[64 * XPH];
    __shared__ __align__(16) __nv_bfloat16 Ws[128 * XPH];
    __shared__ __align__(16) float Sb[8][16 * 20];

    int tid = threadIdx.x;
    int wid = tid >> 5;
    int lane = tid & 31;
    int m0 = blockIdx.x * 64, n0 = blockIdx.y * 128;
    int wm = wid >> 2;          // 0..1 : 32-row slice
    int wn = wid & 3;           // 0..3 : 32-col slice

    const __nv_bfloat16* Xbase = g_xb + (size_t)m0 * 256;
    const __nv_bfloat16* Wbase = g_wb + (size_t)n0 * 256;
    const float* Bbase = (n0 < 256) ? (bq + n0) : (bk + n0 - 256);

    wmma::fragment<wmma::accumulator, 16, 16, 16, float> acc[2][2];
    #pragma unroll
    for (int i = 0; i < 2; i++)
        #pragma unroll
        for (int j = 0; j < 2; j++)
            wmma::fill_fragment(acc[i][j], 0.0f);

    for (int k0 = 0; k0 < 256; k0 += 64) {
        #pragma unroll
        for (int i = 0; i < 6; i++) {
            int s = tid + i * 256;
            int c8 = (s & 7) * 8;
            if (s < 512) {
                int row = s >> 3;
                *(float4*)&Xs[row * XPH + c8] =
                    *(const float4*)(Xbase + (size_t)row * 256 + k0 + c8);
            } else {
                int row = (s - 512) >> 3;
                *(float4*)&Ws[row * XPH + c8] =
                    *(const float4*)(Wbase + (size_t)row * 256 + k0 + c8);
            }
        }
        __syncthreads();

        #pragma unroll
        for (int kk = 0; kk < 64; kk += 16) {
            wmma::fragment<wmma::matrix_a, 16, 16, 16, __nv_bfloat16, wmma::row_major> af[2];
            wmma::fragment<wmma::matrix_b, 16, 16, 16, __nv_bfloat16, wmma::col_major> bf[2];
            #pragma unroll
            for (int i = 0; i < 2; i++)
                wmma::load_matrix_sync(af[i], &Xs[(wm * 32 + i * 16) * XPH + kk], XPH);
            #pragma unroll
            for (int j = 0; j < 2; j++)
                wmma::load_matrix_sync(bf[j], &Ws[(wn * 32 + j * 16) * XPH + kk], XPH);
            #pragma unroll
            for (int i = 0; i < 2; i++)
                #pragma unroll
                for (int j = 0; j < 2; j++)
                    wmma::mma_sync(acc[i][j], af[i], bf[j], acc[i][j]);
        }
        __syncthreads();
    }

    // epilogue: +bias, convert bf16, vectorized store
    int r  = lane >> 1;
    int cs = (lane & 1) * 8;
    float b8[2][8];
    #pragma unroll
    for (int j = 0; j < 2; j++) {
        float4 u = *(const float4*)(Bbase + wn * 32 + j * 16 + cs);
        float4 v = *(const float4*)(Bbase + wn * 32 + j * 16 + cs + 4);
        b8[j][0] = u.x; b8[j][1] = u.y; b8[j][2] = u.z; b8[j][3] = u.w;
        b8[j][4] = v.x; b8[j][5] = v.y; b8[j][6] = v.z; b8[j][7] = v.w;
    }
    #pragma unroll
    for (int i = 0; i < 2; i++)
        #pragma unroll
        for (int j = 0; j < 2; j++) {
            wmma::store_matrix_sync(&Sb[wid][0], acc[i][j], 20, wmma::mem_row_major);
            __syncwarp();
            const float* src = &Sb[wid][r * 20 + cs];
            __align__(16) __nv_bfloat16 o[8];
            #pragma unroll
            for (int t = 0; t < 8; t++)
                o[t] = __float2bfloat16(src[t] + b8[j][t]);
            __nv_bfloat16* dst = g_qkb + (size_t)(m0 + wm * 32 + i * 16 + r) * NQK
                                       + n0 + wn * 32 + j * 16 + cs;
            *(uint4*)dst = *(const uint4*)o;
            __syncwarp();
        }
}

// ---------------- K2: attn, bf16 QK^T, double-buffered panels -------------
// Row max of softmax == 1/se. rinv <= thr => relu(softmax - thr) == 0 exactly.
#define QSH 40   /* q/k smem row stride in halfs (80B): conflict-free ldmatrix */
#define PS 160   /* rel panel row stride (fp32) */
__global__ void __launch_bounds__(256, 4)
k_attn(const float* __restrict__ thr_p)
{
    extern __shared__ char smd[];
    __nv_bfloat16* sq = (__nv_bfloat16*)smd;                     // 144*40 halfs
    __nv_bfloat16* sk = (__nv_bfloat16*)(smd + 144 * QSH * 2);   // 144*40 halfs
    float*        pan = (float*)(smd + 2 * 144 * QSH * 2);       // 2 x 16*160 fp32
    __shared__ float s_gap[8], s_max[8];

    int bh = blockIdx.x, b = bh >> 3, h = bh & 7;
    int tid = threadIdx.x, lane = tid & 31, w = tid >> 5;
    const float thr = *thr_p;

    // load q,k (bias pre-folded, bf16) ; rows 130..143 zero
    // unit = 8 halfs; q units 0..575, k units 576..1151
    for (int e = tid; e < 1152; e += 256) {
        int u = (e < 576) ? e : e - 576;
        int r = u >> 2, seg = (u & 3) * 8;
        uint4 v = make_uint4(0u, 0u, 0u, 0u);
        if (r < Rn) {
            size_t src = (size_t)(b * Rn + r) * NQK + h * 32 + seg
                       + ((e < 576) ? 0 : 256);
            v = *(const uint4*)(g_qkb + src);
        }
        __nv_bfloat16* dst = (e < 576) ? sq : sk;
        *(uint4*)(dst + r * QSH + seg) = v;
    }
    __syncthreads();

    float gapAcc = 0.f, maxAcc = 0.f;
    const float sc = 0.17677669529663687f;   // 1/sqrt(32)
    const int cols1 = 4, cols2 = 5, cols3 = 6, cols4 = 7, cols5 = 8;
    bool val4 = (lane < 2);   // jb=4 valid columns: 128,129 only

    // prologue: panel 0 MMA
    for (int t = w; t < 9; t += 8) {
        wmma::fragment<wmma::accumulator, 16, 16, 16, float> c;
        wmma::fill_fragment(c, 0.0f);
        #pragma unroll
        for (int kk = 0; kk < 32; kk += 16) {
            wmma::fragment<wmma::matrix_a, 16, 16, 16, __nv_bfloat16, wmma::row_major> a;
            wmma::fragment<wmma::matrix_b, 16, 16, 16, __nv_bfloat16, wmma::col_major> bb;
            wmma::load_matrix_sync(a,  sq + 0 * QSH + kk, QSH);
            wmma::load_matrix_sync(bb, sk + t * 16 * QSH + kk, QSH);
            wmma::mma_sync(c, a, bb, c);
        }
        wmma::store_matrix_sync(pan + t * 16, c, PS, wmma::mem_row_major);
    }
    __syncthreads();

    for (int p = 0; p < 9; p++) {
        // MMA for panel p+1 into the other buffer (overlaps postprocess of p)
        if (p < 8) {
            int r1 = (p + 1) * 16;
            float* pn = pan + ((p + 1) & 1) * 16 * PS;
            for (int t = w; t < 9; t += 8) {
                wmma::fragment<wmma::accumulator, 16, 16, 16, float> c;
                wmma::fill_fragment(c, 0.0f);
                #pragma unroll
                for (int kk = 0; kk < 32; kk += 16) {
                    wmma::fragment<wmma::matrix_a, 16, 16, 16, __nv_bfloat16, wmma::row_major> a;
                    wmma::fragment<wmma::matrix_b, 16, 16, 16, __nv_bfloat16, wmma::col_major> bb;
                    wmma::load_matrix_sync(a,  sq + r1 * QSH + kk, QSH);
                    wmma::load_matrix_sync(bb, sk + t * 16 * QSH + kk, QSH);
                    wmma::mma_sync(c, a, bb, c);
                }
                wmma::store_matrix_sync(pn + t * 16, c, PS, wmma::mem_row_major);
            }
        }

        // postprocess panel p: warp w handles rows r0+2w, r0+2w+1
        int r0 = p * 16;
        const float* pb = pan + (p & 1) * 16 * PS;
        int rA = r0 + 2 * w;
        float x[2][5], ex[2][5], lm[2], es[2];
        #pragma unroll
        for (int rr = 0; rr < 2; rr++) {
            const float* prow = pb + (2 * w + rr) * PS;
            #pragma unroll
            for (int jb = 0; jb < 5; jb++)
                x[rr][jb] = prow[jb * 32 + lane] * sc;
            lm[rr] = fmaxf(fmaxf(fmaxf(x[rr][0], x[rr][1]),
                                 fmaxf(x[rr][2], x[rr][3])),
                           val4 ? x[rr][4] : -1e30f);
        }
        #pragma unroll
        for (int o = 16; o; o >>= 1) {
            lm[0] = fmaxf(lm[0], __shfl_xor_sync(~0u, lm[0], o));
            lm[1] = fmaxf(lm[1], __shfl_xor_sync(~0u, lm[1], o));
        }
        #pragma unroll
        for (int rr = 0; rr < 2; rr++) {
            ex[rr][0] = __expf(x[rr][0] - lm[rr]);
            ex[rr][1] = __expf(x[rr][1] - lm[rr]);
            ex[rr][2] = __expf(x[rr][2] - lm[rr]);
            ex[rr][3] = __expf(x[rr][3] - lm[rr]);
            ex[rr][4] = val4 ? __expf(x[rr][4] - lm[rr]) : 0.f;
            es[rr] = ex[rr][0] + ex[rr][1] + ex[rr][2] + ex[rr][3] + ex[rr][4];
        }
        #pragma unroll
        for (int o = 16; o; o >>= 1) {
            es[0] += __shfl_xor_sync(~0u, es[0], o);
            es[1] += __shfl_xor_sync(~0u, es[1], o);
        }

        unsigned dm = 0;
        #pragma unroll
        for (int rr = 0; rr < 2; rr++)
            if (1.f <= thr * es[rr]) dm |= (1u << rr);   // rinv <= thr: row dead
        if (lane < 2) {
            int r = rA + lane;
            if (r < Rn && ((dm >> lane) & 1u)) g_spcnt[bh * Rn + r] = 0;
        }

        if (dm != 3u) {
            // ---- rare full path ----
            #pragma unroll
            for (int rr = 0; rr < 2; rr++) {
                int r = rA + rr;
                if (r >= Rn || ((dm >> rr) & 1u)) continue;
                float rinv = 1.f / es[rr];
                float v0 = fmaxf(fmaf(ex[rr][0], rinv, -thr), 0.f);
                float v1 = fmaxf(fmaf(ex[rr][1], rinv, -thr), 0.f);
                float v2 = fmaxf(fmaf(ex[rr][2], rinv, -thr), 0.f);
                float v3 = fmaxf(fmaf(ex[rr][3], rinv, -thr), 0.f);
                float v4 = val4 ? fmaxf(fmaf(ex[rr][4], rinv, -thr), 0.f) : 0.f;
                float gs = v0 + v1 + v2 + v3 + v4;
                #pragma unroll
                for (int o = 16; o; o >>= 1) gs += __shfl_xor_sync(~0u, gs, o);

                float c0 = __shfl_sync(~0u, v0, 0);
                float c1 = __shfl_sync(~0u, v0, cols1);
                float c2 = __shfl_sync(~0u, v0, cols2);
                float c3 = __shfl_sync(~0u, v0, cols3);
                float c4c = __shfl_sync(~0u, v0, cols4);
                float c5 = __shfl_sync(~0u, v0, cols5);

                unsigned p0 = 0, p1 = 0;
                #pragma unroll
                for (int jb = 0; jb < 5; jb++) {
                    int j = jb * 32 + lane;
                    float vv = (jb == 0) ? v0 : (jb == 1) ? v1 : (jb == 2) ? v2
                             : (jb == 3) ? v3 : v4;
                    p0 += (vv > c0)                                   ? 1u        : 0u;
                    p0 += ((vv > c1) || (vv == c1 && j < cols1))      ? (1u<<8)   : 0u;
                    p0 += ((vv > c2) || (vv == c2 && j < cols2))      ? (1u<<16)  : 0u;
                    p0 += ((vv > c3) || (vv == c3 && j < cols3))      ? (1u<<24)  : 0u;
                    p1 += ((vv > c4c)|| (vv == c4c&& j < cols4))      ? 1u        : 0u;
                    p1 += ((vv > c5) || (vv == c5 && j < cols5))      ? (1u<<8)   : 0u;
                }
                #pragma unroll
                for (int o = 16; o; o >>= 1) {
                    p0 += __shfl_xor_sync(~0u, p0, o);
                    p1 += __shfl_xor_sync(~0u, p1, o);
                }
                int myp = (lane < 4) ? (int)((p0 >> (8 * lane)) & 255u)
                                     : (int)((p1 >> (8 * (lane - 4))) & 255u);
                unsigned ball = __ballot_sync(~0u, (lane < 6) && (myp == r));
                int cnt = 6;
                if (!ball) { if (lane == 6) myp = r; cnt = 7; }

                int base = (bh * Rn + r) * 8;
                float rmax = 0.f;
                for (int i = 0; i < cnt; i++) {
                    int pp = __shfl_sync(~0u, myp, i);
                    int jbp = pp >> 5;
                    float av = (jbp == 0) ? v0 : (jbp == 1) ? v1 : (jbp == 2) ? v2
                             : (jbp == 3) ? v3 : v4;
                    float vv = __shfl_sync(~0u, av, pp & 31);
                    if (lane == 0) { g_spcol[base + i] = pp; g_spval[base + i] = vv; }
                    rmax = fmaxf(rmax, vv);
                }
                if (lane == 0) {
                    g_spcnt[bh * Rn + r] = cnt;
                    gapAcc += gs;
                    maxAcc = fmaxf(maxAcc, rmax);
                }
            }
        }
        __syncthreads();   // panel buffer handoff
    }

    if (lane == 0) { s_gap[w] = gapAcc; s_max[w] = maxAcc; }
    __syncthreads();
    if (tid == 0) {
        float gsum = 0.f, mx = 0.f;
        #pragma unroll
        for (int i = 0; i < 8; i++) { gsum += s_gap[i]; mx = fmaxf(mx, s_max[i]); }
        g_gap[bh] = gsum; g_maxA[bh] = mx;
    }
}

// ---------------- K3: SE gate + flags -------------------------------------
__global__ void k_gate(const float* __restrict__ seW1, const float* __restrict__ seb1,
                       const float* __restrict__ seW2, const float* __restrict__ seb2)
{
    int b = blockIdx.x;
    if (threadIdx.x) return;
    float g[8];
    #pragma unroll
    for (int h = 0; h < 8; h++) g[h] = g_gap[b * 8 + h] * (1.f / 16900.f);
    float hd[4];
    #pragma unroll
    for (int j = 0; j < 4; j++) {
        float a = seb1[j];
        #pragma unroll
        for (int h = 0; h < 8; h++) a = fmaf(seW1[j * 8 + h], g[h], a);
        hd[j] = fmaxf(a, 0.f);
    }
    #pragma unroll
    for (int i = 0; i < 8; i++) {
        float z = seb2[i];
        #pragma unroll
        for (int j = 0; j < 4; j++) z = fmaf(seW2[i * 4 + j], hd[j], z);
        float gt = floorf(1.f / (1.f + expf(-z)));   // .long() truncation
        g_gate[b * 8 + i] = gt;
        g_flag[b * 8 + i] = (gt != 0.f) && (g_maxA[b * 8 + i] > 0.f);
    }
}

// ---------------- Kprep: S[t] = sum_i relu(gcn_b[i][t]) -------------------
__global__ void k_prep(const float* __restrict__ gcn_b)
{
    __shared__ float red[256];
    int t = threadIdx.x;
    float s = 0.f;
    #pragma unroll
    for (int i = 0; i < 8; i++) s += fmaxf(gcn_b[i * 256 + t], 0.f);
    g_S[t] = s;
    red[t] = s; __syncthreads();
    for (int o = 128; o; o >>= 1) { if (t < o) red[t] += red[t + o]; __syncthreads(); }
    if (t == 0) g_S[256] = red[0] * (1.f / 256.f);
}

// ---------------- GCN: all 8 layers, one block per (b,h), flag-guarded ----
__global__ void k_gcnall(const float* __restrict__ x,
                         const float* __restrict__ gcnW, const float* __restrict__ gcnb)
{
    int bh = blockIdx.x;
    if (!g_flag[bh]) return;
    int b = bh >> 3;
    float gt = g_gate[bh];
    size_t base = (size_t)bh * Rn * Tn;
    const float* xb = x + (size_t)b * Rn * Tn;

    for (int e = threadIdx.x; e < Rn * Tn; e += 256) g_feats[base + e] = xb[e];
    __syncthreads();

    for (int L = 0; L < 8; L++) {
        const float* W    = gcnW + (size_t)L * Tn * Tn;
        const float* bias = gcnb + L * Tn;
        for (int e = threadIdx.x; e < Rn * Tn; e += 256) {
            int r = e >> 8, t = e & 255;
            int cnt = g_spcnt[bh * Rn + r];
            int sb  = (bh * Rn + r) * 8;
            float a = 0.f;
            for (int i = 0; i < cnt; i++)
                a = fmaf(g_spval[sb + i],
                         g_feats[base + (size_t)g_spcol[sb + i] * Tn + t], a);
            g_agg[base + e] = a * gt;
        }
        __syncthreads();
        for (int e = threadIdx.x; e < Rn * Tn; e += 256) {
            int r = e >> 8, t = e & 255;
            float acc = bias[t];
            const float* ag = g_agg + base + (size_t)r * Tn;
            const float* wr = W + (size_t)t * Tn;
            for (int u = 0; u < Tn; u++) acc = fmaf(ag[u], wr[u], acc);
            g_feats[base + e] = fmaxf(acc, 0.f) + g_feats[base + e];
        }
        __syncthreads();
    }
}

// ---------------- K5: fusion + pool + MLP head ----------------------------
__global__ void k_head(const float* __restrict__ x,
                       const float* __restrict__ fw, const float* __restrict__ fb,
                       const float* __restrict__ W1, const float* __restrict__ b1,
                       const float* __restrict__ W2, const float* __restrict__ b2,
                       const float* __restrict__ W3, const float* __restrict__ b3,
                       float* __restrict__ out)
{
    int b = blockIdx.x;
    int tid = threadIdx.x, lane = tid & 31, w = tid >> 5;
    __shared__ float pooled[132], sh1[64], sh2[16];
    __shared__ float swf[8];
    __shared__ int   sfl[8];
    if (tid < 8) { swf[tid] = fw[tid]; sfl[tid] = g_flag[b * 8 + tid]; }
    __syncthreads();
    float meanS = g_S[256], fbv = *fb;

    for (int r = w; r < Rn; r += 8) {
        const float* xr = x + ((size_t)b * Rn + r) * Tn;
        float sx = 0.f;
        for (int t = lane; t < Tn; t += 32) sx += xr[t];
        #pragma unroll
        for (int o = 16; o; o >>= 1) sx += __shfl_xor_sync(~0u, sx, o);
        float mx = sx * (1.f / 256.f);
        float acc = fbv;
        #pragma unroll
        for (int h = 0; h < 8; h++) {
            if (sfl[h]) {
                const float* fr = g_feats + ((size_t)(b * 8 + h) * Rn + r) * Tn;
                float sf = 0.f;
                for (int t = lane; t < Tn; t += 32) sf += fr[t];
                #pragma unroll
                for (int o = 16; o; o >>= 1) sf += __shfl_xor_sync(~0u, sf, o);
                acc = fmaf(swf[h], sf * (1.f / 256.f), acc);
            } else {
                acc = fmaf(swf[h], mx + meanS, acc);   // closed form: feats = x + S
            }
        }
        if (lane == 0) pooled[r] = acc;
    }
    __syncthreads();
    if (tid < 64) {
        float a = b1[tid];
        for (int r = 0; r < Rn; r++) a = fmaf(W1[tid * Rn + r], pooled[r], a);
        sh1[tid] = fmaxf(a, 0.f);
    }
    __syncthreads();
    if (tid < 16) {
        float a = b2[tid];
        #pragma unroll
        for (int j = 0; j < 64; j++) a = fmaf(W2[tid * 64 + j], sh1[j], a);
        sh2[tid] = fmaxf(a, 0.f);
    }
    __syncthreads();
    if (tid < 5) {
        float a = b3[tid];
        #pragma unroll
        for (int j = 0; j < 16; j++) a = fmaf(W3[tid * 16 + j], sh2[j], a);
        out[b * 5 + tid] = fmaxf(a, 0.f);
    }
}

// ---------------- launch ---------------------------------------------------
extern "C" void kernel_launch(void* const* d_in, const int* in_sizes, int n_in,
                              void* d_out, int out_size)
{
    const float* x    = (const float*)d_in[0];
    const float* Wq   = (const float*)d_in[1];
    const float* bq   = (const float*)d_in[2];
    const float* Wk   = (const float*)d_in[3];
    const float* bk   = (const float*)d_in[4];
    const float* thr  = (const float*)d_in[5];
    const float* seW1 = (const float*)d_in[6];
    const float* seb1 = (const float*)d_in[7];
    const float* seW2 = (const float*)d_in[8];
    const float* seb2 = (const float*)d_in[9];
    const float* gcnW = (const float*)d_in[10];
    const float* gcnb = (const float*)d_in[11];
    const float* fw   = (const float*)d_in[12];
    const float* fb   = (const float*)d_in[13];
    const float* W1   = (const float*)d_in[14];
    const float* b1   = (const float*)d_in[15];
    const float* W2   = (const float*)d_in[16];
    const float* b2   = (const float*)d_in[17];
    const float* W3   = (const float*)d_in[18];
    const float* b3   = (const float*)d_in[19];
    float* out = (float*)d_out;

    const int SMEM_ATTN = 2 * 144 * QSH * 2 + 2 * 16 * PS * 4;   // 43520 B
    cudaFuncSetAttribute(k_attn, cudaFuncAttributeMaxDynamicSharedMemorySize,
                         SMEM_ATTN);

    dim3 g1(Mn / 64, NQK / 128);
    k_prep<<<1, 256>>>(gcnb);                            // launch 1
    k_cvt<<<2144, 256>>>(x, Wq, Wk);                     // launch 2
    k_qkproj<<<g1, 256>>>(bq, bk);                       // launch 3
    k_attn<<<BHn, 256, SMEM_ATTN>>>(thr);                // launch 4 <- ncu capture
    k_gate<<<Bn, 32>>>(seW1, seb1, seW2, seb2);          // launch 5
    k_gcnall<<<BHn, 256>>>(x, gcnW, gcnb);               // launch 6
    k_head<<<Bn, 256>>>(x, fw, fb, W1, b1, W2, b2, W3, b3, out);  // launch 7
}

// round 16
// speedup vs baseline: 4.7906x; 1.0015x over previous
#include <cuda_runtime.h>
#include <cstdint>
#include <cuda_bf16.h>
#include <mma.h>
#include <math.h>

using namespace nvcuda;

#define Bn   128
#define Hn   8
#define Rn   130
#define Tn   256
#define Qd   32
#define BHn  (Bn*Hn)     /* 1024 */
#define Mn   (Bn*Rn)     /* 16640 */
#define NQK  512

// ---------------- device scratch (no allocations allowed) ----------------
__device__ __align__(16) __nv_bfloat16 g_qkb[(size_t)Mn*NQK];  // q|k + bias, bf16
__device__ __align__(16) __nv_bfloat16 g_xb[(size_t)Mn*256];   // x in bf16
__device__ __align__(16) __nv_bfloat16 g_wb[512*256];          // Wq||Wk in bf16
__device__ float g_feats[(size_t)BHn*Rn*Tn];      // GCN features (flagged heads only)
__device__ float g_agg[(size_t)BHn*Rn*Tn];        // sparse A @ feats scratch
__device__ float g_spval[BHn*Rn*8];               // sparse A values (pre-gate)
__device__ int   g_spcol[BHn*Rn*8];               // sparse A column indices
__device__ int   g_spcnt[BHn*Rn];                 // nnz per row
__device__ float g_gap[BHn];                      // sum of rel per (b,h)
__device__ float g_maxA[BHn];                     // max kept rel value per (b,h)
__device__ float g_gate[BHn];                     // SE gate (0 or 1)
__device__ int   g_flag[BHn];                     // gate!=0 && maxA>0
__device__ float g_S[Tn+1];                       // S[t]=sum_i relu(gcn_b[i][t]); S[256]=mean

__global__ void k_nop() {}

// ---------------- K0: fp32 -> bf16 conversion (x, Wq, Wk) -----------------
__global__ void k_cvt(const float* __restrict__ x,
                      const float* __restrict__ Wq, const float* __restrict__ Wk)
{
    const size_t NXQ = (size_t)Mn * 256 / 4;   // x quads
    const size_t NWQ = 65536 / 4;              // per-W quads
    size_t tot = NXQ + 2 * NWQ;
    for (size_t q = (size_t)blockIdx.x * blockDim.x + threadIdx.x;
         q < tot; q += (size_t)gridDim.x * blockDim.x) {
        const float* src;
        __nv_bfloat16* dst;
        size_t off;
        if (q < NXQ)            { src = x;  dst = g_xb;          off = q; }
        else if (q < NXQ + NWQ) { src = Wq; dst = g_wb;          off = q - NXQ; }
        else                    { src = Wk; dst = g_wb + 65536;  off = q - NXQ - NWQ; }
        float4 v = *(const float4*)(src + off * 4);
        __nv_bfloat162 lo = __floats2bfloat162_rn(v.x, v.y);
        __nv_bfloat162 hi = __floats2bfloat162_rn(v.z, v.w);
        *(__nv_bfloat162*)(dst + off * 4)     = lo;
        *(__nv_bfloat162*)(dst + off * 4 + 2) = hi;
    }
}

// ---------------- K1: qkb = bf16(xb @ wb^T + bias)  (bf16 HMMA, BK=64) ----
#define XPH 72   /* smem row stride in halfs (144B): conflict-free ldmatrix */
__global__ void __launch_bounds__(256, 3)
k_qkproj(const float* __restrict__ bq, const float* __restrict__ bk)
{
    __shared__ __align__(16) __nv_bfloat16 Xs[64 * XPH];
    __shared__ __align__(16) __nv_bfloat16 Ws[128 * XPH];
    __shared__ __align__(16) float Sb[8][16 * 20];

    int tid = threadIdx.x;
    int wid = tid >> 5;
    int lane = tid & 31;
    int m0 = blockIdx.x * 64, n0 = blockIdx.y * 128;
    int wm = wid >> 2;          // 0..1 : 32-row slice
    int wn = wid & 3;           // 0..3 : 32-col slice

    const __nv_bfloat16* Xbase = g_xb + (size_t)m0 * 256;
    const __nv_bfloat16* Wbase = g_wb + (size_t)n0 * 256;
    const float* Bbase = (n0 < 256) ? (bq + n0) : (bk + n0 - 256);

    wmma::fragment<wmma::accumulator, 16, 16, 16, float> acc[2][2];
    #pragma unroll
    for (int i = 0; i < 2; i++)
        #pragma unroll
        for (int j = 0; j < 2; j++)
            wmma::fill_fragment(acc[i][j], 0.0f);

    for (int k0 = 0; k0 < 256; k0 += 64) {
        #pragma unroll
        for (int i = 0; i < 6; i++) {
            int s = tid + i * 256;
            int c8 = (s & 7) * 8;
            if (s < 512) {
                int row = s >> 3;
                *(float4*)&Xs[row * XPH + c8] =
                    *(const float4*)(Xbase + (size_t)row * 256 + k0 + c8);
            } else {
                int row = (s - 512) >> 3;
                *(float4*)&Ws[row * XPH + c8] =
                    *(const float4*)(Wbase + (size_t)row * 256 + k0 + c8);
            }
        }
        __syncthreads();

        #pragma unroll
        for (int kk = 0; kk < 64; kk += 16) {
            wmma::fragment<wmma::matrix_a, 16, 16, 16, __nv_bfloat16, wmma::row_major> af[2];
            wmma::fragment<wmma::matrix_b, 16, 16, 16, __nv_bfloat16, wmma::col_major> bf[2];
            #pragma unroll
            for (int i = 0; i < 2; i++)
                wmma::load_matrix_sync(af[i], &Xs[(wm * 32 + i * 16) * XPH + kk], XPH);
            #pragma unroll
            for (int j = 0; j < 2; j++)
                wmma::load_matrix_sync(bf[j], &Ws[(wn * 32 + j * 16) * XPH + kk], XPH);
            #pragma unroll
            for (int i = 0; i < 2; i++)
                #pragma unroll
                for (int j = 0; j < 2; j++)
                    wmma::mma_sync(acc[i][j], af[i], bf[j], acc[i][j]);
        }
        __syncthreads();
    }

    // epilogue: +bias, convert bf16, vectorized store
    int r  = lane >> 1;
    int cs = (lane & 1) * 8;
    float b8[2][8];
    #pragma unroll
    for (int j = 0; j < 2; j++) {
        float4 u = *(const float4*)(Bbase + wn * 32 + j * 16 + cs);
        float4 v = *(const float4*)(Bbase + wn * 32 + j * 16 + cs + 4);
        b8[j][0] = u.x; b8[j][1] = u.y; b8[j][2] = u.z; b8[j][3] = u.w;
        b8[j][4] = v.x; b8[j][5] = v.y; b8[j][6] = v.z; b8[j][7] = v.w;
    }
    #pragma unroll
    for (int i = 0; i < 2; i++)
        #pragma unroll
        for (int j = 0; j < 2; j++) {
            wmma::store_matrix_sync(&Sb[wid][0], acc[i][j], 20, wmma::mem_row_major);
            __syncwarp();
            const float* src = &Sb[wid][r * 20 + cs];
            __align__(16) __nv_bfloat16 o[8];
            #pragma unroll
            for (int t = 0; t < 8; t++)
                o[t] = __float2bfloat16(src[t] + b8[j][t]);
            __nv_bfloat16* dst = g_qkb + (size_t)(m0 + wm * 32 + i * 16 + r) * NQK
                                       + n0 + wn * 32 + j * 16 + cs;
            *(uint4*)dst = *(const uint4*)o;
            __syncwarp();
        }
}

// ---------------- K2: attn, bf16 QK^T, balanced 8-tile panels -------------
// Row max of softmax == 1/se. rinv <= thr => relu(softmax - thr) == 0 exactly.
// MMA covers cols 0..127 (1 tile per warp); cols 128,129 via scalar dots.
#define QSH 40   /* q/k smem row stride in halfs (80B): conflict-free ldmatrix */
#define PS 132   /* rel panel row stride (fp32) */
__global__ void __launch_bounds__(256, 5)
k_attn(const float* __restrict__ thr_p)
{
    extern __shared__ char smd[];
    __nv_bfloat16* sq = (__nv_bfloat16*)smd;                     // 144*40 halfs
    __nv_bfloat16* sk = (__nv_bfloat16*)(smd + 144 * QSH * 2);   // 144*40 halfs
    float*        pan = (float*)(smd + 2 * 144 * QSH * 2);       // 2 x 16*132 fp32
    __shared__ float s_gap[8], s_max[8];

    int bh = blockIdx.x, b = bh >> 3, h = bh & 7;
    int tid = threadIdx.x, lane = tid & 31, w = tid >> 5;
    const float thr = *thr_p;

    // load q,k (bias pre-folded, bf16) ; rows 130..143 zero
    for (int e = tid; e < 1152; e += 256) {
        int u = (e < 576) ? e : e - 576;
        int r = u >> 2, seg = (u & 3) * 8;
        uint4 v = make_uint4(0u, 0u, 0u, 0u);
        if (r < Rn) {
            size_t src = (size_t)(b * Rn + r) * NQK + h * 32 + seg
                       + ((e < 576) ? 0 : 256);
            v = *(const uint4*)(g_qkb + src);
        }
        __nv_bfloat16* dst = (e < 576) ? sq : sk;
        *(uint4*)(dst + r * QSH + seg) = v;
    }
    __syncthreads();

    float gapAcc = 0.f, maxAcc = 0.f;
    const float sc = 0.17677669529663687f;   // 1/sqrt(32)
    const int cols1 = 4, cols2 = 5, cols3 = 6, cols4 = 7, cols5 = 8;
    bool val4 = (lane < 2);   // cols 128,129 live in slot 4 lanes 0,1

    // per-lane k columns 128/129 elements (constant per block)
    float k128 = __bfloat162float(sk[128 * QSH + lane]);
    float k129 = __bfloat162float(sk[129 * QSH + lane]);

    // prologue: panel 0 MMA (tile w: cols 16w..16w+15)
    {
        wmma::fragment<wmma::accumulator, 16, 16, 16, float> c;
        wmma::fill_fragment(c, 0.0f);
        #pragma unroll
        for (int kk = 0; kk < 32; kk += 16) {
            wmma::fragment<wmma::matrix_a, 16, 16, 16, __nv_bfloat16, wmma::row_major> a;
            wmma::fragment<wmma::matrix_b, 16, 16, 16, __nv_bfloat16, wmma::col_major> bb;
            wmma::load_matrix_sync(a,  sq + 0 * QSH + kk, QSH);
            wmma::load_matrix_sync(bb, sk + w * 16 * QSH + kk, QSH);
            wmma::mma_sync(c, a, bb, c);
        }
        wmma::store_matrix_sync(pan + w * 16, c, PS, wmma::mem_row_major);
    }
    __syncthreads();

    for (int p = 0; p < 9; p++) {
        // MMA for panel p+1 into the other buffer (overlaps postprocess of p)
        if (p < 8) {
            int r1 = (p + 1) * 16;
            float* pn = pan + ((p + 1) & 1) * 16 * PS;
            wmma::fragment<wmma::accumulator, 16, 16, 16, float> c;
            wmma::fill_fragment(c, 0.0f);
            #pragma unroll
            for (int kk = 0; kk < 32; kk += 16) {
                wmma::fragment<wmma::matrix_a, 16, 16, 16, __nv_bfloat16, wmma::row_major> a;
                wmma::fragment<wmma::matrix_b, 16, 16, 16, __nv_bfloat16, wmma::col_major> bb;
                wmma::load_matrix_sync(a,  sq + r1 * QSH + kk, QSH);
                wmma::load_matrix_sync(bb, sk + w * 16 * QSH + kk, QSH);
                wmma::mma_sync(c, a, bb, c);
            }
            wmma::store_matrix_sync(pn + w * 16, c, PS, wmma::mem_row_major);
        }

        // postprocess panel p: warp w handles rows r0+2w, r0+2w+1
        int r0 = p * 16;
        const float* pb = pan + (p & 1) * 16 * PS;
        int rA = r0 + 2 * w;

        // scalar dots for cols 128/129 (4 interleaved reduce chains)
        float q0 = __bfloat162float(sq[rA * QSH + lane]);
        float q1 = __bfloat162float(sq[(rA + 1) * QSH + lane]);
        float d0 = q0 * k128, d1 = q0 * k129, d2 = q1 * k128, d3 = q1 * k129;
        #pragma unroll
        for (int o = 16; o; o >>= 1) {
            d0 += __shfl_xor_sync(~0u, d0, o);
            d1 += __shfl_xor_sync(~0u, d1, o);
            d2 += __shfl_xor_sync(~0u, d2, o);
            d3 += __shfl_xor_sync(~0u, d3, o);
        }

        float x[2][5], ex[2][5], lm[2], es[2];
        x[0][4] = ((lane == 0) ? d0 : d1) * sc;
        x[1][4] = ((lane == 0) ? d2 : d3) * sc;
        #pragma unroll
        for (int rr = 0; rr < 2; rr++) {
            const float* prow = pb + (2 * w + rr) * PS;
            #pragma unroll
            for (int jb = 0; jb < 4; jb++)
                x[rr][jb] = prow[jb * 32 + lane] * sc;
            lm[rr] = fmaxf(fmaxf(fmaxf(x[rr][0], x[rr][1]),
                                 fmaxf(x[rr][2], x[rr][3])),
                           val4 ? x[rr][4] : -1e30f);
        }
        #pragma unroll
        for (int o = 16; o; o >>= 1) {
            lm[0] = fmaxf(lm[0], __shfl_xor_sync(~0u, lm[0], o));
            lm[1] = fmaxf(lm[1], __shfl_xor_sync(~0u, lm[1], o));
        }
        #pragma unroll
        for (int rr = 0; rr < 2; rr++) {
            ex[rr][0] = __expf(x[rr][0] - lm[rr]);
            ex[rr][1] = __expf(x[rr][1] - lm[rr]);
            ex[rr][2] = __expf(x[rr][2] - lm[rr]);
            ex[rr][3] = __expf(x[rr][3] - lm[rr]);
            ex[rr][4] = val4 ? __expf(x[rr][4] - lm[rr]) : 0.f;
            es[rr] = ex[rr][0] + ex[rr][1] + ex[rr][2] + ex[rr][3] + ex[rr][4];
        }
        #pragma unroll
        for (int o = 16; o; o >>= 1) {
            es[0] += __shfl_xor_sync(~0u, es[0], o);
            es[1] += __shfl_xor_sync(~0u, es[1], o);
        }

        unsigned dm = 0;
        #pragma unroll
        for (int rr = 0; rr < 2; rr++)
            if (1.f <= thr * es[rr]) dm |= (1u << rr);   // rinv <= thr: row dead
        if (lane < 2) {
            int r = rA + lane;
            if (r < Rn && ((dm >> lane) & 1u)) g_spcnt[bh * Rn + r] = 0;
        }

        if (dm != 3u) {
            // ---- rare full path ----
            #pragma unroll
            for (int rr = 0; rr < 2; rr++) {
                int r = rA + rr;
                if (r >= Rn || ((dm >> rr) & 1u)) continue;
                float rinv = 1.f / es[rr];
                float v0 = fmaxf(fmaf(ex[rr][0], rinv, -thr), 0.f);
                float v1 = fmaxf(fmaf(ex[rr][1], rinv, -thr), 0.f);
                float v2 = fmaxf(fmaf(ex[rr][2], rinv, -thr), 0.f);
                float v3 = fmaxf(fmaf(ex[rr][3], rinv, -thr), 0.f);
                float v4 = val4 ? fmaxf(fmaf(ex[rr][4], rinv, -thr), 0.f) : 0.f;
                float gs = v0 + v1 + v2 + v3 + v4;
                #pragma unroll
                for (int o = 16; o; o >>= 1) gs += __shfl_xor_sync(~0u, gs, o);

                float c0 = __shfl_sync(~0u, v0, 0);
                float c1 = __shfl_sync(~0u, v0, cols1);
                float c2 = __shfl_sync(~0u, v0, cols2);
                float c3 = __shfl_sync(~0u, v0, cols3);
                float c4c = __shfl_sync(~0u, v0, cols4);
                float c5 = __shfl_sync(~0u, v0, cols5);

                unsigned p0 = 0, p1 = 0;
                #pragma unroll
                for (int jb = 0; jb < 5; jb++) {
                    int j = jb * 32 + lane;
                    float vv = (jb == 0) ? v0 : (jb == 1) ? v1 : (jb == 2) ? v2
                             : (jb == 3) ? v3 : v4;
                    p0 += (vv > c0)                                   ? 1u        : 0u;
                    p0 += ((vv > c1) || (vv == c1 && j < cols1))      ? (1u<<8)   : 0u;
                    p0 += ((vv > c2) || (vv == c2 && j < cols2))      ? (1u<<16)  : 0u;
                    p0 += ((vv > c3) || (vv == c3 && j < cols3))      ? (1u<<24)  : 0u;
                    p1 += ((vv > c4c)|| (vv == c4c&& j < cols4))      ? 1u        : 0u;
                    p1 += ((vv > c5) || (vv == c5 && j < cols5))      ? (1u<<8)   : 0u;
                }
                #pragma unroll
                for (int o = 16; o; o >>= 1) {
                    p0 += __shfl_xor_sync(~0u, p0, o);
                    p1 += __shfl_xor_sync(~0u, p1, o);
                }
                int myp = (lane < 4) ? (int)((p0 >> (8 * lane)) & 255u)
                                     : (int)((p1 >> (8 * (lane - 4))) & 255u);
                unsigned ball = __ballot_sync(~0u, (lane < 6) && (myp == r));
                int cnt = 6;
                if (!ball) { if (lane == 6) myp = r; cnt = 7; }

                int base = (bh * Rn + r) * 8;
                float rmax = 0.f;
                for (int i = 0; i < cnt; i++) {
                    int pp = __shfl_sync(~0u, myp, i);
                    int jbp = pp >> 5;
                    float av = (jbp == 0) ? v0 : (jbp == 1) ? v1 : (jbp == 2) ? v2
                             : (jbp == 3) ? v3 : v4;
                    float vv = __shfl_sync(~0u, av, pp & 31);
                    if (lane == 0) { g_spcol[base + i] = pp; g_spval[base + i] = vv; }
                    rmax = fmaxf(rmax, vv);
                }
                if (lane == 0) {
                    g_spcnt[bh * Rn + r] = cnt;
                    gapAcc += gs;
                    maxAcc = fmaxf(maxAcc, rmax);
                }
            }
        }
        __syncthreads();   // panel buffer handoff
    }

    if (lane == 0) { s_gap[w] = gapAcc; s_max[w] = maxAcc; }
    __syncthreads();
    if (tid == 0) {
        float gsum = 0.f, mx = 0.f;
        #pragma unroll
        for (int i = 0; i < 8; i++) { gsum += s_gap[i]; mx = fmaxf(mx, s_max[i]); }
        g_gap[bh] = gsum; g_maxA[bh] = mx;
    }
}

// ---------------- K3: SE gate + flags (one block, thread=batch) -----------
__global__ void k_gate(const float* __restrict__ seW1, const float* __restrict__ seb1,
                       const float* __restrict__ seW2, const float* __restrict__ seb2)
{
    int b = threadIdx.x;
    if (b >= Bn) return;
    float g[8];
    #pragma unroll
    for (int h = 0; h < 8; h++) g[h] = g_gap[b * 8 + h] * (1.f / 16900.f);
    float hd[4];
    #pragma unroll
    for (int j = 0; j < 4; j++) {
        float a = seb1[j];
        #pragma unroll
        for (int h = 0; h < 8; h++) a = fmaf(seW1[j * 8 + h], g[h], a);
        hd[j] = fmaxf(a, 0.f);
    }
    #pragma unroll
    for (int i = 0; i < 8; i++) {
        float z = seb2[i];
        #pragma unroll
        for (int j = 0; j < 4; j++) z = fmaf(seW2[i * 4 + j], hd[j], z);
        float gt = floorf(1.f / (1.f + expf(-z)));   // .long() truncation
        g_gate[b * 8 + i] = gt;
        g_flag[b * 8 + i] = (gt != 0.f) && (g_maxA[b * 8 + i] > 0.f);
    }
}

// ---------------- Kprep: S[t] = sum_i relu(gcn_b[i][t]) -------------------
__global__ void k_prep(const float* __restrict__ gcn_b)
{
    __shared__ float red[256];
    int t = threadIdx.x;
    float s = 0.f;
    #pragma unroll
    for (int i = 0; i < 8; i++) s += fmaxf(gcn_b[i * 256 + t], 0.f);
    g_S[t] = s;
    red[t] = s; __syncthreads();
    for (int o = 128; o; o >>= 1) { if (t < o) red[t] += red[t + o]; __syncthreads(); }
    if (t == 0) g_S[256] = red[0] * (1.f / 256.f);
}

// ---------------- GCN: all 8 layers, one block per (b,h), flag-guarded ----
__global__ void k_gcnall(const float* __restrict__ x,
                         const float* __restrict__ gcnW, const float* __restrict__ gcnb)
{
    int bh = blockIdx.x;
    if (!g_flag[bh]) return;
    int b = bh >> 3;
    float gt = g_gate[bh];
    size_t base = (size_t)bh * Rn * Tn;
    const float* xb = x + (size_t)b * Rn * Tn;

    for (int e = threadIdx.x; e < Rn * Tn; e += 256) g_feats[base + e] = xb[e];
    __syncthreads();

    for (int L = 0; L < 8; L++) {
        const float* W    = gcnW + (size_t)L * Tn * Tn;
        const float* bias = gcnb + L * Tn;
        for (int e = threadIdx.x; e < Rn * Tn; e += 256) {
            int r = e >> 8, t = e & 255;
            int cnt = g_spcnt[bh * Rn + r];
            int sb  = (bh * Rn + r) * 8;
            float a = 0.f;
            for (int i = 0; i < cnt; i++)
                a = fmaf(g_spval[sb + i],
                         g_feats[base + (size_t)g_spcol[sb + i] * Tn + t], a);
            g_agg[base + e] = a * gt;
        }
        __syncthreads();
        for (int e = threadIdx.x; e < Rn * Tn; e += 256) {
            int r = e >> 8, t = e & 255;
            float acc = bias[t];
            const float* ag = g_agg + base + (size_t)r * Tn;
            const float* wr = W + (size_t)t * Tn;
            for (int u = 0; u < Tn; u++) acc = fmaf(ag[u], wr[u], acc);
            g_feats[base + e] = fmaxf(acc, 0.f) + g_feats[base + e];
        }
        __syncthreads();
    }
}

// ---------------- K5: fusion + pool + MLP head ----------------------------
__global__ void k_head(const float* __restrict__ x,
                       const float* __restrict__ fw, const float* __restrict__ fb,
                       const float* __restrict__ W1, const float* __restrict__ b1,
                       const float* __restrict__ W2, const float* __restrict__ b2,
                       const float* __restrict__ W3, const float* __restrict__ b3,
                       float* __restrict__ out)
{
    int b = blockIdx.x;
    int tid = threadIdx.x, lane = tid & 31, w = tid >> 5;
    __shared__ float pooled[132], sh1[64], sh2[16];
    __shared__ float swf[8];
    __shared__ int   sfl[8];
    if (tid < 8) { swf[tid] = fw[tid]; sfl[tid] = g_flag[b * 8 + tid]; }
    __syncthreads();
    float meanS = g_S[256], fbv = *fb;

    for (int r = w; r < Rn; r += 8) {
        const float* xr = x + ((size_t)b * Rn + r) * Tn;
        float sx = 0.f;
        for (int t = lane; t < Tn; t += 32) sx += xr[t];
        #pragma unroll
        for (int o = 16; o; o >>= 1) sx += __shfl_xor_sync(~0u, sx, o);
        float mx = sx * (1.f / 256.f);
        float acc = fbv;
        #pragma unroll
        for (int h = 0; h < 8; h++) {
            if (sfl[h]) {
                const float* fr = g_feats + ((size_t)(b * 8 + h) * Rn + r) * Tn;
                float sf = 0.f;
                for (int t = lane; t < Tn; t += 32) sf += fr[t];
                #pragma unroll
                for (int o = 16; o; o >>= 1) sf += __shfl_xor_sync(~0u, sf, o);
                acc = fmaf(swf[h], sf * (1.f / 256.f), acc);
            } else {
                acc = fmaf(swf[h], mx + meanS, acc);   // closed form: feats = x + S
            }
        }
        if (lane == 0) pooled[r] = acc;
    }
    __syncthreads();
    if (tid < 64) {
        float a = b1[tid];
        for (int r = 0; r < Rn; r++) a = fmaf(W1[tid * Rn + r], pooled[r], a);
        sh1[tid] = fmaxf(a, 0.f);
    }
    __syncthreads();
    if (tid < 16) {
        float a = b2[tid];
        #pragma unroll
        for (int j = 0; j < 64; j++) a = fmaf(W2[tid * 64 + j], sh1[j], a);
        sh2[tid] = fmaxf(a, 0.f);
    }
    __syncthreads();
    if (tid < 5) {
        float a = b3[tid];
        #pragma unroll
        for (int j = 0; j < 16; j++) a = fmaf(W3[tid * 16 + j], sh2[j], a);
        out[b * 5 + tid] = fmaxf(a, 0.f);
    }
}

// ---------------- launch ---------------------------------------------------
extern "C" void kernel_launch(void* const* d_in, const int* in_sizes, int n_in,
                              void* d_out, int out_size)
{
    const float* x    = (const float*)d_in[0];
    const float* Wq   = (const float*)d_in[1];
    const float* bq   = (const float*)d_in[2];
    const float* Wk   = (const float*)d_in[3];
    const float* bk   = (const float*)d_in[4];
    const float* thr  = (const float*)d_in[5];
    const float* seW1 = (const float*)d_in[6];
    const float* seb1 = (const float*)d_in[7];
    const float* seW2 = (const float*)d_in[8];
    const float* seb2 = (const float*)d_in[9];
    const float* gcnW = (const float*)d_in[10];
    const float* gcnb = (const float*)d_in[11];
    const float* fw   = (const float*)d_in[12];
    const float* fb   = (const float*)d_in[13];
    const float* W1   = (const float*)d_in[14];
    const float* b1   = (const float*)d_in[15];
    const float* W2   = (const float*)d_in[16];
    const float* b2   = (const float*)d_in[17];
    const float* W3   = (const float*)d_in[18];
    const float* b3   = (const float*)d_in[19];
    float* out = (float*)d_out;

    const int SMEM_ATTN = 2 * 144 * QSH * 2 + 2 * 16 * PS * 4;   // 39936 B
    cudaFuncSetAttribute(k_attn, cudaFuncAttributeMaxDynamicSharedMemorySize,
                         SMEM_ATTN);

    dim3 g1(Mn / 64, NQK / 128);
    k_prep<<<1, 256>>>(gcnb);                            // launch 1
    k_cvt<<<2144, 256>>>(x, Wq, Wk);                     // launch 2
    k_qkproj<<<g1, 256>>>(bq, bk);                       // launch 3
    k_attn<<<BHn, 256, SMEM_ATTN>>>(thr);                // launch 4 <- ncu capture
    k_gate<<<1, 128>>>(seW1, seb1, seW2, seb2);          // launch 5
    k_gcnall<<<BHn, 256>>>(x, gcnW, gcnb);               // launch 6
    k_head<<<Bn, 256>>>(x, fw, fb, W1, b1, W2, b2, W3, b3, out);  // launch 7
}

// round 17
// speedup vs baseline: 5.2992x; 1.1062x over previous
#include <cuda_runtime.h>
#include <cstdint>
#include <cuda_bf16.h>
#include <mma.h>
#include <math.h>

using namespace nvcuda;

#define Bn   128
#define Hn   8
#define Rn   130
#define Tn   256
#define Qd   32
#define BHn  (Bn*Hn)     /* 1024 */
#define Mn   (Bn*Rn)     /* 16640 */
#define NQK  512

// ---------------- device scratch (no allocations allowed) ----------------
__device__ __align__(16) __nv_bfloat16 g_qkb[(size_t)Mn*NQK];  // q|k + bias, bf16
__device__ __align__(16) __nv_bfloat16 g_xb[(size_t)Mn*256];   // x in bf16
__device__ __align__(16) __nv_bfloat16 g_wb[512*256];          // Wq||Wk in bf16
__device__ float g_feats[(size_t)BHn*Rn*Tn];      // GCN features (flagged heads only)
__device__ float g_agg[(size_t)BHn*Rn*Tn];        // sparse A @ feats scratch
__device__ float g_spval[BHn*Rn*8];               // sparse A values (pre-gate)
__device__ int   g_spcol[BHn*Rn*8];               // sparse A column indices
__device__ int   g_spcnt[BHn*Rn];                 // nnz per row
__device__ float g_gap[BHn];                      // sum of rel per (b,h)
__device__ float g_maxA[BHn];                     // max kept rel value per (b,h)
__device__ float g_S[Tn+1];                       // S[t]=sum_i relu(gcn_b[i][t]); S[256]=mean

__global__ void k_nop() {}

// ---------------- SE gate helper (shared by gcnall / head) ----------------
__device__ __forceinline__ float se_gate(int b, int h,
                                         const float* seW1, const float* seb1,
                                         const float* seW2, const float* seb2)
{
    float g[8];
    #pragma unroll
    for (int j = 0; j < 8; j++) g[j] = g_gap[b * 8 + j] * (1.f / 16900.f);
    float hd[4];
    #pragma unroll
    for (int j = 0; j < 4; j++) {
        float a = seb1[j];
        #pragma unroll
        for (int t = 0; t < 8; t++) a = fmaf(seW1[j * 8 + t], g[t], a);
        hd[j] = fmaxf(a, 0.f);
    }
    float z = seb2[h];
    #pragma unroll
    for (int j = 0; j < 4; j++) z = fmaf(seW2[h * 4 + j], hd[j], z);
    return floorf(1.f / (1.f + expf(-z)));   // .long() truncation
}

// ---------------- K0: fp32->bf16 conversion + S-prep (block 0) ------------
__global__ void k_cvt(const float* __restrict__ x,
                      const float* __restrict__ Wq, const float* __restrict__ Wk,
                      const float* __restrict__ gcn_b)
{
    if (blockIdx.x == 0) {
        __shared__ float red[256];
        int t = threadIdx.x;
        float s = 0.f;
        #pragma unroll
        for (int i = 0; i < 8; i++) s += fmaxf(gcn_b[i * 256 + t], 0.f);
        g_S[t] = s;
        red[t] = s; __syncthreads();
        for (int o = 128; o; o >>= 1) { if (t < o) red[t] += red[t + o]; __syncthreads(); }
        if (t == 0) g_S[256] = red[0] * (1.f / 256.f);
    }
    const size_t NXQ = (size_t)Mn * 256 / 4;   // x quads
    const size_t NWQ = 65536 / 4;              // per-W quads
    size_t tot = NXQ + 2 * NWQ;
    for (size_t q = (size_t)blockIdx.x * blockDim.x + threadIdx.x;
         q < tot; q += (size_t)gridDim.x * blockDim.x) {
        const float* src;
        __nv_bfloat16* dst;
        size_t off;
        if (q < NXQ)            { src = x;  dst = g_xb;          off = q; }
        else if (q < NXQ + NWQ) { src = Wq; dst = g_wb;          off = q - NXQ; }
        else                    { src = Wk; dst = g_wb + 65536;  off = q - NXQ - NWQ; }
        float4 v = *(const float4*)(src + off * 4);
        __nv_bfloat162 lo = __floats2bfloat162_rn(v.x, v.y);
        __nv_bfloat162 hi = __floats2bfloat162_rn(v.z, v.w);
        *(__nv_bfloat162*)(dst + off * 4)     = lo;
        *(__nv_bfloat162*)(dst + off * 4 + 2) = hi;
    }
}

// ---------------- K1: qkb = bf16(xb @ wb^T + bias)  (bf16 HMMA, BK=64) ----
#define XPH 72   /* smem row stride in halfs (144B): conflict-free ldmatrix */
__global__ void __launch_bounds__(256, 3)
k_qkproj(const float* __restrict__ bq, const float* __restrict__ bk)
{
    __shared__ __align__(16) __nv_bfloat16 Xs[64 * XPH];
    __shared__ __align__(16) __nv_bfloat16 Ws[128 * XPH];
    __shared__ __align__(16) float Sb[8][16 * 20];

    int tid = threadIdx.x;
    int wid = tid >> 5;
    int lane = tid & 31;
    int m0 = blockIdx.x * 64, n0 = blockIdx.y * 128;
    int wm = wid >> 2;          // 0..1 : 32-row slice
    int wn = wid & 3;           // 0..3 : 32-col slice

    const __nv_bfloat16* Xbase = g_xb + (size_t)m0 * 256;
    const __nv_bfloat16* Wbase = g_wb + (size_t)n0 * 256;
    const float* Bbase = (n0 < 256) ? (bq + n0) : (bk + n0 - 256);

    wmma::fragment<wmma::accumulator, 16, 16, 16, float> acc[2][2];
    #pragma unroll
    for (int i = 0; i < 2; i++)
        #pragma unroll
        for (int j = 0; j < 2; j++)
            wmma::fill_fragment(acc[i][j], 0.0f);

    for (int k0 = 0; k0 < 256; k0 += 64) {
        #pragma unroll
        for (int i = 0; i < 6; i++) {
            int s = tid + i * 256;
            int c8 = (s & 7) * 8;
            if (s < 512) {
                int row = s >> 3;
                *(float4*)&Xs[row * XPH + c8] =
                    *(const float4*)(Xbase + (size_t)row * 256 + k0 + c8);
            } else {
                int row = (s - 512) >> 3;
                *(float4*)&Ws[row * XPH + c8] =
                    *(const float4*)(Wbase + (size_t)row * 256 + k0 + c8);
            }
        }
        __syncthreads();

        #pragma unroll
        for (int kk = 0; kk < 64; kk += 16) {
            wmma::fragment<wmma::matrix_a, 16, 16, 16, __nv_bfloat16, wmma::row_major> af[2];
            wmma::fragment<wmma::matrix_b, 16, 16, 16, __nv_bfloat16, wmma::col_major> bf[2];
            #pragma unroll
            for (int i = 0; i < 2; i++)
                wmma::load_matrix_sync(af[i], &Xs[(wm * 32 + i * 16) * XPH + kk], XPH);
            #pragma unroll
            for (int j = 0; j < 2; j++)
                wmma::load_matrix_sync(bf[j], &Ws[(wn * 32 + j * 16) * XPH + kk], XPH);
            #pragma unroll
            for (int i = 0; i < 2; i++)
                #pragma unroll
                for (int j = 0; j < 2; j++)
                    wmma::mma_sync(acc[i][j], af[i], bf[j], acc[i][j]);
        }
        __syncthreads();
    }

    // epilogue: +bias, convert bf16, vectorized store
    int r  = lane >> 1;
    int cs = (lane & 1) * 8;
    float b8[2][8];
    #pragma unroll
    for (int j = 0; j < 2; j++) {
        float4 u = *(const float4*)(Bbase + wn * 32 + j * 16 + cs);
        float4 v = *(const float4*)(Bbase + wn * 32 + j * 16 + cs + 4);
        b8[j][0] = u.x; b8[j][1] = u.y; b8[j][2] = u.z; b8[j][3] = u.w;
        b8[j][4] = v.x; b8[j][5] = v.y; b8[j][6] = v.z; b8[j][7] = v.w;
    }
    #pragma unroll
    for (int i = 0; i < 2; i++)
        #pragma unroll
        for (int j = 0; j < 2; j++) {
            wmma::store_matrix_sync(&Sb[wid][0], acc[i][j], 20, wmma::mem_row_major);
            __syncwarp();
            const float* src = &Sb[wid][r * 20 + cs];
            __align__(16) __nv_bfloat16 o[8];
            #pragma unroll
            for (int t = 0; t < 8; t++)
                o[t] = __float2bfloat16(src[t] + b8[j][t]);
            __nv_bfloat16* dst = g_qkb + (size_t)(m0 + wm * 32 + i * 16 + r) * NQK
                                       + n0 + wn * 32 + j * 16 + cs;
            *(uint4*)dst = *(const uint4*)o;
            __syncwarp();
        }
}

// ---------------- K2: attn, bf16 QK^T, rotated 9-tile panels --------------
// Row max of softmax == 1/se. rinv <= thr => relu(softmax - thr) == 0 exactly.
// Tiles 0..7 -> warp w; tile 8 (cols 128..143) -> warp (panel&7) extra.
#define QSH 40   /* q/k smem row stride in halfs (80B): conflict-free ldmatrix */
#define PS 148   /* rel panel row stride (fp32), >=144, mult of 4 */
__global__ void __launch_bounds__(256, 4)
k_attn(const float* __restrict__ thr_p)
{
    extern __shared__ char smd[];
    __nv_bfloat16* sq = (__nv_bfloat16*)smd;                     // 144*40 halfs
    __nv_bfloat16* sk = (__nv_bfloat16*)(smd + 144 * QSH * 2);   // 144*40 halfs
    float*        pan = (float*)(smd + 2 * 144 * QSH * 2);       // 2 x 16*148 fp32
    __shared__ float s_gap[8], s_max[8];

    int bh = blockIdx.x, b = bh >> 3, h = bh & 7;
    int tid = threadIdx.x, lane = tid & 31, w = tid >> 5;
    const float thr = *thr_p;

    // load q,k (bias pre-folded, bf16) ; rows 130..143 zero
    for (int e = tid; e < 1152; e += 256) {
        int u = (e < 576) ? e : e - 576;
        int r = u >> 2, seg = (u & 3) * 8;
        uint4 v = make_uint4(0u, 0u, 0u, 0u);
        if (r < Rn) {
            size_t src = (size_t)(b * Rn + r) * NQK + h * 32 + seg
                       + ((e < 576) ? 0 : 256);
            v = *(const uint4*)(g_qkb + src);
        }
        __nv_bfloat16* dst = (e < 576) ? sq : sk;
        *(uint4*)(dst + r * QSH + seg) = v;
    }
    __syncthreads();

    float gapAcc = 0.f, maxAcc = 0.f;
    const float sc = 0.17677669529663687f;   // 1/sqrt(32)
    const int cols1 = 4, cols2 = 5, cols3 = 6, cols4 = 7, cols5 = 8;
    bool val4 = (lane < 2);   // cols 128,129 live in slot 4 lanes 0,1

    // panel MMA helper pattern: warp w does tile w; warp (pp&7) also tile 8
    #define PANEL_MMA(ROWBASE, DSTPAN, PP)                                         \
    {                                                                              \
        wmma::fragment<wmma::accumulator, 16, 16, 16, float> c;                    \
        wmma::fill_fragment(c, 0.0f);                                              \
        _Pragma("unroll")                                                          \
        for (int kk = 0; kk < 32; kk += 16) {                                      \
            wmma::fragment<wmma::matrix_a, 16, 16, 16, __nv_bfloat16, wmma::row_major> a; \
            wmma::fragment<wmma::matrix_b, 16, 16, 16, __nv_bfloat16, wmma::col_major> bb; \
            wmma::load_matrix_sync(a,  sq + (ROWBASE) * QSH + kk, QSH);            \
            wmma::load_matrix_sync(bb, sk + w * 16 * QSH + kk, QSH);               \
            wmma::mma_sync(c, a, bb, c);                                           \
        }                                                                          \
        wmma::store_matrix_sync((DSTPAN) + w * 16, c, PS, wmma::mem_row_major);    \
        if (w == ((PP) & 7)) {                                                     \
            wmma::fragment<wmma::accumulator, 16, 16, 16, float> c8;               \
            wmma::fill_fragment(c8, 0.0f);                                         \
            _Pragma("unroll")                                                      \
            for (int kk = 0; kk < 32; kk += 16) {                                  \
                wmma::fragment<wmma::matrix_a, 16, 16, 16, __nv_bfloat16, wmma::row_major> a; \
                wmma::fragment<wmma::matrix_b, 16, 16, 16, __nv_bfloat16, wmma::col_major> bb; \
                wmma::load_matrix_sync(a,  sq + (ROWBASE) * QSH + kk, QSH);        \
                wmma::load_matrix_sync(bb, sk + 128 * QSH + kk, QSH);              \
                wmma::mma_sync(c8, a, bb, c8);                                     \
            }                                                                      \
            wmma::store_matrix_sync((DSTPAN) + 128, c8, PS, wmma::mem_row_major);  \
        }                                                                          \
    }

    // prologue: panel 0
    PANEL_MMA(0, pan, 0)
    __syncthreads();

    for (int p = 0; p < 9; p++) {
        if (p < 8) {
            float* pn = pan + ((p + 1) & 1) * 16 * PS;
            PANEL_MMA((p + 1) * 16, pn, p + 1)
        }

        // postprocess panel p: warp w handles rows r0+2w, r0+2w+1
        int r0 = p * 16;
        const float* pb = pan + (p & 1) * 16 * PS;
        int rA = r0 + 2 * w;
        float x[2][5], ex[2][5], lm[2], es[2];
        #pragma unroll
        for (int rr = 0; rr < 2; rr++) {
            const float* prow = pb + (2 * w + rr) * PS;
            #pragma unroll
            for (int jb = 0; jb < 5; jb++)
                x[rr][jb] = prow[jb * 32 + lane] * sc;
            lm[rr] = fmaxf(fmaxf(fmaxf(x[rr][0], x[rr][1]),
                                 fmaxf(x[rr][2], x[rr][3])),
                           val4 ? x[rr][4] : -1e30f);
        }
        #pragma unroll
        for (int o = 16; o; o >>= 1) {
            lm[0] = fmaxf(lm[0], __shfl_xor_sync(~0u, lm[0], o));
            lm[1] = fmaxf(lm[1], __shfl_xor_sync(~0u, lm[1], o));
        }
        #pragma unroll
        for (int rr = 0; rr < 2; rr++) {
            ex[rr][0] = __expf(x[rr][0] - lm[rr]);
            ex[rr][1] = __expf(x[rr][1] - lm[rr]);
            ex[rr][2] = __expf(x[rr][2] - lm[rr]);
            ex[rr][3] = __expf(x[rr][3] - lm[rr]);
            ex[rr][4] = val4 ? __expf(x[rr][4] - lm[rr]) : 0.f;
            es[rr] = ex[rr][0] + ex[rr][1] + ex[rr][2] + ex[rr][3] + ex[rr][4];
        }
        #pragma unroll
        for (int o = 16; o; o >>= 1) {
            es[0] += __shfl_xor_sync(~0u, es[0], o);
            es[1] += __shfl_xor_sync(~0u, es[1], o);
        }

        unsigned dm = 0;
        #pragma unroll
        for (int rr = 0; rr < 2; rr++)
            if (1.f <= thr * es[rr]) dm |= (1u << rr);   // rinv <= thr: row dead
        if (lane < 2) {
            int r = rA + lane;
            if (r < Rn && ((dm >> lane) & 1u)) g_spcnt[bh * Rn + r] = 0;
        }

        if (dm != 3u) {
            // ---- rare full path ----
            #pragma unroll
            for (int rr = 0; rr < 2; rr++) {
                int r = rA + rr;
                if (r >= Rn || ((dm >> rr) & 1u)) continue;
                float rinv = 1.f / es[rr];
                float v0 = fmaxf(fmaf(ex[rr][0], rinv, -thr), 0.f);
                float v1 = fmaxf(fmaf(ex[rr][1], rinv, -thr), 0.f);
                float v2 = fmaxf(fmaf(ex[rr][2], rinv, -thr), 0.f);
                float v3 = fmaxf(fmaf(ex[rr][3], rinv, -thr), 0.f);
                float v4 = val4 ? fmaxf(fmaf(ex[rr][4], rinv, -thr), 0.f) : 0.f;
                float gs = v0 + v1 + v2 + v3 + v4;
                #pragma unroll
                for (int o = 16; o; o >>= 1) gs += __shfl_xor_sync(~0u, gs, o);

                float c0 = __shfl_sync(~0u, v0, 0);
                float c1 = __shfl_sync(~0u, v0, cols1);
                float c2 = __shfl_sync(~0u, v0, cols2);
                float c3 = __shfl_sync(~0u, v0, cols3);
                float c4c = __shfl_sync(~0u, v0, cols4);
                float c5 = __shfl_sync(~0u, v0, cols5);

                unsigned p0 = 0, p1 = 0;
                #pragma unroll
                for (int jb = 0; jb < 5; jb++) {
                    int j = jb * 32 + lane;
                    float vv = (jb == 0) ? v0 : (jb == 1) ? v1 : (jb == 2) ? v2
                             : (jb == 3) ? v3 : v4;
                    p0 += (vv > c0)                                   ? 1u        : 0u;
                    p0 += ((vv > c1) || (vv == c1 && j < cols1))      ? (1u<<8)   : 0u;
                    p0 += ((vv > c2) || (vv == c2 && j < cols2))      ? (1u<<16)  : 0u;
                    p0 += ((vv > c3) || (vv == c3 && j < cols3))      ? (1u<<24)  : 0u;
                    p1 += ((vv > c4c)|| (vv == c4c&& j < cols4))      ? 1u        : 0u;
                    p1 += ((vv > c5) || (vv == c5 && j < cols5))      ? (1u<<8)   : 0u;
                }
                #pragma unroll
                for (int o = 16; o; o >>= 1) {
                    p0 += __shfl_xor_sync(~0u, p0, o);
                    p1 += __shfl_xor_sync(~0u, p1, o);
                }
                int myp = (lane < 4) ? (int)((p0 >> (8 * lane)) & 255u)
                                     : (int)((p1 >> (8 * (lane - 4))) & 255u);
                unsigned ball = __ballot_sync(~0u, (lane < 6) && (myp == r));
                int cnt = 6;
                if (!ball) { if (lane == 6) myp = r; cnt = 7; }

                int base = (bh * Rn + r) * 8;
                float rmax = 0.f;
                for (int i = 0; i < cnt; i++) {
                    int pp = __shfl_sync(~0u, myp, i);
                    int jbp = pp >> 5;
                    float av = (jbp == 0) ? v0 : (jbp == 1) ? v1 : (jbp == 2) ? v2
                             : (jbp == 3) ? v3 : v4;
                    float vv = __shfl_sync(~0u, av, pp & 31);
                    if (lane == 0) { g_spcol[base + i] = pp; g_spval[base + i] = vv; }
                    rmax = fmaxf(rmax, vv);
                }
                if (lane == 0) {
                    g_spcnt[bh * Rn + r] = cnt;
                    gapAcc += gs;
                    maxAcc = fmaxf(maxAcc, rmax);
                }
            }
        }
        __syncthreads();   // panel buffer handoff
    }

    if (lane == 0) { s_gap[w] = gapAcc; s_max[w] = maxAcc; }
    __syncthreads();
    if (tid == 0) {
        float gsum = 0.f, mx = 0.f;
        #pragma unroll
        for (int i = 0; i < 8; i++) { gsum += s_gap[i]; mx = fmaxf(mx, s_max[i]); }
        g_gap[bh] = gsum; g_maxA[bh] = mx;
    }
}

// ---------------- GCN: all 8 layers, gate computed inline -----------------
__global__ void k_gcnall(const float* __restrict__ x,
                         const float* __restrict__ gcnW, const float* __restrict__ gcnb,
                         const float* __restrict__ seW1, const float* __restrict__ seb1,
                         const float* __restrict__ seW2, const float* __restrict__ seb2)
{
    int bh = blockIdx.x;
    int b = bh >> 3, h = bh & 7;
    __shared__ float s_gt;
    if (threadIdx.x == 0) {
        float gt = se_gate(b, h, seW1, seb1, seW2, seb2);
        s_gt = ((gt != 0.f) && (g_maxA[bh] > 0.f)) ? gt : 0.f;
    }
    __syncthreads();
    float gt = s_gt;
    if (gt == 0.f) return;   // degenerate: head uses closed form
    size_t base = (size_t)bh * Rn * Tn;
    const float* xb = x + (size_t)b * Rn * Tn;

    for (int e = threadIdx.x; e < Rn * Tn; e += 256) g_feats[base + e] = xb[e];
    __syncthreads();

    for (int L = 0; L < 8; L++) {
        const float* W    = gcnW + (size_t)L * Tn * Tn;
        const float* bias = gcnb + L * Tn;
        for (int e = threadIdx.x; e < Rn * Tn; e += 256) {
            int r = e >> 8, t = e & 255;
            int cnt = g_spcnt[bh * Rn + r];
            int sb  = (bh * Rn + r) * 8;
            float a = 0.f;
            for (int i = 0; i < cnt; i++)
                a = fmaf(g_spval[sb + i],
                         g_feats[base + (size_t)g_spcol[sb + i] * Tn + t], a);
            g_agg[base + e] = a * gt;
        }
        __syncthreads();
        for (int e = threadIdx.x; e < Rn * Tn; e += 256) {
            int r = e >> 8, t = e & 255;
            float acc = bias[t];
            const float* ag = g_agg + base + (size_t)r * Tn;
            const float* wr = W + (size_t)t * Tn;
            for (int u = 0; u < Tn; u++) acc = fmaf(ag[u], wr[u], acc);
            g_feats[base + e] = fmaxf(acc, 0.f) + g_feats[base + e];
        }
        __syncthreads();
    }
}

// ---------------- K5: fusion + pool + MLP head (flags inline) -------------
__global__ void k_head(const float* __restrict__ x,
                       const float* __restrict__ fw, const float* __restrict__ fb,
                       const float* __restrict__ W1, const float* __restrict__ b1,
                       const float* __restrict__ W2, const float* __restrict__ b2,
                       const float* __restrict__ W3, const float* __restrict__ b3,
                       const float* __restrict__ seW1, const float* __restrict__ seb1,
                       const float* __restrict__ seW2, const float* __restrict__ seb2,
                       float* __restrict__ out)
{
    int b = blockIdx.x;
    int tid = threadIdx.x, lane = tid & 31, w = tid >> 5;
    __shared__ float pooled[132], sh1[64], sh2[16];
    __shared__ float swf[8];
    __shared__ int   sfl[8];
    if (tid < 8) {
        swf[tid] = fw[tid];
        float gt = se_gate(b, tid, seW1, seb1, seW2, seb2);
        sfl[tid] = (gt != 0.f) && (g_maxA[b * 8 + tid] > 0.f);
    }
    __syncthreads();
    float meanS = g_S[256], fbv = *fb;

    for (int r = w; r < Rn; r += 8) {
        const float* xr = x + ((size_t)b * Rn + r) * Tn;
        float sx = 0.f;
        for (int t = lane; t < Tn; t += 32) sx += xr[t];
        #pragma unroll
        for (int o = 16; o; o >>= 1) sx += __shfl_xor_sync(~0u, sx, o);
        float mx = sx * (1.f / 256.f);
        float acc = fbv;
        #pragma unroll
        for (int h = 0; h < 8; h++) {
            if (sfl[h]) {
                const float* fr = g_feats + ((size_t)(b * 8 + h) * Rn + r) * Tn;
                float sf = 0.f;
                for (int t = lane; t < Tn; t += 32) sf += fr[t];
                #pragma unroll
                for (int o = 16; o; o >>= 1) sf += __shfl_xor_sync(~0u, sf, o);
                acc = fmaf(swf[h], sf * (1.f / 256.f), acc);
            } else {
                acc = fmaf(swf[h], mx + meanS, acc);   // closed form: feats = x + S
            }
        }
        if (lane == 0) pooled[r] = acc;
    }
    __syncthreads();
    if (tid < 64) {
        float a = b1[tid];
        for (int r = 0; r < Rn; r++) a = fmaf(W1[tid * Rn + r], pooled[r], a);
        sh1[tid] = fmaxf(a, 0.f);
    }
    __syncthreads();
    if (tid < 16) {
        float a = b2[tid];
        #pragma unroll
        for (int j = 0; j < 64; j++) a = fmaf(W2[tid * 64 + j], sh1[j], a);
        sh2[tid] = fmaxf(a, 0.f);
    }
    __syncthreads();
    if (tid < 5) {
        float a = b3[tid];
        #pragma unroll
        for (int j = 0; j < 16; j++) a = fmaf(W3[tid * 16 + j], sh2[j], a);
        out[b * 5 + tid] = fmaxf(a, 0.f);
    }
}

// ---------------- launch ---------------------------------------------------
extern "C" void kernel_launch(void* const* d_in, const int* in_sizes, int n_in,
                              void* d_out, int out_size)
{
    const float* x    = (const float*)d_in[0];
    const float* Wq   = (const float*)d_in[1];
    const float* bq   = (const float*)d_in[2];
    const float* Wk   = (const float*)d_in[3];
    const float* bk   = (const float*)d_in[4];
    const float* thr  = (const float*)d_in[5];
    const float* seW1 = (const float*)d_in[6];
    const float* seb1 = (const float*)d_in[7];
    const float* seW2 = (const float*)d_in[8];
    const float* seb2 = (const float*)d_in[9];
    const float* gcnW = (const float*)d_in[10];
    const float* gcnb = (const float*)d_in[11];
    const float* fw   = (const float*)d_in[12];
    const float* fb   = (const float*)d_in[13];
    const float* W1   = (const float*)d_in[14];
    const float* b1   = (const float*)d_in[15];
    const float* W2   = (const float*)d_in[16];
    const float* b2   = (const float*)d_in[17];
    const float* W3   = (const float*)d_in[18];
    const float* b3   = (const float*)d_in[19];
    float* out = (float*)d_out;

    const int SMEM_ATTN = 2 * 144 * QSH * 2 + 2 * 16 * PS * 4;   // 41984 B
    cudaFuncSetAttribute(k_attn, cudaFuncAttributeMaxDynamicSharedMemorySize,
                         SMEM_ATTN);

    dim3 g1(Mn / 64, NQK / 128);
    k_nop<<<1, 32>>>();                                  // launch 1 (capture align)
    k_cvt<<<2144, 256>>>(x, Wq, Wk, gcnb);               // launch 2
    k_qkproj<<<g1, 256>>>(bq, bk);                       // launch 3
    k_attn<<<BHn, 256, SMEM_ATTN>>>(thr);                // launch 4 <- ncu capture
    k_gcnall<<<BHn, 256>>>(x, gcnW, gcnb, seW1, seb1, seW2, seb2);  // launch 5
    k_head<<<Bn, 256>>>(x, fw, fb, W1, b1, W2, b2, W3, b3,
                        seW1, seb1, seW2, seb2, out);    // launch 6
}